// round 1
// baseline (speedup 1.0000x reference)
#include <cuda_runtime.h>
#include <math.h>

// Problem dims
#define Bb   8
#define Oo   12
#define Tt   64
#define DMF  256
#define DIF  512
#define DSF  16
#define LL   768          // Oo*Tt
#define MM   6144         // Bb*LL
#define NLAY 2

// ---------------- scratch (static device globals; no runtime allocs) -------
__device__ float g_x   [MM*DMF];          // current activation, (B,768,256) in (o,t) order
__device__ float g_seq1[MM*DMF];          // transposed (t,o) order
__device__ float g_xz  [4][(size_t)MM*2*DIF];
__device__ float g_xc  [4][(size_t)MM*DIF];
__device__ float g_dbl [4][(size_t)MM*48];
__device__ float g_dlt [4][(size_t)MM*DIF];
__device__ float g_u   [4][(size_t)MM*DIF];
__device__ float g_o   [4][(size_t)MM*DMF];

__device__ __forceinline__ float siluf(float x){ return x / (1.f + __expf(-x)); }

// ---------------- elementwise kernels --------------------------------------
__global__ void add_pe_ker(const float* __restrict__ x, const float* __restrict__ pe){
  int i = blockIdx.x, c = threadIdx.x;
  int t = i % Tt;
  g_x[(size_t)i*DMF + c] = x[(size_t)i*DMF + c] + pe[t*DMF + c];
}

__global__ void transpose_ker(){
  int p = blockIdx.x, b = blockIdx.y, c = threadIdx.x;
  int o = p % Oo, t = p / Oo;
  g_seq1[((size_t)(b*LL) + p)*DMF + c] = g_x[((size_t)(b*LL) + (o*Tt + t))*DMF + c];
}

__global__ void copy_out_ker(float* __restrict__ out){
  int i = blockIdx.x, c = threadIdx.x;
  out[(size_t)i*DMF + c] = g_x[(size_t)i*DMF + c];
}

// ---------------- generic tiled SGEMM: C[z] = A[z] @ W[l*4+z] --------------
// A: (MM x K) row-major.  W: weights with leading (2,2,2)=8 index = l*4+z.
// If a_zstride!=0: A = A0 + z*a_zstride. Else A = (z<2 ? A0 : A1).
template<int BM,int BN,int BK,int TM,int TN>
__global__ void __launch_bounds__(256) sgemm_ker(
    const float* __restrict__ A0, const float* __restrict__ A1, size_t a_zstride,
    const float* __restrict__ Wb, float* __restrict__ Cb, int N, int K, int l)
{
  const int z = blockIdx.z;
  const float* A  = a_zstride ? (A0 + (size_t)z*a_zstride) : (z < 2 ? A0 : A1);
  const float* Bw = Wb + (size_t)(l*4 + z) * K * N;
  float* C = Cb + (size_t)z * MM * N;

  __shared__ __align__(16) float As[BK][BM];
  __shared__ __align__(16) float Bs[BK][BN];

  const int tid = threadIdx.x;
  const int tx  = tid % (BN/TN);
  const int ty  = tid / (BN/TN);
  const int row0 = blockIdx.x * BM;
  const int n0   = blockIdx.y * BN;

  float acc[TM][TN];
  #pragma unroll
  for (int i = 0; i < TM; i++)
    #pragma unroll
    for (int j = 0; j < TN; j++) acc[i][j] = 0.f;

  constexpr int AVEC = (BM*BK)/(256*4);
  constexpr int BVEC = (BK*BN)/(256*4);

  for (int k0 = 0; k0 < K; k0 += BK){
    #pragma unroll
    for (int v = 0; v < AVEC; v++){
      int idx = tid + v*256;
      int ar = idx / (BK/4);
      int ac = (idx % (BK/4)) * 4;
      const float4 t4 = *reinterpret_cast<const float4*>(&A[(size_t)(row0+ar)*K + (k0+ac)]);
      As[ac+0][ar] = t4.x; As[ac+1][ar] = t4.y; As[ac+2][ar] = t4.z; As[ac+3][ar] = t4.w;
    }
    #pragma unroll
    for (int v = 0; v < BVEC; v++){
      int idx = tid + v*256;
      int br = idx / (BN/4);
      int bc = (idx % (BN/4)) * 4;
      float4 t4 = make_float4(0.f,0.f,0.f,0.f);
      if (n0 + bc < N)
        t4 = *reinterpret_cast<const float4*>(&Bw[(size_t)(k0+br)*N + (n0+bc)]);
      *reinterpret_cast<float4*>(&Bs[br][bc]) = t4;
    }
    __syncthreads();
    #pragma unroll
    for (int k = 0; k < BK; k++){
      float ra[TM], rb[TN];
      #pragma unroll
      for (int i = 0; i < TM; i += 4){
        float4 t = *reinterpret_cast<const float4*>(&As[k][ty*TM + i]);
        ra[i]=t.x; ra[i+1]=t.y; ra[i+2]=t.z; ra[i+3]=t.w;
      }
      #pragma unroll
      for (int j = 0; j < TN; j += 4){
        float4 t = *reinterpret_cast<const float4*>(&Bs[k][tx*TN + j]);
        rb[j]=t.x; rb[j+1]=t.y; rb[j+2]=t.z; rb[j+3]=t.w;
      }
      #pragma unroll
      for (int i = 0; i < TM; i++)
        #pragma unroll
        for (int j = 0; j < TN; j++)
          acc[i][j] = fmaf(ra[i], rb[j], acc[i][j]);
    }
    __syncthreads();
  }

  #pragma unroll
  for (int i = 0; i < TM; i++){
    int r = row0 + ty*TM + i;
    #pragma unroll
    for (int j = 0; j < TN; j++){
      int cc = n0 + tx*TN + j;
      if (cc < N) C[(size_t)r*N + cc] = acc[i][j];
    }
  }
}

// ---------------- depthwise causal conv (dir-aware) + SiLU -----------------
__global__ void conv_ker(const float* __restrict__ conv_w, const float* __restrict__ conv_b, int l){
  int z   = blockIdx.y;
  int gid = blockIdx.x*256 + threadIdx.x;
  int i = gid / DIF;
  int d = gid % DIF;
  int b = i / LL, t = i % LL;
  int widx = l*4 + z;
  const float* xz = g_xz[z];
  const float* w  = &conv_w[(size_t)(widx*DIF + d)*4];
  float s = conv_b[widx*DIF + d];
  size_t base = (size_t)b*LL;
  if ((z & 1) == 0){                       // forward: looks back
    #pragma unroll
    for (int k = 0; k < 4; k++){
      int tt = t + k - 3;
      if (tt >= 0) s += w[k] * xz[(base + tt)*1024 + d];
    }
  } else {                                 // backward dir at orig position: looks forward
    #pragma unroll
    for (int j = 0; j < 4; j++){
      int tt = t + j;
      if (tt < LL) s += w[3-j] * xz[(base + tt)*1024 + d];
    }
  }
  g_xc[z][(size_t)i*DIF + d] = siluf(s);
}

// ---------------- delta = softplus(dbl[:, :16] @ dt_w + dt_b) --------------
__global__ void delta_ker(const float* __restrict__ dtw, const float* __restrict__ dtb, int l){
  int i = blockIdx.x, z = blockIdx.y, tid = threadIdx.x;
  int widx = l*4 + z;
  const float* dbl = g_dbl[z];
  __shared__ float sdt[16];
  if (tid < 16) sdt[tid] = dbl[(size_t)i*48 + tid];
  __syncthreads();
  const float* W = dtw + (size_t)widx*16*DIF;
  const float* bB = dtb + (size_t)widx*DIF;
  for (int dd = tid; dd < DIF; dd += 256){
    float a = bB[dd];
    #pragma unroll
    for (int k = 0; k < 16; k++) a = fmaf(sdt[k], W[k*DIF + dd], a);
    // softplus (stable)
    g_dlt[z][(size_t)i*DIF + dd] = fmaxf(a, 0.f) + log1pf(__expf(-fabsf(a)));
  }
}

// ---------------- selective scan + D-skip + silu(z) gate -------------------
#define SCH 64
__global__ void __launch_bounds__(128) scan_ker(const float* __restrict__ A_log,
                                                const float* __restrict__ Dp, int l){
  int z = blockIdx.z, b = blockIdx.y;
  int d = blockIdx.x*128 + threadIdx.x;
  int tid = threadIdx.x;
  int widx = l*4 + z;
  bool bwd = (z & 1);
  const float* delta = g_dlt[z];
  const float* xc    = g_xc[z];
  const float* dbl   = g_dbl[z];
  const float* xz    = g_xz[z];
  float* u = g_u[z];

  float Av[16];
  #pragma unroll
  for (int s = 0; s < 16; s++)
    Av[s] = -expf(A_log[((size_t)widx*DIF + d)*DSF + s]);
  // detect A_s = (s+1)*A_0 structure (true for this dataset) -> 1 exp/step
  bool pc = true;
  #pragma unroll
  for (int s = 1; s < 16; s++)
    pc = pc && (fabsf(Av[s] - (float)(s+1)*Av[0]) <= 1e-4f * fabsf(Av[s]));
  float Dpar = Dp[widx*DIF + d];

  float h[16];
  #pragma unroll
  for (int s = 0; s < 16; s++) h[s] = 0.f;

  __shared__ __align__(16) float4 sBC[SCH][8];

  for (int c0 = 0; c0 < LL; c0 += SCH){
    __syncthreads();
    #pragma unroll
    for (int v = 0; v < 4; v++){
      int idx = tid + v*128;
      int ls = idx / 8, q = idx % 8;
      int t = bwd ? (LL-1 - (c0+ls)) : (c0+ls);
      sBC[ls][q] = *reinterpret_cast<const float4*>(&dbl[(size_t)(b*LL + t)*48 + 16 + q*4]);
    }
    __syncthreads();
    for (int ls = 0; ls < SCH; ls++){
      int t = bwd ? (LL-1 - (c0+ls)) : (c0+ls);
      size_t rowd = (size_t)(b*LL + t)*DIF + d;
      float dv  = delta[rowd];
      float xcv = xc[rowd];
      float du  = dv * xcv;
      float Bf[16], Cf[16];
      {
        float4 q0=sBC[ls][0], q1=sBC[ls][1], q2=sBC[ls][2], q3=sBC[ls][3];
        float4 q4=sBC[ls][4], q5=sBC[ls][5], q6=sBC[ls][6], q7=sBC[ls][7];
        Bf[0]=q0.x;Bf[1]=q0.y;Bf[2]=q0.z;Bf[3]=q0.w;
        Bf[4]=q1.x;Bf[5]=q1.y;Bf[6]=q1.z;Bf[7]=q1.w;
        Bf[8]=q2.x;Bf[9]=q2.y;Bf[10]=q2.z;Bf[11]=q2.w;
        Bf[12]=q3.x;Bf[13]=q3.y;Bf[14]=q3.z;Bf[15]=q3.w;
        Cf[0]=q4.x;Cf[1]=q4.y;Cf[2]=q4.z;Cf[3]=q4.w;
        Cf[4]=q5.x;Cf[5]=q5.y;Cf[6]=q5.z;Cf[7]=q5.w;
        Cf[8]=q6.x;Cf[9]=q6.y;Cf[10]=q6.z;Cf[11]=q6.w;
        Cf[12]=q7.x;Cf[13]=q7.y;Cf[14]=q7.z;Cf[15]=q7.w;
      }
      float acc = 0.f;
      if (pc){
        float e = __expf(dv * Av[0]);
        float p = 1.f;
        #pragma unroll
        for (int s = 0; s < 16; s++){
          p *= e;
          h[s] = fmaf(p, h[s], du * Bf[s]);
          acc  = fmaf(h[s], Cf[s], acc);
        }
      } else {
        #pragma unroll
        for (int s = 0; s < 16; s++){
          float a = __expf(dv * Av[s]);
          h[s] = fmaf(a, h[s], du * Bf[s]);
          acc  = fmaf(h[s], Cf[s], acc);
        }
      }
      float y  = acc + xcv * Dpar;
      float zv = xz[(size_t)(b*LL + t)*1024 + DIF + d];
      u[rowd] = y * siluf(zv);
    }
  }
}

// ---------------- combine: LN(o0+o1), LN(o2+o3), residual add --------------
__global__ void combine_ker(const float* __restrict__ lnw, const float* __restrict__ lnb){
  int i = blockIdx.x, c = threadIdx.x;
  float a  = g_o[0][(size_t)i*DMF + c] + g_o[1][(size_t)i*DMF + c];
  float bv = g_o[2][(size_t)i*DMF + c] + g_o[3][(size_t)i*DMF + c];
  __shared__ float r1[256], r2[256];
  r1[c] = a; r2[c] = bv; __syncthreads();
  for (int s = 128; s > 0; s >>= 1){
    if (c < s){ r1[c] += r1[c+s]; r2[c] += r2[c+s]; }
    __syncthreads();
  }
  float ma = r1[0] * (1.f/DMF), mb = r2[0] * (1.f/DMF);
  __syncthreads();
  float da = a - ma, db = bv - mb;
  r1[c] = da*da; r2[c] = db*db; __syncthreads();
  for (int s = 128; s > 0; s >>= 1){
    if (c < s){ r1[c] += r1[c+s]; r2[c] += r2[c+s]; }
    __syncthreads();
  }
  float va = r1[0] * (1.f/DMF), vb = r2[0] * (1.f/DMF);
  float s1 = da * rsqrtf(va + 1e-5f) * lnw[c] + lnb[c];
  float s2 = db * rsqrtf(vb + 1e-5f) * lnw[c] + lnb[c];
  g_x[(size_t)i*DMF + c] += 0.5f * (s1 + s2);
}

// ---------------- host orchestration ---------------------------------------
extern "C" void kernel_launch(void* const* d_in, const int* in_sizes, int n_in,
                              void* d_out, int out_size){
  const float* x       = (const float*)d_in[0];
  const float* pe      = (const float*)d_in[1];
  const float* ln_w    = (const float*)d_in[2];
  const float* ln_b    = (const float*)d_in[3];
  const float* in_proj = (const float*)d_in[4];
  const float* conv_w  = (const float*)d_in[5];
  const float* conv_b  = (const float*)d_in[6];
  const float* x_proj  = (const float*)d_in[7];
  const float* dt_w    = (const float*)d_in[8];
  const float* dt_b    = (const float*)d_in[9];
  const float* A_log   = (const float*)d_in[10];
  const float* Dp      = (const float*)d_in[11];
  const float* out_prj = (const float*)d_in[12];

  void *px, *pseq1, *pxz, *pxc, *pdbl, *pu, *po;
  cudaGetSymbolAddress(&px,    g_x);
  cudaGetSymbolAddress(&pseq1, g_seq1);
  cudaGetSymbolAddress(&pxz,   g_xz);
  cudaGetSymbolAddress(&pxc,   g_xc);
  cudaGetSymbolAddress(&pdbl,  g_dbl);
  cudaGetSymbolAddress(&pu,    g_u);
  cudaGetSymbolAddress(&po,    g_o);

  add_pe_ker<<<MM, 256>>>(x, pe);

  for (int l = 0; l < NLAY; l++){
    transpose_ker<<<dim3(LL, Bb), 256>>>();
    // GEMM1: xz[z] = seq @ in_proj[l,z]  (N=1024, K=256)
    sgemm_ker<128,64,16,8,4><<<dim3(MM/128, 1024/64, 4), 256>>>(
        (const float*)px, (const float*)pseq1, (size_t)0,
        in_proj, (float*)pxz, 1024, 256, l);
    conv_ker<<<dim3((MM*DIF)/256, 4), 256>>>(conv_w, conv_b, l);
    // GEMM2: dbl[z] = xc[z] @ x_proj[l,z]  (N=48 padded to 64, K=512)
    sgemm_ker<64,64,16,4,4><<<dim3(MM/64, 1, 4), 256>>>(
        (const float*)pxc, (const float*)0, (size_t)MM*DIF,
        x_proj, (float*)pdbl, 48, 512, l);
    delta_ker<<<dim3(MM, 4), 256>>>(dt_w, dt_b, l);
    scan_ker<<<dim3(4, Bb, 4), 128>>>(A_log, Dp, l);
    // GEMM4: o[z] = u[z] @ out_proj[l,z]  (N=256, K=512)
    sgemm_ker<128,64,16,8,4><<<dim3(MM/128, 256/64, 4), 256>>>(
        (const float*)pu, (const float*)0, (size_t)MM*DIF,
        out_prj, (float*)po, 256, 512, l);
    combine_ker<<<MM, 256>>>(ln_w, ln_b);
  }

  copy_out_ker<<<MM, 256>>>((float*)d_out);
}

// round 2
// speedup vs baseline: 1.2908x; 1.2908x over previous
#include <cuda_runtime.h>
#include <math.h>
#include <stdint.h>

// Problem dims
#define Bb   8
#define Oo   12
#define Tt   64
#define DMF  256
#define DIF  512
#define DSF  16
#define LL   768          // Oo*Tt
#define MM   6144         // Bb*LL
#define NLAY 2

// ---------------- scratch (static device globals; no runtime allocs) -------
__device__ float g_x   [MM*DMF];
__device__ float g_seq1[MM*DMF];
__device__ float g_xz  [4][(size_t)MM*2*DIF];
__device__ float g_xc  [4][(size_t)MM*DIF];
__device__ float g_dbl [4][(size_t)MM*48];
__device__ float g_dlt [4][(size_t)MM*DIF];
__device__ float g_u   [4][(size_t)MM*DIF];
__device__ float g_o   [4][(size_t)MM*DMF];

__device__ __forceinline__ float siluf(float x){ return x / (1.f + __expf(-x)); }

__device__ __forceinline__ uint32_t f2tf(float x){
  uint32_t r; asm("cvt.rna.tf32.f32 %0, %1;" : "=r"(r) : "f"(x)); return r;
}

// ---------------- elementwise kernels --------------------------------------
__global__ void add_pe_ker(const float* __restrict__ x, const float* __restrict__ pe){
  int i = blockIdx.x, c = threadIdx.x;
  int t = i % Tt;
  g_x[(size_t)i*DMF + c] = x[(size_t)i*DMF + c] + pe[t*DMF + c];
}

__global__ void transpose_ker(){
  int p = blockIdx.x, b = blockIdx.y, c = threadIdx.x;
  int o = p % Oo, t = p / Oo;
  g_seq1[((size_t)(b*LL) + p)*DMF + c] = g_x[((size_t)(b*LL) + (o*Tt + t))*DMF + c];
}

__global__ void copy_out_ker(float* __restrict__ out){
  int i = blockIdx.x, c = threadIdx.x;
  out[(size_t)i*DMF + c] = g_x[(size_t)i*DMF + c];
}

// ---------------- TF32 tensor-core GEMM ------------------------------------
// C[z] (MM x N) = A[z] (MM x K) @ W[l*4+z] (K x N), all row-major fp32.
// CTA tile 128x64, BK=32, 8 warps (4x2), warp tile 32x32 (2 m-atoms x 4 n-atoms
// of m16n8k8). Double-buffered smem, register-staged gmem loads.
// As layout [m][k] stride 36 (loads: bank = 4g+tig -> conflict-free)
// Bs layout [k][n] stride 72 (loads: bank = 8(tig+na)+g -> conflict-free)
#define GBM 128
#define GBN 64
#define GBK 32
#define AS_STRIDE 36
#define BS_STRIDE 72
#define SMEM_WORDS (2*GBM*AS_STRIDE + 2*GBK*BS_STRIDE)
#define SMEM_BYTES (SMEM_WORDS*4)

__device__ __forceinline__ void mma_tf32(float* c, const uint32_t* a, const uint32_t* b){
  asm volatile(
    "mma.sync.aligned.m16n8k8.row.col.f32.tf32.tf32.f32 "
    "{%0,%1,%2,%3}, {%4,%5,%6,%7}, {%8,%9}, {%0,%1,%2,%3};\n"
    : "+f"(c[0]), "+f"(c[1]), "+f"(c[2]), "+f"(c[3])
    : "r"(a[0]), "r"(a[1]), "r"(a[2]), "r"(a[3]), "r"(b[0]), "r"(b[1]));
}

__global__ void __launch_bounds__(256) tf32_gemm_ker(
    const float* __restrict__ A0, const float* __restrict__ A1, size_t a_zstride,
    const float* __restrict__ Wb, float* __restrict__ Cb, int N, int K, int l)
{
  extern __shared__ uint32_t smw[];
  uint32_t* As = smw;                      // [2][GBM][AS_STRIDE]
  uint32_t* Bs = smw + 2*GBM*AS_STRIDE;    // [2][GBK][BS_STRIDE]

  const int z = blockIdx.z;
  const float* A  = a_zstride ? (A0 + (size_t)z*a_zstride) : (z < 2 ? A0 : A1);
  const float* Bw = Wb + (size_t)(l*4 + z) * K * N;
  float* C = Cb + (size_t)z * (size_t)MM * N;

  const int tid  = threadIdx.x;
  const int lane = tid & 31;
  const int w    = tid >> 5;
  const int g    = lane >> 2;      // groupID
  const int tig  = lane & 3;       // thread-in-group
  const int wr   = w & 3, wc = w >> 2;     // 4x2 warp grid
  const int wm   = wr * 32, wn = wc * 32;
  const int row0 = blockIdx.x * GBM;
  const int n0   = blockIdx.y * GBN;

  float acc[2][4][4];
  #pragma unroll
  for (int ma = 0; ma < 2; ma++)
    #pragma unroll
    for (int na = 0; na < 4; na++)
      #pragma unroll
      for (int q = 0; q < 4; q++) acc[ma][na][q] = 0.f;

  const int a_r = tid >> 3;          // 0..31 (rows per pass: 32, 4 passes)
  const int a_k = (tid & 7) * 4;
  const int b_r = tid >> 4;          // 0..15 (rows per pass: 16, 2 passes)
  const int b_c = (tid & 15) * 4;
  const bool bpred = (n0 + GBN > N);

  float4 Areg[4], Breg[2];

  auto loadg = [&](int t){
    const int k0 = t * GBK;
    #pragma unroll
    for (int v = 0; v < 4; v++)
      Areg[v] = *reinterpret_cast<const float4*>(&A[(size_t)(row0 + v*32 + a_r)*K + k0 + a_k]);
    #pragma unroll
    for (int v = 0; v < 2; v++){
      const int kk = k0 + v*16 + b_r;
      const int col = n0 + b_c;
      if (!bpred){
        Breg[v] = *reinterpret_cast<const float4*>(&Bw[(size_t)kk*N + col]);
      } else {
        float t0 = (col+0 < N) ? Bw[(size_t)kk*N + col+0] : 0.f;
        float t1 = (col+1 < N) ? Bw[(size_t)kk*N + col+1] : 0.f;
        float t2 = (col+2 < N) ? Bw[(size_t)kk*N + col+2] : 0.f;
        float t3 = (col+3 < N) ? Bw[(size_t)kk*N + col+3] : 0.f;
        Breg[v] = make_float4(t0, t1, t2, t3);
      }
    }
  };

  auto stores = [&](int buf){
    uint32_t* Ab = As + buf*GBM*AS_STRIDE;
    #pragma unroll
    for (int v = 0; v < 4; v++){
      const int m = v*32 + a_r;
      Ab[m*AS_STRIDE + a_k + 0] = f2tf(Areg[v].x);
      Ab[m*AS_STRIDE + a_k + 1] = f2tf(Areg[v].y);
      Ab[m*AS_STRIDE + a_k + 2] = f2tf(Areg[v].z);
      Ab[m*AS_STRIDE + a_k + 3] = f2tf(Areg[v].w);
    }
    uint32_t* Bbf = Bs + buf*GBK*BS_STRIDE;
    #pragma unroll
    for (int v = 0; v < 2; v++){
      const int kk = v*16 + b_r;
      Bbf[kk*BS_STRIDE + b_c + 0] = f2tf(Breg[v].x);
      Bbf[kk*BS_STRIDE + b_c + 1] = f2tf(Breg[v].y);
      Bbf[kk*BS_STRIDE + b_c + 2] = f2tf(Breg[v].z);
      Bbf[kk*BS_STRIDE + b_c + 3] = f2tf(Breg[v].w);
    }
  };

  auto compute = [&](int buf){
    const uint32_t* Ab  = As + buf*GBM*AS_STRIDE;
    const uint32_t* Bbf = Bs + buf*GBK*BS_STRIDE;
    #pragma unroll
    for (int ks = 0; ks < 4; ks++){
      const int k0 = ks*8 + tig, k1 = k0 + 4;
      uint32_t af[2][4];
      #pragma unroll
      for (int ma = 0; ma < 2; ma++){
        const int m = wm + ma*16 + g;
        af[ma][0] = Ab[m*AS_STRIDE + k0];
        af[ma][1] = Ab[(m+8)*AS_STRIDE + k0];
        af[ma][2] = Ab[m*AS_STRIDE + k1];
        af[ma][3] = Ab[(m+8)*AS_STRIDE + k1];
      }
      uint32_t bf2[4][2];
      #pragma unroll
      for (int na = 0; na < 4; na++){
        const int n = wn + na*8 + g;
        bf2[na][0] = Bbf[k0*BS_STRIDE + n];
        bf2[na][1] = Bbf[k1*BS_STRIDE + n];
      }
      #pragma unroll
      for (int ma = 0; ma < 2; ma++)
        #pragma unroll
        for (int na = 0; na < 4; na++)
          mma_tf32(acc[ma][na], af[ma], bf2[na]);
    }
  };

  const int nt = K / GBK;
  loadg(0); stores(0); __syncthreads();
  for (int t = 0; t < nt; t++){
    const int buf = t & 1;
    if (t + 1 < nt) loadg(t + 1);
    compute(buf);
    if (t + 1 < nt) stores(buf ^ 1);
    __syncthreads();
  }

  #pragma unroll
  for (int ma = 0; ma < 2; ma++){
    const int r = row0 + wm + ma*16 + g;
    #pragma unroll
    for (int na = 0; na < 4; na++){
      const int cc = n0 + wn + na*8 + tig*2;
      if (cc < N){
        *reinterpret_cast<float2*>(&C[(size_t)r*N + cc])     = make_float2(acc[ma][na][0], acc[ma][na][1]);
        *reinterpret_cast<float2*>(&C[(size_t)(r+8)*N + cc]) = make_float2(acc[ma][na][2], acc[ma][na][3]);
      }
    }
  }
}

// ---------------- depthwise causal conv (dir-aware) + SiLU -----------------
__global__ void conv_ker(const float* __restrict__ conv_w, const float* __restrict__ conv_b, int l){
  int z   = blockIdx.y;
  int gid = blockIdx.x*256 + threadIdx.x;
  int i = gid / DIF;
  int d = gid % DIF;
  int b = i / LL, t = i % LL;
  int widx = l*4 + z;
  const float* xz = g_xz[z];
  const float* w  = &conv_w[(size_t)(widx*DIF + d)*4];
  float s = conv_b[widx*DIF + d];
  size_t base = (size_t)b*LL;
  if ((z & 1) == 0){                       // forward: looks back
    #pragma unroll
    for (int k = 0; k < 4; k++){
      int tt = t + k - 3;
      if (tt >= 0) s += w[k] * xz[(base + tt)*1024 + d];
    }
  } else {                                 // backward dir at orig position: looks forward
    #pragma unroll
    for (int j = 0; j < 4; j++){
      int tt = t + j;
      if (tt < LL) s += w[3-j] * xz[(base + tt)*1024 + d];
    }
  }
  g_xc[z][(size_t)i*DIF + d] = siluf(s);
}

// ---------------- delta = softplus(dbl[:, :16] @ dt_w + dt_b) --------------
__global__ void delta_ker(const float* __restrict__ dtw, const float* __restrict__ dtb, int l){
  int i = blockIdx.x, z = blockIdx.y, tid = threadIdx.x;
  int widx = l*4 + z;
  const float* dbl = g_dbl[z];
  __shared__ float sdt[16];
  if (tid < 16) sdt[tid] = dbl[(size_t)i*48 + tid];
  __syncthreads();
  const float* W = dtw + (size_t)widx*16*DIF;
  const float* bB = dtb + (size_t)widx*DIF;
  for (int dd = tid; dd < DIF; dd += 256){
    float a = bB[dd];
    #pragma unroll
    for (int k = 0; k < 16; k++) a = fmaf(sdt[k], W[k*DIF + dd], a);
    g_dlt[z][(size_t)i*DIF + dd] = fmaxf(a, 0.f) + log1pf(__expf(-fabsf(a)));
  }
}

// ---------------- selective scan + D-skip + silu(z) gate -------------------
#define SCH 64
__global__ void __launch_bounds__(128) scan_ker(const float* __restrict__ A_log,
                                                const float* __restrict__ Dp, int l){
  int z = blockIdx.z, b = blockIdx.y;
  int d = blockIdx.x*128 + threadIdx.x;
  int tid = threadIdx.x;
  int widx = l*4 + z;
  bool bwd = (z & 1);
  const float* delta = g_dlt[z];
  const float* xc    = g_xc[z];
  const float* dbl   = g_dbl[z];
  const float* xz    = g_xz[z];
  float* u = g_u[z];

  float Av[16];
  #pragma unroll
  for (int s = 0; s < 16; s++)
    Av[s] = -expf(A_log[((size_t)widx*DIF + d)*DSF + s]);
  bool pc = true;
  #pragma unroll
  for (int s = 1; s < 16; s++)
    pc = pc && (fabsf(Av[s] - (float)(s+1)*Av[0]) <= 1e-4f * fabsf(Av[s]));
  float Dpar = Dp[widx*DIF + d];

  float h[16];
  #pragma unroll
  for (int s = 0; s < 16; s++) h[s] = 0.f;

  __shared__ __align__(16) float4 sBC[SCH][8];

  for (int c0 = 0; c0 < LL; c0 += SCH){
    __syncthreads();
    #pragma unroll
    for (int v = 0; v < 4; v++){
      int idx = tid + v*128;
      int ls = idx / 8, q = idx % 8;
      int t = bwd ? (LL-1 - (c0+ls)) : (c0+ls);
      sBC[ls][q] = *reinterpret_cast<const float4*>(&dbl[(size_t)(b*LL + t)*48 + 16 + q*4]);
    }
    __syncthreads();
    for (int ls = 0; ls < SCH; ls++){
      int t = bwd ? (LL-1 - (c0+ls)) : (c0+ls);
      size_t rowd = (size_t)(b*LL + t)*DIF + d;
      float dv  = delta[rowd];
      float xcv = xc[rowd];
      float du  = dv * xcv;
      float Bf[16], Cf[16];
      {
        float4 q0=sBC[ls][0], q1=sBC[ls][1], q2=sBC[ls][2], q3=sBC[ls][3];
        float4 q4=sBC[ls][4], q5=sBC[ls][5], q6=sBC[ls][6], q7=sBC[ls][7];
        Bf[0]=q0.x;Bf[1]=q0.y;Bf[2]=q0.z;Bf[3]=q0.w;
        Bf[4]=q1.x;Bf[5]=q1.y;Bf[6]=q1.z;Bf[7]=q1.w;
        Bf[8]=q2.x;Bf[9]=q2.y;Bf[10]=q2.z;Bf[11]=q2.w;
        Bf[12]=q3.x;Bf[13]=q3.y;Bf[14]=q3.z;Bf[15]=q3.w;
        Cf[0]=q4.x;Cf[1]=q4.y;Cf[2]=q4.z;Cf[3]=q4.w;
        Cf[4]=q5.x;Cf[5]=q5.y;Cf[6]=q5.z;Cf[7]=q5.w;
        Cf[8]=q6.x;Cf[9]=q6.y;Cf[10]=q6.z;Cf[11]=q6.w;
        Cf[12]=q7.x;Cf[13]=q7.y;Cf[14]=q7.z;Cf[15]=q7.w;
      }
      float acc = 0.f;
      if (pc){
        float e = __expf(dv * Av[0]);
        float p = 1.f;
        #pragma unroll
        for (int s = 0; s < 16; s++){
          p *= e;
          h[s] = fmaf(p, h[s], du * Bf[s]);
          acc  = fmaf(h[s], Cf[s], acc);
        }
      } else {
        #pragma unroll
        for (int s = 0; s < 16; s++){
          float a = __expf(dv * Av[s]);
          h[s] = fmaf(a, h[s], du * Bf[s]);
          acc  = fmaf(h[s], Cf[s], acc);
        }
      }
      float y  = acc + xcv * Dpar;
      float zv = xz[(size_t)(b*LL + t)*1024 + DIF + d];
      u[rowd] = y * siluf(zv);
    }
  }
}

// ---------------- combine: LN(o0+o1), LN(o2+o3), residual add --------------
__global__ void combine_ker(const float* __restrict__ lnw, const float* __restrict__ lnb){
  int i = blockIdx.x, c = threadIdx.x;
  float a  = g_o[0][(size_t)i*DMF + c] + g_o[1][(size_t)i*DMF + c];
  float bv = g_o[2][(size_t)i*DMF + c] + g_o[3][(size_t)i*DMF + c];
  __shared__ float r1[256], r2[256];
  r1[c] = a; r2[c] = bv; __syncthreads();
  for (int s = 128; s > 0; s >>= 1){
    if (c < s){ r1[c] += r1[c+s]; r2[c] += r2[c+s]; }
    __syncthreads();
  }
  float ma = r1[0] * (1.f/DMF), mb = r2[0] * (1.f/DMF);
  __syncthreads();
  float da = a - ma, db = bv - mb;
  r1[c] = da*da; r2[c] = db*db; __syncthreads();
  for (int s = 128; s > 0; s >>= 1){
    if (c < s){ r1[c] += r1[c+s]; r2[c] += r2[c+s]; }
    __syncthreads();
  }
  float va = r1[0] * (1.f/DMF), vb = r2[0] * (1.f/DMF);
  float s1 = da * rsqrtf(va + 1e-5f) * lnw[c] + lnb[c];
  float s2 = db * rsqrtf(vb + 1e-5f) * lnw[c] + lnb[c];
  g_x[(size_t)i*DMF + c] += 0.5f * (s1 + s2);
}

// ---------------- host orchestration ---------------------------------------
extern "C" void kernel_launch(void* const* d_in, const int* in_sizes, int n_in,
                              void* d_out, int out_size){
  const float* x       = (const float*)d_in[0];
  const float* pe      = (const float*)d_in[1];
  const float* ln_w    = (const float*)d_in[2];
  const float* ln_b    = (const float*)d_in[3];
  const float* in_proj = (const float*)d_in[4];
  const float* conv_w  = (const float*)d_in[5];
  const float* conv_b  = (const float*)d_in[6];
  const float* x_proj  = (const float*)d_in[7];
  const float* dt_w    = (const float*)d_in[8];
  const float* dt_b    = (const float*)d_in[9];
  const float* A_log   = (const float*)d_in[10];
  const float* Dp      = (const float*)d_in[11];
  const float* out_prj = (const float*)d_in[12];

  void *px, *pseq1, *pxz, *pxc, *pdbl, *pu, *po;
  cudaGetSymbolAddress(&px,    g_x);
  cudaGetSymbolAddress(&pseq1, g_seq1);
  cudaGetSymbolAddress(&pxz,   g_xz);
  cudaGetSymbolAddress(&pxc,   g_xc);
  cudaGetSymbolAddress(&pdbl,  g_dbl);
  cudaGetSymbolAddress(&pu,    g_u);
  cudaGetSymbolAddress(&po,    g_o);

  cudaFuncSetAttribute(tf32_gemm_ker, cudaFuncAttributeMaxDynamicSharedMemorySize, SMEM_BYTES);

  add_pe_ker<<<MM, 256>>>(x, pe);

  for (int l = 0; l < NLAY; l++){
    transpose_ker<<<dim3(LL, Bb), 256>>>();
    // GEMM1: xz[z] = seq @ in_proj[l,z]  (N=1024, K=256)
    tf32_gemm_ker<<<dim3(MM/GBM, 1024/GBN, 4), 256, SMEM_BYTES>>>(
        (const float*)px, (const float*)pseq1, (size_t)0,
        in_proj, (float*)pxz, 1024, 256, l);
    conv_ker<<<dim3((MM*DIF)/256, 4), 256>>>(conv_w, conv_b, l);
    // GEMM2: dbl[z] = xc[z] @ x_proj[l,z]  (N=48, K=512)
    tf32_gemm_ker<<<dim3(MM/GBM, 1, 4), 256, SMEM_BYTES>>>(
        (const float*)pxc, (const float*)0, (size_t)MM*DIF,
        x_proj, (float*)pdbl, 48, 512, l);
    delta_ker<<<dim3(MM, 4), 256>>>(dt_w, dt_b, l);
    scan_ker<<<dim3(4, Bb, 4), 128>>>(A_log, Dp, l);
    // GEMM4: o[z] = u[z] @ out_proj[l,z]  (N=256, K=512)
    tf32_gemm_ker<<<dim3(MM/GBM, 256/GBN, 4), 256, SMEM_BYTES>>>(
        (const float*)pu, (const float*)0, (size_t)MM*DIF,
        out_prj, (float*)po, 256, 512, l);
    combine_ker<<<MM, 256>>>(ln_w, ln_b);
  }

  copy_out_ker<<<MM, 256>>>((float*)d_out);
}

// round 3
// speedup vs baseline: 2.2250x; 1.7238x over previous
#include <cuda_runtime.h>
#include <math.h>
#include <stdint.h>

// Problem dims
#define Bb   8
#define Oo   12
#define Tt   64
#define DMF  256
#define DIF  512
#define DSF  16
#define LL   768          // Oo*Tt
#define MM   6144         // Bb*LL
#define NLAY 2

// ---------------- scratch (static device globals; no runtime allocs) -------
__device__ float g_x   [MM*DMF];
__device__ float g_seq1[MM*DMF];
__device__ float g_xz  [4][(size_t)MM*2*DIF];
__device__ float g_xc  [4][(size_t)MM*DIF];
__device__ float g_dbl [4][(size_t)MM*48];
__device__ float g_u   [4][(size_t)MM*DIF];
__device__ float g_o   [4][(size_t)MM*DMF];

__device__ __forceinline__ float siluf(float x){ return x / (1.f + __expf(-x)); }

// ---------------- elementwise kernels --------------------------------------
__global__ void add_pe_ker(const float* __restrict__ x, const float* __restrict__ pe){
  int i = blockIdx.x, c = threadIdx.x;
  int t = i % Tt;
  g_x[(size_t)i*DMF + c] = x[(size_t)i*DMF + c] + pe[t*DMF + c];
}

__global__ void transpose_ker(){
  int p = blockIdx.x, b = blockIdx.y, c = threadIdx.x;
  int o = p % Oo, t = p / Oo;
  g_seq1[((size_t)(b*LL) + p)*DMF + c] = g_x[((size_t)(b*LL) + (o*Tt + t))*DMF + c];
}

__global__ void copy_out_ker(float* __restrict__ out){
  int i = blockIdx.x, c = threadIdx.x;
  out[(size_t)i*DMF + c] = g_x[(size_t)i*DMF + c];
}

// ---------------- TF32 tensor-core GEMM (cp.async, 128x128x32) -------------
// C[z] (MM x N) = A[z] (MM x K) @ W[l*4+z] (K x N), row-major fp32.
// 8 warps in 2(m) x 4(n); warp tile 64x32 = 4 m-atoms x 4 n-atoms of m16n8k8.
// Raw fp32 bits fed to tf32 MMA (hw truncation), no cvt, no register staging.
// As [m][k] stride 36 words -> compute-load bank = 4g+tig (conflict-free)
// Bs [k][n] stride 136 words -> compute-load bank = 8tig+g (conflict-free)
#define GBM 128
#define GBN 128
#define GBK 32
#define AS_STRIDE 36
#define BS_STRIDE 136
#define ASIZE (GBM*AS_STRIDE)      // 4608 words
#define BSIZE (GBK*BS_STRIDE)      // 4352 words
#define GSMEM_BYTES (2*(ASIZE+BSIZE)*4)   // 71680 B

__device__ __forceinline__ void mma_tf32(float* c, const uint32_t* a, const uint32_t* b){
  asm volatile(
    "mma.sync.aligned.m16n8k8.row.col.f32.tf32.tf32.f32 "
    "{%0,%1,%2,%3}, {%4,%5,%6,%7}, {%8,%9}, {%0,%1,%2,%3};\n"
    : "+f"(c[0]), "+f"(c[1]), "+f"(c[2]), "+f"(c[3])
    : "r"(a[0]), "r"(a[1]), "r"(a[2]), "r"(a[3]), "r"(b[0]), "r"(b[1]));
}

__device__ __forceinline__ void cpa16(uint32_t dst, const void* src, int szbytes){
  asm volatile("cp.async.cg.shared.global [%0], [%1], 16, %2;\n"
               :: "r"(dst), "l"(src), "r"(szbytes));
}

__global__ void __launch_bounds__(256) tf32_gemm_ker(
    const float* __restrict__ A0, const float* __restrict__ A1, size_t a_zstride,
    const float* __restrict__ Wb, float* __restrict__ Cb, int N, int K, int l)
{
  extern __shared__ float smf[];
  const uint32_t smem_u32 = (uint32_t)__cvta_generic_to_shared(smf);

  const int z = blockIdx.z;
  const float* A  = a_zstride ? (A0 + (size_t)z*a_zstride) : (z < 2 ? A0 : A1);
  const float* Bw = Wb + (size_t)(l*4 + z) * K * N;
  float* C = Cb + (size_t)z * (size_t)MM * N;

  const int tid  = threadIdx.x;
  const int lane = tid & 31;
  const int w    = tid >> 5;
  const int g    = lane >> 2;
  const int tig  = lane & 3;
  const int wm   = (w & 1) * 64;
  const int wn   = (w >> 1) * 32;
  const int row0 = blockIdx.x * GBM;
  const int n0   = blockIdx.y * GBN;

  float acc[4][4][4];
  #pragma unroll
  for (int ma = 0; ma < 4; ma++)
    #pragma unroll
    for (int na = 0; na < 4; na++)
      #pragma unroll
      for (int q = 0; q < 4; q++) acc[ma][na][q] = 0.f;

  // gmem->smem async copy indices
  const int a_r = tid >> 3;          // 0..31, 4 passes of 32 rows
  const int a_k = (tid & 7) * 4;
  const int b_r = tid >> 5;          // 0..7, 4 passes of 8 k-rows
  const int b_c = (tid & 31) * 4;
  const int bsz = (n0 + b_c < N) ? 16 : 0;   // N multiple of 4 in all uses

  auto loadg = [&](int t, int buf){
    const int k0 = t * GBK;
    const uint32_t aBase = smem_u32 + (uint32_t)(buf*ASIZE)*4;
    const uint32_t bBase = smem_u32 + (uint32_t)(2*ASIZE + buf*BSIZE)*4;
    #pragma unroll
    for (int v = 0; v < 4; v++){
      const int m = v*32 + a_r;
      cpa16(aBase + (uint32_t)(m*AS_STRIDE + a_k)*4,
            &A[(size_t)(row0 + m)*K + k0 + a_k], 16);
    }
    #pragma unroll
    for (int v = 0; v < 4; v++){
      const int kk = v*8 + b_r;
      cpa16(bBase + (uint32_t)(kk*BS_STRIDE + b_c)*4,
            &Bw[(size_t)(k0 + kk)*N + n0 + b_c], bsz);
    }
    asm volatile("cp.async.commit_group;\n" ::: "memory");
  };

  auto compute = [&](int buf){
    const uint32_t* As = reinterpret_cast<const uint32_t*>(smf) + buf*ASIZE;
    const uint32_t* Bs = reinterpret_cast<const uint32_t*>(smf) + 2*ASIZE + buf*BSIZE;
    #pragma unroll
    for (int ks = 0; ks < 4; ks++){
      const int k0 = ks*8 + tig, k1 = k0 + 4;
      uint32_t af[4][4];
      #pragma unroll
      for (int ma = 0; ma < 4; ma++){
        const int m = wm + ma*16 + g;
        af[ma][0] = As[m*AS_STRIDE + k0];
        af[ma][1] = As[(m+8)*AS_STRIDE + k0];
        af[ma][2] = As[m*AS_STRIDE + k1];
        af[ma][3] = As[(m+8)*AS_STRIDE + k1];
      }
      uint32_t bf[4][2];
      #pragma unroll
      for (int na = 0; na < 4; na++){
        const int n = wn + na*8 + g;
        bf[na][0] = Bs[k0*BS_STRIDE + n];
        bf[na][1] = Bs[k1*BS_STRIDE + n];
      }
      #pragma unroll
      for (int ma = 0; ma < 4; ma++)
        #pragma unroll
        for (int na = 0; na < 4; na++)
          mma_tf32(acc[ma][na], af[ma], bf[na]);
    }
  };

  const int nt = K / GBK;
  loadg(0, 0);
  for (int t = 0; t < nt; t++){
    asm volatile("cp.async.wait_group 0;\n" ::: "memory");
    __syncthreads();
    if (t + 1 < nt) loadg(t + 1, (t + 1) & 1);
    compute(t & 1);
    __syncthreads();
  }

  #pragma unroll
  for (int ma = 0; ma < 4; ma++){
    const int r = row0 + wm + ma*16 + g;
    #pragma unroll
    for (int na = 0; na < 4; na++){
      const int cc = n0 + wn + na*8 + tig*2;
      if (cc < N){
        *reinterpret_cast<float2*>(&C[(size_t)r*N + cc])     = make_float2(acc[ma][na][0], acc[ma][na][1]);
        *reinterpret_cast<float2*>(&C[(size_t)(r+8)*N + cc]) = make_float2(acc[ma][na][2], acc[ma][na][3]);
      }
    }
  }
}

// ---------------- depthwise causal conv (dir-aware) + SiLU, float4 ---------
__global__ void conv_ker(const float* __restrict__ conv_w, const float* __restrict__ conv_b, int l){
  int z   = blockIdx.y;
  int gid = blockIdx.x*256 + threadIdx.x;     // over MM * DIF/4
  int i  = gid / (DIF/4);
  int dq = gid % (DIF/4);
  int d  = dq * 4;
  int b = i / LL, t = i % LL;
  int widx = l*4 + z;
  const float* xz = g_xz[z];
  const float4 wA = *reinterpret_cast<const float4*>(&conv_w[(size_t)(widx*DIF + d+0)*4]);
  const float4 wB = *reinterpret_cast<const float4*>(&conv_w[(size_t)(widx*DIF + d+1)*4]);
  const float4 wC = *reinterpret_cast<const float4*>(&conv_w[(size_t)(widx*DIF + d+2)*4]);
  const float4 wD = *reinterpret_cast<const float4*>(&conv_w[(size_t)(widx*DIF + d+3)*4]);
  float wt[4][4] = {{wA.x,wA.y,wA.z,wA.w},{wB.x,wB.y,wB.z,wB.w},
                    {wC.x,wC.y,wC.z,wC.w},{wD.x,wD.y,wD.z,wD.w}};
  float4 s = *reinterpret_cast<const float4*>(&conv_b[(size_t)widx*DIF + d]);
  size_t base = (size_t)b*LL;
  if ((z & 1) == 0){                       // forward: looks back
    #pragma unroll
    for (int k = 0; k < 4; k++){
      int tt = t + k - 3;
      if (tt >= 0){
        float4 v = *reinterpret_cast<const float4*>(&xz[(base + tt)*1024 + d]);
        s.x = fmaf(wt[0][k], v.x, s.x);
        s.y = fmaf(wt[1][k], v.y, s.y);
        s.z = fmaf(wt[2][k], v.z, s.z);
        s.w = fmaf(wt[3][k], v.w, s.w);
      }
    }
  } else {                                 // backward dir: looks forward
    #pragma unroll
    for (int j = 0; j < 4; j++){
      int tt = t + j;
      if (tt < LL){
        float4 v = *reinterpret_cast<const float4*>(&xz[(base + tt)*1024 + d]);
        s.x = fmaf(wt[0][3-j], v.x, s.x);
        s.y = fmaf(wt[1][3-j], v.y, s.y);
        s.z = fmaf(wt[2][3-j], v.z, s.z);
        s.w = fmaf(wt[3][3-j], v.w, s.w);
      }
    }
  }
  float4 o;
  o.x = siluf(s.x); o.y = siluf(s.y); o.z = siluf(s.z); o.w = siluf(s.w);
  *reinterpret_cast<float4*>(&g_xc[z][(size_t)i*DIF + d]) = o;
}

// ---------------- selective scan: fused delta + scan + D-skip + gate -------
#define SCH 64
__global__ void __launch_bounds__(128) scan_ker(const float* __restrict__ A_log,
                                                const float* __restrict__ Dp,
                                                const float* __restrict__ dtw,
                                                const float* __restrict__ dtb, int l){
  int z = blockIdx.z, b = blockIdx.y;
  int d = blockIdx.x*128 + threadIdx.x;
  int tid = threadIdx.x;
  int widx = l*4 + z;
  bool bwd = (z & 1);
  const float* xc  = g_xc[z];
  const float* dbl = g_dbl[z];
  const float* xz  = g_xz[z];
  float* u = g_u[z];

  // per-thread dt_w column (16 regs) + bias
  float W[16];
  #pragma unroll
  for (int k = 0; k < 16; k++) W[k] = dtw[((size_t)widx*16 + k)*DIF + d];
  float bia = dtb[(size_t)widx*DIF + d];

  float Av[16];
  #pragma unroll
  for (int s = 0; s < 16; s++)
    Av[s] = -expf(A_log[((size_t)widx*DIF + d)*DSF + s]);
  bool pc = true;
  #pragma unroll
  for (int s = 1; s < 16; s++)
    pc = pc && (fabsf(Av[s] - (float)(s+1)*Av[0]) <= 1e-4f * fabsf(Av[s]));
  float Dpar = Dp[(size_t)widx*DIF + d];

  float h[16];
  #pragma unroll
  for (int s = 0; s < 16; s++) h[s] = 0.f;

  // per-timestep raw dbl rows: [dt(4 float4) | B(4 float4) | C(4 float4)]
  __shared__ __align__(16) float4 sRaw[SCH][12];

  // 1-ahead prefetch of xc / z-gate
  int t0 = bwd ? (LL-1) : 0;
  float nxc = xc[(size_t)(b*LL + t0)*DIF + d];
  float nzv = xz[(size_t)(b*LL + t0)*1024 + DIF + d];

  for (int c0 = 0; c0 < LL; c0 += SCH){
    __syncthreads();
    #pragma unroll
    for (int v = 0; v < 6; v++){
      int idx = tid + v*128;
      int ls = idx / 12, q = idx - ls*12;
      int t = bwd ? (LL-1 - (c0+ls)) : (c0+ls);
      sRaw[ls][q] = *reinterpret_cast<const float4*>(&dbl[(size_t)(b*LL + t)*48 + q*4]);
    }
    __syncthreads();
    for (int ls = 0; ls < SCH; ls++){
      int gi = c0 + ls;
      int t  = bwd ? (LL-1 - gi) : gi;
      size_t rowd = (size_t)(b*LL + t)*DIF + d;
      float xcv = nxc, zv = nzv;
      if (gi + 1 < LL){
        int t2 = bwd ? (LL-1 - (gi+1)) : (gi+1);
        nxc = xc[(size_t)(b*LL + t2)*DIF + d];
        nzv = xz[(size_t)(b*LL + t2)*1024 + DIF + d];
      }
      // delta = softplus(dt_row @ W + bias)
      float4 q0 = sRaw[ls][0], q1 = sRaw[ls][1], q2 = sRaw[ls][2], q3 = sRaw[ls][3];
      float a = bia;
      a = fmaf(q0.x, W[0],  a); a = fmaf(q0.y, W[1],  a);
      a = fmaf(q0.z, W[2],  a); a = fmaf(q0.w, W[3],  a);
      a = fmaf(q1.x, W[4],  a); a = fmaf(q1.y, W[5],  a);
      a = fmaf(q1.z, W[6],  a); a = fmaf(q1.w, W[7],  a);
      a = fmaf(q2.x, W[8],  a); a = fmaf(q2.y, W[9],  a);
      a = fmaf(q2.z, W[10], a); a = fmaf(q2.w, W[11], a);
      a = fmaf(q3.x, W[12], a); a = fmaf(q3.y, W[13], a);
      a = fmaf(q3.z, W[14], a); a = fmaf(q3.w, W[15], a);
      float dv = fmaxf(a, 0.f) + log1pf(__expf(-fabsf(a)));
      float du = dv * xcv;

      float acc = 0.f;
      if (pc){
        float e = __expf(dv * Av[0]);
        float p = 1.f;
        #pragma unroll
        for (int q = 0; q < 4; q++){
          float4 B4 = sRaw[ls][4+q];
          float4 C4 = sRaw[ls][8+q];
          p *= e; h[q*4+0] = fmaf(p, h[q*4+0], du*B4.x); acc = fmaf(h[q*4+0], C4.x, acc);
          p *= e; h[q*4+1] = fmaf(p, h[q*4+1], du*B4.y); acc = fmaf(h[q*4+1], C4.y, acc);
          p *= e; h[q*4+2] = fmaf(p, h[q*4+2], du*B4.z); acc = fmaf(h[q*4+2], C4.z, acc);
          p *= e; h[q*4+3] = fmaf(p, h[q*4+3], du*B4.w); acc = fmaf(h[q*4+3], C4.w, acc);
        }
      } else {
        #pragma unroll
        for (int q = 0; q < 4; q++){
          float4 B4 = sRaw[ls][4+q];
          float4 C4 = sRaw[ls][8+q];
          float a0 = __expf(dv*Av[q*4+0]); h[q*4+0] = fmaf(a0, h[q*4+0], du*B4.x); acc = fmaf(h[q*4+0], C4.x, acc);
          float a1 = __expf(dv*Av[q*4+1]); h[q*4+1] = fmaf(a1, h[q*4+1], du*B4.y); acc = fmaf(h[q*4+1], C4.y, acc);
          float a2 = __expf(dv*Av[q*4+2]); h[q*4+2] = fmaf(a2, h[q*4+2], du*B4.z); acc = fmaf(h[q*4+2], C4.z, acc);
          float a3 = __expf(dv*Av[q*4+3]); h[q*4+3] = fmaf(a3, h[q*4+3], du*B4.w); acc = fmaf(h[q*4+3], C4.w, acc);
        }
      }
      float y = acc + xcv * Dpar;
      u[rowd] = y * siluf(zv);
    }
  }
}

// ---------------- combine: LN(o0+o1), LN(o2+o3), residual add --------------
__global__ void combine_ker(const float* __restrict__ lnw, const float* __restrict__ lnb){
  int i = blockIdx.x, c = threadIdx.x;
  float a  = g_o[0][(size_t)i*DMF + c] + g_o[1][(size_t)i*DMF + c];
  float bv = g_o[2][(size_t)i*DMF + c] + g_o[3][(size_t)i*DMF + c];
  __shared__ float r1[256], r2[256];
  r1[c] = a; r2[c] = bv; __syncthreads();
  for (int s = 128; s > 0; s >>= 1){
    if (c < s){ r1[c] += r1[c+s]; r2[c] += r2[c+s]; }
    __syncthreads();
  }
  float ma = r1[0] * (1.f/DMF), mb = r2[0] * (1.f/DMF);
  __syncthreads();
  float da = a - ma, db = bv - mb;
  r1[c] = da*da; r2[c] = db*db; __syncthreads();
  for (int s = 128; s > 0; s >>= 1){
    if (c < s){ r1[c] += r1[c+s]; r2[c] += r2[c+s]; }
    __syncthreads();
  }
  float va = r1[0] * (1.f/DMF), vb = r2[0] * (1.f/DMF);
  float s1 = da * rsqrtf(va + 1e-5f) * lnw[c] + lnb[c];
  float s2 = db * rsqrtf(vb + 1e-5f) * lnw[c] + lnb[c];
  g_x[(size_t)i*DMF + c] += 0.5f * (s1 + s2);
}

// ---------------- host orchestration ---------------------------------------
extern "C" void kernel_launch(void* const* d_in, const int* in_sizes, int n_in,
                              void* d_out, int out_size){
  const float* x       = (const float*)d_in[0];
  const float* pe      = (const float*)d_in[1];
  const float* ln_w    = (const float*)d_in[2];
  const float* ln_b    = (const float*)d_in[3];
  const float* in_proj = (const float*)d_in[4];
  const float* conv_w  = (const float*)d_in[5];
  const float* conv_b  = (const float*)d_in[6];
  const float* x_proj  = (const float*)d_in[7];
  const float* dt_w    = (const float*)d_in[8];
  const float* dt_b    = (const float*)d_in[9];
  const float* A_log   = (const float*)d_in[10];
  const float* Dp      = (const float*)d_in[11];
  const float* out_prj = (const float*)d_in[12];

  void *px, *pseq1, *pxz, *pxc, *pdbl, *pu, *po;
  cudaGetSymbolAddress(&px,    g_x);
  cudaGetSymbolAddress(&pseq1, g_seq1);
  cudaGetSymbolAddress(&pxz,   g_xz);
  cudaGetSymbolAddress(&pxc,   g_xc);
  cudaGetSymbolAddress(&pdbl,  g_dbl);
  cudaGetSymbolAddress(&pu,    g_u);
  cudaGetSymbolAddress(&po,    g_o);

  cudaFuncSetAttribute(tf32_gemm_ker, cudaFuncAttributeMaxDynamicSharedMemorySize, GSMEM_BYTES);

  add_pe_ker<<<MM, 256>>>(x, pe);

  for (int l = 0; l < NLAY; l++){
    transpose_ker<<<dim3(LL, Bb), 256>>>();
    // GEMM1: xz[z] = seq @ in_proj[l,z]  (N=1024, K=256)
    tf32_gemm_ker<<<dim3(MM/GBM, 1024/GBN, 4), 256, GSMEM_BYTES>>>(
        (const float*)px, (const float*)pseq1, (size_t)0,
        in_proj, (float*)pxz, 1024, 256, l);
    conv_ker<<<dim3((MM*(DIF/4))/256, 4), 256>>>(conv_w, conv_b, l);
    // GEMM2: dbl[z] = xc[z] @ x_proj[l,z]  (N=48, K=512)
    tf32_gemm_ker<<<dim3(MM/GBM, 1, 4), 256, GSMEM_BYTES>>>(
        (const float*)pxc, (const float*)0, (size_t)MM*DIF,
        x_proj, (float*)pdbl, 48, 512, l);
    // fused delta + selective scan + gate
    scan_ker<<<dim3(4, Bb, 4), 128>>>(A_log, Dp, dt_w, dt_b, l);
    // GEMM4: o[z] = u[z] @ out_proj[l,z]  (N=256, K=512)
    tf32_gemm_ker<<<dim3(MM/GBM, 256/GBN, 4), 256, GSMEM_BYTES>>>(
        (const float*)pu, (const float*)0, (size_t)MM*DIF,
        out_prj, (float*)po, 256, 512, l);
    combine_ker<<<MM, 256>>>(ln_w, ln_b);
  }

  copy_out_ker<<<MM, 256>>>((float*)d_out);
}

// round 5
// speedup vs baseline: 2.5090x; 1.1277x over previous
#include <cuda_runtime.h>
#include <cuda_fp16.h>
#include <math.h>
#include <stdint.h>

// Problem dims
#define Bb   8
#define Oo   12
#define Tt   64
#define DMF  256
#define DIF  512
#define DSF  16
#define LL   768          // Oo*Tt
#define MM   6144         // Bb*LL
#define NLAY 2

// ---------------- scratch (static device globals; no runtime allocs) -------
__device__ float  g_x   [MM*DMF];                     // fp32 residual stream
__device__ __align__(16) __half g_xh  [MM*DMF];       // half copy (GEMM1 A, blk0)
__device__ __align__(16) __half g_seq1h[MM*DMF];      // half transposed (GEMM1 A, blk1)
__device__ float  g_xz  [4][(size_t)MM*2*DIF];        // GEMM1 out (fp32)
__device__ float  g_xc  [4][(size_t)MM*DIF];          // conv out (fp32, scan)
__device__ __align__(16) __half g_xch [4][(size_t)MM*DIF];   // conv out (half, GEMM2 A)
__device__ float  g_dbl [4][(size_t)MM*48];           // GEMM2 out
__device__ __align__(16) __half g_uh  [4][(size_t)MM*DIF];   // scan out (half, GEMM4 A)
__device__ float  g_o   [4][(size_t)MM*DMF];          // GEMM4 out
// transposed + half weights: [w][n][k]
__device__ __align__(16) __half g_wt1[8*1024*256];
__device__ __align__(16) __half g_wt2[8*64*512];
__device__ __align__(16) __half g_wt4[8*256*512];

__device__ __forceinline__ float siluf(float x){ return x / (1.f + __expf(-x)); }

// ---------------- PTX helpers ----------------------------------------------
__device__ __forceinline__ void mma_f16(float* c, const uint32_t* a, const uint32_t* b){
  asm volatile(
    "mma.sync.aligned.m16n8k16.row.col.f32.f16.f16.f32 "
    "{%0,%1,%2,%3}, {%4,%5,%6,%7}, {%8,%9}, {%0,%1,%2,%3};\n"
    : "+f"(c[0]), "+f"(c[1]), "+f"(c[2]), "+f"(c[3])
    : "r"(a[0]), "r"(a[1]), "r"(a[2]), "r"(a[3]), "r"(b[0]), "r"(b[1]));
}
__device__ __forceinline__ void ldsm4(uint32_t* r, uint32_t addr){
  asm volatile("ldmatrix.sync.aligned.m8n8.x4.shared.b16 {%0,%1,%2,%3}, [%4];"
    : "=r"(r[0]), "=r"(r[1]), "=r"(r[2]), "=r"(r[3]) : "r"(addr));
}
__device__ __forceinline__ void cpa16(uint32_t dst, const void* src){
  asm volatile("cp.async.cg.shared.global [%0], [%1], 16;" :: "r"(dst), "l"(src));
}

// ---------------- weight transpose + fp16 convert ---------------------------
// set 0: in_proj  (K=256,N=1024) -> g_wt1[w][n][k]
// set 1: x_proj   (K=512,N=48)   -> g_wt2[w][n(64 pad)][k]
// set 2: out_proj (K=512,N=256)  -> g_wt4[w][n][k]
__global__ void wtrans_ker(const float* __restrict__ ip, const float* __restrict__ xp,
                           const float* __restrict__ op){
  int s = blockIdx.z >> 3;
  int w = blockIdx.z & 7;
  int K = (s==0)?256:512;
  int N = (s==0)?1024:((s==1)?48:256);
  int Nout = (s==1)?64:N;
  const float* src = (s==0)?ip:((s==1)?xp:op);
  __half* dst = (s==0)?g_wt1:((s==1)?g_wt2:g_wt4);
  src += (size_t)w*K*N; dst += (size_t)w*(size_t)Nout*K;
  int k0 = blockIdx.x*32, n0 = blockIdx.y*32;
  if (k0 >= K || n0 >= Nout) return;
  __shared__ float tile[32][33];
  int tx = threadIdx.x, ty = threadIdx.y;
  for (int i = ty; i < 32; i += 8){
    int k = k0+i, n = n0+tx;
    tile[i][tx] = (k < K && n < N) ? src[(size_t)k*N + n] : 0.f;
  }
  __syncthreads();
  for (int i = ty; i < 32; i += 8){
    int n = n0+i, k = k0+tx;
    if (n < Nout && k < K) dst[(size_t)n*K + k] = __float2half(tile[tx][i]);
  }
}

// ---------------- elementwise kernels --------------------------------------
__global__ void add_pe_ker(const float* __restrict__ x, const float* __restrict__ pe){
  int i = blockIdx.x, c = threadIdx.x;
  int t = i % Tt;
  float v = x[(size_t)i*DMF + c] + pe[t*DMF + c];
  g_x [(size_t)i*DMF + c] = v;
  g_xh[(size_t)i*DMF + c] = __float2half(v);
}
__global__ void transpose_ker(){
  int p = blockIdx.x, b = blockIdx.y, c = threadIdx.x;
  int o = p % Oo, t = p / Oo;
  g_seq1h[((size_t)(b*LL) + p)*DMF + c] =
      __float2half(g_x[((size_t)(b*LL) + (o*Tt + t))*DMF + c]);
}
__global__ void copy_out_ker(float* __restrict__ out){
  int i = blockIdx.x, c = threadIdx.x;
  out[(size_t)i*DMF + c] = g_x[(size_t)i*DMF + c];
}

// ---------------- fp16 tensor-core GEMM (ldmatrix + cp.async) --------------
// C[z] (MM x Ntot) fp32 = A[z] (MM x K) half @ Wt[l*4+z]^T (Nt x K half, K-major)
// CTA 128 x NT, BK=32 halfs; 8 warps 2(m) x 4(n); warp tile 64 x NT/4.
// Smem rows padded to 40 halfs (80 B) -> conflict-free ldmatrix.
#define STRH 40
#define ABUF (128*STRH)            // halfs per A buffer (5120)
template<int NT>
__global__ void __launch_bounds__(256) hgemm_ker(
    const __half* __restrict__ A0, const __half* __restrict__ A1, size_t zstr,
    const __half* __restrict__ WtB, float* __restrict__ Cb, int K, int Ntot, int l)
{
  constexpr int BBUF = NT*STRH;
  extern __shared__ __half smh[];
  const uint32_t sb = (uint32_t)__cvta_generic_to_shared(smh);
  const uint32_t aOff[2] = {0u, (uint32_t)ABUF*2u};
  const uint32_t bOff[2] = {(uint32_t)(2*ABUF)*2u, (uint32_t)(2*ABUF + BBUF)*2u};

  const int z = blockIdx.z;
  const __half* A = zstr ? (A0 + (size_t)z*zstr) : (z < 2 ? A0 : A1);
  const int n0 = blockIdx.y * NT;
  const int Nrows = (Ntot==48) ? 64 : Ntot;
  const __half* Wt = WtB + ((size_t)(l*4 + z)*Nrows + n0) * K;
  float* C = Cb + (size_t)z * (size_t)MM * Ntot;

  const int tid  = threadIdx.x;
  const int lane = tid & 31;
  const int w    = tid >> 5;
  constexpr int WN = NT/4;           // warp n-extent (32 or 16)
  constexpr int NATOMS = WN/8;       // 4 or 2
  constexpr int NPAIRS = WN/16;      // 2 or 1
  const int wm = (w & 1) * 64;
  const int wn = (w >> 1) * WN;
  const int row0 = blockIdx.x * 128;

  float acc[4][NATOMS][4];
  #pragma unroll
  for (int ma = 0; ma < 4; ma++)
    #pragma unroll
    for (int na = 0; na < NATOMS; na++)
      #pragma unroll
      for (int q = 0; q < 4; q++) acc[ma][na][q] = 0.f;

  // cp.async indices: 16B = 8 halfs
  const int a_r = tid >> 1;                 // 0..127
  const int a_u = (tid & 1) * 2;            // chunk pairs
  // ldmatrix per-lane byte offsets (within buffer)
  const uint32_t aLd = (uint32_t)((wm + (lane & 15))*STRH + (lane >> 4)*8) * 2u;
  const int nloc = ((lane & 16) >> 1) | (lane & 7);        // 0-7 / 8-15
  const uint32_t bLd = (uint32_t)((wn + nloc)*STRH + ((lane >> 3) & 1)*8) * 2u;

  auto load_chunk = [&](int buf, int c){
    const int kb = c*32;
    const uint32_t ab = sb + aOff[buf];
    const uint32_t bb = sb + bOff[buf];
    #pragma unroll
    for (int u = 0; u < 2; u++)
      cpa16(ab + (uint32_t)(a_r*STRH + (a_u+u)*8)*2u,
            &A[(size_t)(row0 + a_r)*K + kb + (a_u+u)*8]);
    #pragma unroll
    for (int it = 0; it < NT/64; it++){
      int idx = tid + it*256;
      int r = idx >> 2, u = idx & 3;
      cpa16(bb + (uint32_t)(r*STRH + u*8)*2u,
            &Wt[(size_t)r*K + kb + u*8]);
    }
    asm volatile("cp.async.commit_group;" ::: "memory");
  };

  auto compute = [&](int buf){
    const uint32_t ab = sb + aOff[buf];
    const uint32_t bb = sb + bOff[buf];
    #pragma unroll
    for (int ks = 0; ks < 2; ks++){
      uint32_t af[4][4];
      #pragma unroll
      for (int ma = 0; ma < 4; ma++)
        ldsm4(af[ma], ab + aLd + (uint32_t)(ma*16*STRH + ks*16)*2u);
      uint32_t bf[2*NPAIRS][2];
      #pragma unroll
      for (int np = 0; np < NPAIRS; np++){
        uint32_t r4[4];
        ldsm4(r4, bb + bLd + (uint32_t)(np*16*STRH + ks*16)*2u);
        bf[np*2+0][0] = r4[0]; bf[np*2+0][1] = r4[1];
        bf[np*2+1][0] = r4[2]; bf[np*2+1][1] = r4[3];
      }
      #pragma unroll
      for (int ma = 0; ma < 4; ma++)
        #pragma unroll
        for (int na = 0; na < NATOMS; na++)
          mma_f16(acc[ma][na], af[ma], bf[na]);
    }
  };

  const int nc = K / 32;
  load_chunk(0, 0);
  for (int c = 0; c < nc; c++){
    const int buf = c & 1;
    if (c + 1 < nc){
      load_chunk(buf ^ 1, c + 1);
      asm volatile("cp.async.wait_group 1;" ::: "memory");
    } else {
      asm volatile("cp.async.wait_group 0;" ::: "memory");
    }
    __syncthreads();
    compute(buf);
    __syncthreads();
  }

  #pragma unroll
  for (int ma = 0; ma < 4; ma++){
    const int r = row0 + wm + ma*16 + (lane >> 2);
    #pragma unroll
    for (int na = 0; na < NATOMS; na++){
      const int cc = n0 + wn + na*8 + (lane & 3)*2;
      if (cc < Ntot){
        *reinterpret_cast<float2*>(&C[(size_t)r*Ntot + cc])     = make_float2(acc[ma][na][0], acc[ma][na][1]);
        *reinterpret_cast<float2*>(&C[(size_t)(r+8)*Ntot + cc]) = make_float2(acc[ma][na][2], acc[ma][na][3]);
      }
    }
  }
}

// ---------------- depthwise causal conv (dir-aware) + SiLU, float4 ---------
__global__ void conv_ker(const float* __restrict__ conv_w, const float* __restrict__ conv_b, int l){
  int z   = blockIdx.y;
  int gid = blockIdx.x*256 + threadIdx.x;
  int i  = gid / (DIF/4);
  int dq = gid % (DIF/4);
  int d  = dq * 4;
  int b = i / LL, t = i % LL;
  int widx = l*4 + z;
  const float* xz = g_xz[z];
  const float4 wA = *reinterpret_cast<const float4*>(&conv_w[(size_t)(widx*DIF + d+0)*4]);
  const float4 wB = *reinterpret_cast<const float4*>(&conv_w[(size_t)(widx*DIF + d+1)*4]);
  const float4 wC = *reinterpret_cast<const float4*>(&conv_w[(size_t)(widx*DIF + d+2)*4]);
  const float4 wD = *reinterpret_cast<const float4*>(&conv_w[(size_t)(widx*DIF + d+3)*4]);
  float wt[4][4] = {{wA.x,wA.y,wA.z,wA.w},{wB.x,wB.y,wB.z,wB.w},
                    {wC.x,wC.y,wC.z,wC.w},{wD.x,wD.y,wD.z,wD.w}};
  float4 s = *reinterpret_cast<const float4*>(&conv_b[(size_t)widx*DIF + d]);
  size_t base = (size_t)b*LL;
  if ((z & 1) == 0){
    #pragma unroll
    for (int k = 0; k < 4; k++){
      int tt = t + k - 3;
      if (tt >= 0){
        float4 v = *reinterpret_cast<const float4*>(&xz[(base + tt)*1024 + d]);
        s.x = fmaf(wt[0][k], v.x, s.x);
        s.y = fmaf(wt[1][k], v.y, s.y);
        s.z = fmaf(wt[2][k], v.z, s.z);
        s.w = fmaf(wt[3][k], v.w, s.w);
      }
    }
  } else {
    #pragma unroll
    for (int j = 0; j < 4; j++){
      int tt = t + j;
      if (tt < LL){
        float4 v = *reinterpret_cast<const float4*>(&xz[(base + tt)*1024 + d]);
        s.x = fmaf(wt[0][3-j], v.x, s.x);
        s.y = fmaf(wt[1][3-j], v.y, s.y);
        s.z = fmaf(wt[2][3-j], v.z, s.z);
        s.w = fmaf(wt[3][3-j], v.w, s.w);
      }
    }
  }
  float4 o;
  o.x = siluf(s.x); o.y = siluf(s.y); o.z = siluf(s.z); o.w = siluf(s.w);
  *reinterpret_cast<float4*>(&g_xc[z][(size_t)i*DIF + d]) = o;
  __half2* oh = reinterpret_cast<__half2*>(&g_xch[z][(size_t)i*DIF + d]);
  oh[0] = __floats2half2_rn(o.x, o.y);
  oh[1] = __floats2half2_rn(o.z, o.w);
}

// ---------------- selective scan: fused delta + scan + D-skip + gate -------
#define SCH 64
__global__ void __launch_bounds__(128) scan_ker(const float* __restrict__ A_log,
                                                const float* __restrict__ Dp,
                                                const float* __restrict__ dtw,
                                                const float* __restrict__ dtb, int l){
  int z = blockIdx.z, b = blockIdx.y;
  int d = blockIdx.x*128 + threadIdx.x;
  int tid = threadIdx.x;
  int widx = l*4 + z;
  bool bwd = (z & 1);
  const float* xc  = g_xc[z];
  const float* dbl = g_dbl[z];
  const float* xz  = g_xz[z];
  __half* u = g_uh[z];

  float W[16];
  #pragma unroll
  for (int k = 0; k < 16; k++) W[k] = dtw[((size_t)widx*16 + k)*DIF + d];
  float bia = dtb[(size_t)widx*DIF + d];

  float Av[16];
  #pragma unroll
  for (int s = 0; s < 16; s++)
    Av[s] = -expf(A_log[((size_t)widx*DIF + d)*DSF + s]);
  bool pc = true;
  #pragma unroll
  for (int s = 1; s < 16; s++)
    pc = pc && (fabsf(Av[s] - (float)(s+1)*Av[0]) <= 1e-4f * fabsf(Av[s]));
  float Dpar = Dp[(size_t)widx*DIF + d];

  float h[16];
  #pragma unroll
  for (int s = 0; s < 16; s++) h[s] = 0.f;

  __shared__ __align__(16) float4 sRaw[SCH][12];

  int t0 = bwd ? (LL-1) : 0;
  float nxc = xc[(size_t)(b*LL + t0)*DIF + d];
  float nzv = xz[(size_t)(b*LL + t0)*1024 + DIF + d];

  for (int c0 = 0; c0 < LL; c0 += SCH){
    __syncthreads();
    #pragma unroll
    for (int v = 0; v < 6; v++){
      int idx = tid + v*128;
      int ls = idx / 12, q = idx - ls*12;
      int t = bwd ? (LL-1 - (c0+ls)) : (c0+ls);
      sRaw[ls][q] = *reinterpret_cast<const float4*>(&dbl[(size_t)(b*LL + t)*48 + q*4]);
    }
    __syncthreads();
    for (int ls = 0; ls < SCH; ls++){
      int gi = c0 + ls;
      int t  = bwd ? (LL-1 - gi) : gi;
      size_t rowd = (size_t)(b*LL + t)*DIF + d;
      float xcv = nxc, zv = nzv;
      if (gi + 1 < LL){
        int t2 = bwd ? (LL-1 - (gi+1)) : (gi+1);
        nxc = xc[(size_t)(b*LL + t2)*DIF + d];
        nzv = xz[(size_t)(b*LL + t2)*1024 + DIF + d];
      }
      float4 q0 = sRaw[ls][0], q1 = sRaw[ls][1], q2 = sRaw[ls][2], q3 = sRaw[ls][3];
      float a = bia;
      a = fmaf(q0.x, W[0],  a); a = fmaf(q0.y, W[1],  a);
      a = fmaf(q0.z, W[2],  a); a = fmaf(q0.w, W[3],  a);
      a = fmaf(q1.x, W[4],  a); a = fmaf(q1.y, W[5],  a);
      a = fmaf(q1.z, W[6],  a); a = fmaf(q1.w, W[7],  a);
      a = fmaf(q2.x, W[8],  a); a = fmaf(q2.y, W[9],  a);
      a = fmaf(q2.z, W[10], a); a = fmaf(q2.w, W[11], a);
      a = fmaf(q3.x, W[12], a); a = fmaf(q3.y, W[13], a);
      a = fmaf(q3.z, W[14], a); a = fmaf(q3.w, W[15], a);
      float dv = fmaxf(a, 0.f) + log1pf(__expf(-fabsf(a)));
      float du = dv * xcv;

      float acc = 0.f;
      if (pc){
        float e = __expf(dv * Av[0]);
        float p = 1.f;
        #pragma unroll
        for (int q = 0; q < 4; q++){
          float4 B4 = sRaw[ls][4+q];
          float4 C4 = sRaw[ls][8+q];
          p *= e; h[q*4+0] = fmaf(p, h[q*4+0], du*B4.x); acc = fmaf(h[q*4+0], C4.x, acc);
          p *= e; h[q*4+1] = fmaf(p, h[q*4+1], du*B4.y); acc = fmaf(h[q*4+1], C4.y, acc);
          p *= e; h[q*4+2] = fmaf(p, h[q*4+2], du*B4.z); acc = fmaf(h[q*4+2], C4.z, acc);
          p *= e; h[q*4+3] = fmaf(p, h[q*4+3], du*B4.w); acc = fmaf(h[q*4+3], C4.w, acc);
        }
      } else {
        #pragma unroll
        for (int q = 0; q < 4; q++){
          float4 B4 = sRaw[ls][4+q];
          float4 C4 = sRaw[ls][8+q];
          float a0 = __expf(dv*Av[q*4+0]); h[q*4+0] = fmaf(a0, h[q*4+0], du*B4.x); acc = fmaf(h[q*4+0], C4.x, acc);
          float a1 = __expf(dv*Av[q*4+1]); h[q*4+1] = fmaf(a1, h[q*4+1], du*B4.y); acc = fmaf(h[q*4+1], C4.y, acc);
          float a2 = __expf(dv*Av[q*4+2]); h[q*4+2] = fmaf(a2, h[q*4+2], du*B4.z); acc = fmaf(h[q*4+2], C4.z, acc);
          float a3 = __expf(dv*Av[q*4+3]); h[q*4+3] = fmaf(a3, h[q*4+3], du*B4.w); acc = fmaf(h[q*4+3], C4.w, acc);
        }
      }
      float y = acc + xcv * Dpar;
      u[rowd] = __float2half(y * siluf(zv));
    }
  }
}

// ---------------- combine: LN(o0+o1), LN(o2+o3), residual add --------------
__global__ void combine_ker(const float* __restrict__ lnw, const float* __restrict__ lnb){
  int i = blockIdx.x, c = threadIdx.x;
  float a  = g_o[0][(size_t)i*DMF + c] + g_o[1][(size_t)i*DMF + c];
  float bv = g_o[2][(size_t)i*DMF + c] + g_o[3][(size_t)i*DMF + c];
  __shared__ float r1[256], r2[256];
  r1[c] = a; r2[c] = bv; __syncthreads();
  for (int s = 128; s > 0; s >>= 1){
    if (c < s){ r1[c] += r1[c+s]; r2[c] += r2[c+s]; }
    __syncthreads();
  }
  float ma = r1[0] * (1.f/DMF), mb = r2[0] * (1.f/DMF);
  __syncthreads();
  float da = a - ma, db = bv - mb;
  r1[c] = da*da; r2[c] = db*db; __syncthreads();
  for (int s = 128; s > 0; s >>= 1){
    if (c < s){ r1[c] += r1[c+s]; r2[c] += r2[c+s]; }
    __syncthreads();
  }
  float va = r1[0] * (1.f/DMF), vb = r2[0] * (1.f/DMF);
  float s1 = da * rsqrtf(va + 1e-5f) * lnw[c] + lnb[c];
  float s2 = db * rsqrtf(vb + 1e-5f) * lnw[c] + lnb[c];
  float nv = g_x[(size_t)i*DMF + c] + 0.5f * (s1 + s2);
  g_x [(size_t)i*DMF + c] = nv;
  g_xh[(size_t)i*DMF + c] = __float2half(nv);
}

// ---------------- host orchestration ---------------------------------------
#define SMEM_H128 ((2*ABUF + 2*128*STRH)*2)   // 40960 B
#define SMEM_H64  ((2*ABUF + 2*64*STRH)*2)    // 30720 B

extern "C" void kernel_launch(void* const* d_in, const int* in_sizes, int n_in,
                              void* d_out, int out_size){
  const float* x       = (const float*)d_in[0];
  const float* pe      = (const float*)d_in[1];
  const float* ln_w    = (const float*)d_in[2];
  const float* ln_b    = (const float*)d_in[3];
  const float* in_proj = (const float*)d_in[4];
  const float* conv_w  = (const float*)d_in[5];
  const float* conv_b  = (const float*)d_in[6];
  const float* x_proj  = (const float*)d_in[7];
  const float* dt_w    = (const float*)d_in[8];
  const float* dt_b    = (const float*)d_in[9];
  const float* A_log   = (const float*)d_in[10];
  const float* Dp      = (const float*)d_in[11];
  const float* out_prj = (const float*)d_in[12];

  void *pxh, *pseq1h, *pxz, *pxch, *pdbl, *puh, *po, *pw1, *pw2, *pw4;
  cudaGetSymbolAddress(&pxh,    g_xh);
  cudaGetSymbolAddress(&pseq1h, g_seq1h);
  cudaGetSymbolAddress(&pxz,    g_xz);
  cudaGetSymbolAddress(&pxch,   g_xch);
  cudaGetSymbolAddress(&pdbl,   g_dbl);
  cudaGetSymbolAddress(&puh,    g_uh);
  cudaGetSymbolAddress(&po,     g_o);
  cudaGetSymbolAddress(&pw1,    g_wt1);
  cudaGetSymbolAddress(&pw2,    g_wt2);
  cudaGetSymbolAddress(&pw4,    g_wt4);

  // launch 1: weight transpose + half convert
  wtrans_ker<<<dim3(16, 32, 24), dim3(32, 8)>>>(in_proj, x_proj, out_prj);
  // launch 2
  add_pe_ker<<<MM, 256>>>(x, pe);

  for (int l = 0; l < NLAY; l++){
    transpose_ker<<<dim3(LL, Bb), 256>>>();
    // GEMM1: xz[z] = seq @ in_proj[l,z]  (N=1024, K=256)
    hgemm_ker<128><<<dim3(MM/128, 8, 4), 256, SMEM_H128>>>(
        (const __half*)pxh, (const __half*)pseq1h, (size_t)0,
        (const __half*)pw1, (float*)pxz, 256, 1024, l);
    conv_ker<<<dim3((MM*(DIF/4))/256, 4), 256>>>(conv_w, conv_b, l);
    // GEMM2: dbl[z] = xc[z] @ x_proj (N=48 pad 64, K=512)
    hgemm_ker<64><<<dim3(MM/128, 1, 4), 256, SMEM_H64>>>(
        (const __half*)pxch, (const __half*)0, (size_t)MM*DIF,
        (const __half*)pw2, (float*)pdbl, 512, 48, l);
    scan_ker<<<dim3(4, Bb, 4), 128>>>(A_log, Dp, dt_w, dt_b, l);
    // GEMM4: o[z] = u[z] @ out_proj (N=256, K=512)
    hgemm_ker<128><<<dim3(MM/128, 2, 4), 256, SMEM_H128>>>(
        (const __half*)puh, (const __half*)0, (size_t)MM*DIF,
        (const __half*)pw4, (float*)po, 512, 256, l);
    combine_ker<<<MM, 256>>>(ln_w, ln_b);
  }

  copy_out_ker<<<MM, 256>>>((float*)d_out);
}

// round 7
// speedup vs baseline: 3.8685x; 1.5418x over previous
#include <cuda_runtime.h>
#include <cuda_fp16.h>
#include <math.h>
#include <stdint.h>

// Problem dims
#define Bb   8
#define Oo   12
#define Tt   64
#define DMF  256
#define DIF  512
#define DSF  16
#define LL   768          // Oo*Tt
#define MM   6144         // Bb*LL
#define NLAY 2

// ---------------- scratch (static device globals; no runtime allocs) -------
__device__ float  g_x   [MM*DMF];                     // fp32 residual stream
__device__ __align__(16) __half g_xh  [MM*DMF];       // half copy (GEMM1 A, blk0)
__device__ __align__(16) __half g_seq1h[MM*DMF];      // half transposed (GEMM1 A, blk1)
__device__ float  g_xz  [4][(size_t)MM*2*DIF];        // GEMM1 out (fp32)
__device__ float  g_xc  [4][(size_t)MM*DIF];          // conv out (fp32) [unused by scan now]
__device__ __align__(16) __half g_xch [4][(size_t)MM*DIF];   // conv out (half)
__device__ __align__(16) __half g_zh  [4][(size_t)MM*DIF];   // z-gate (half)
__device__ float  g_dbl [4][(size_t)MM*48];           // GEMM2 out
__device__ __align__(16) __half g_uh  [4][(size_t)MM*DIF];   // scan out (half, GEMM4 A)
__device__ float  g_o   [4][(size_t)MM*DMF];          // GEMM4 out
// transposed + half weights: [w][n][k]
__device__ __align__(16) __half g_wt1[8*1024*256];
__device__ __align__(16) __half g_wt2[8*64*512];
__device__ __align__(16) __half g_wt4[8*256*512];

__device__ __forceinline__ float siluf(float x){ return x / (1.f + __expf(-x)); }

// ---------------- PTX helpers ----------------------------------------------
__device__ __forceinline__ void mma_f16(float* c, const uint32_t* a, const uint32_t* b){
  asm volatile(
    "mma.sync.aligned.m16n8k16.row.col.f32.f16.f16.f32 "
    "{%0,%1,%2,%3}, {%4,%5,%6,%7}, {%8,%9}, {%0,%1,%2,%3};\n"
    : "+f"(c[0]), "+f"(c[1]), "+f"(c[2]), "+f"(c[3])
    : "r"(a[0]), "r"(a[1]), "r"(a[2]), "r"(a[3]), "r"(b[0]), "r"(b[1]));
}
__device__ __forceinline__ void ldsm4(uint32_t* r, uint32_t addr){
  asm volatile("ldmatrix.sync.aligned.m8n8.x4.shared.b16 {%0,%1,%2,%3}, [%4];"
    : "=r"(r[0]), "=r"(r[1]), "=r"(r[2]), "=r"(r[3]) : "r"(addr));
}
__device__ __forceinline__ void cpa16(uint32_t dst, const void* src){
  asm volatile("cp.async.cg.shared.global [%0], [%1], 16;" :: "r"(dst), "l"(src));
}

// ---------------- weight transpose + fp16 convert ---------------------------
__global__ void wtrans_ker(const float* __restrict__ ip, const float* __restrict__ xp,
                           const float* __restrict__ op){
  int s = blockIdx.z >> 3;
  int w = blockIdx.z & 7;
  int K = (s==0)?256:512;
  int N = (s==0)?1024:((s==1)?48:256);
  int Nout = (s==1)?64:N;
  const float* src = (s==0)?ip:((s==1)?xp:op);
  __half* dst = (s==0)?g_wt1:((s==1)?g_wt2:g_wt4);
  src += (size_t)w*K*N; dst += (size_t)w*(size_t)Nout*K;
  int k0 = blockIdx.x*32, n0 = blockIdx.y*32;
  if (k0 >= K || n0 >= Nout) return;
  __shared__ float tile[32][33];
  int tx = threadIdx.x, ty = threadIdx.y;
  for (int i = ty; i < 32; i += 8){
    int k = k0+i, n = n0+tx;
    tile[i][tx] = (k < K && n < N) ? src[(size_t)k*N + n] : 0.f;
  }
  __syncthreads();
  for (int i = ty; i < 32; i += 8){
    int n = n0+i, k = k0+tx;
    if (n < Nout && k < K) dst[(size_t)n*K + k] = __float2half(tile[tx][i]);
  }
}

// ---------------- elementwise kernels --------------------------------------
__global__ void add_pe_ker(const float* __restrict__ x, const float* __restrict__ pe){
  int i = blockIdx.x, c = threadIdx.x;
  int t = i % Tt;
  float v = x[(size_t)i*DMF + c] + pe[t*DMF + c];
  g_x [(size_t)i*DMF + c] = v;
  g_xh[(size_t)i*DMF + c] = __float2half(v);
}
__global__ void transpose_ker(){
  int p = blockIdx.x, b = blockIdx.y, c = threadIdx.x;
  int o = p % Oo, t = p / Oo;
  g_seq1h[((size_t)(b*LL) + p)*DMF + c] =
      __float2half(g_x[((size_t)(b*LL) + (o*Tt + t))*DMF + c]);
}
__global__ void copy_out_ker(float* __restrict__ out){
  int i = blockIdx.x, c = threadIdx.x;
  out[(size_t)i*DMF + c] = g_x[(size_t)i*DMF + c];
}

// ---------------- fp16 tensor-core GEMM (ldmatrix + cp.async) --------------
#define STRH 40
#define ABUF (128*STRH)
template<int NT>
__global__ void __launch_bounds__(256) hgemm_ker(
    const __half* __restrict__ A0, const __half* __restrict__ A1, size_t zstr,
    const __half* __restrict__ WtB, float* __restrict__ Cb, int K, int Ntot, int l)
{
  constexpr int BBUF = NT*STRH;
  extern __shared__ __half smh[];
  const uint32_t sb = (uint32_t)__cvta_generic_to_shared(smh);
  const uint32_t aOff[2] = {0u, (uint32_t)ABUF*2u};
  const uint32_t bOff[2] = {(uint32_t)(2*ABUF)*2u, (uint32_t)(2*ABUF + BBUF)*2u};

  const int z = blockIdx.z;
  const __half* A = zstr ? (A0 + (size_t)z*zstr) : (z < 2 ? A0 : A1);
  const int n0 = blockIdx.y * NT;
  const int Nrows = (Ntot==48) ? 64 : Ntot;
  const __half* Wt = WtB + ((size_t)(l*4 + z)*Nrows + n0) * K;
  float* C = Cb + (size_t)z * (size_t)MM * Ntot;

  const int tid  = threadIdx.x;
  const int lane = tid & 31;
  const int w    = tid >> 5;
  constexpr int WN = NT/4;
  constexpr int NATOMS = WN/8;
  constexpr int NPAIRS = WN/16;
  const int wm = (w & 1) * 64;
  const int wn = (w >> 1) * WN;
  const int row0 = blockIdx.x * 128;

  float acc[4][NATOMS][4];
  #pragma unroll
  for (int ma = 0; ma < 4; ma++)
    #pragma unroll
    for (int na = 0; na < NATOMS; na++)
      #pragma unroll
      for (int q = 0; q < 4; q++) acc[ma][na][q] = 0.f;

  const int a_r = tid >> 1;
  const int a_u = (tid & 1) * 2;
  const uint32_t aLd = (uint32_t)((wm + (lane & 15))*STRH + (lane >> 4)*8) * 2u;
  const int nloc = ((lane & 16) >> 1) | (lane & 7);
  const uint32_t bLd = (uint32_t)((wn + nloc)*STRH + ((lane >> 3) & 1)*8) * 2u;

  auto load_chunk = [&](int buf, int c){
    const int kb = c*32;
    const uint32_t ab = sb + aOff[buf];
    const uint32_t bb = sb + bOff[buf];
    #pragma unroll
    for (int u = 0; u < 2; u++)
      cpa16(ab + (uint32_t)(a_r*STRH + (a_u+u)*8)*2u,
            &A[(size_t)(row0 + a_r)*K + kb + (a_u+u)*8]);
    #pragma unroll
    for (int it = 0; it < NT/64; it++){
      int idx = tid + it*256;
      int r = idx >> 2, u = idx & 3;
      cpa16(bb + (uint32_t)(r*STRH + u*8)*2u,
            &Wt[(size_t)r*K + kb + u*8]);
    }
    asm volatile("cp.async.commit_group;" ::: "memory");
  };

  auto compute = [&](int buf){
    const uint32_t ab = sb + aOff[buf];
    const uint32_t bb = sb + bOff[buf];
    #pragma unroll
    for (int ks = 0; ks < 2; ks++){
      uint32_t af[4][4];
      #pragma unroll
      for (int ma = 0; ma < 4; ma++)
        ldsm4(af[ma], ab + aLd + (uint32_t)(ma*16*STRH + ks*16)*2u);
      uint32_t bf[2*NPAIRS][2];
      #pragma unroll
      for (int np = 0; np < NPAIRS; np++){
        uint32_t r4[4];
        ldsm4(r4, bb + bLd + (uint32_t)(np*16*STRH + ks*16)*2u);
        bf[np*2+0][0] = r4[0]; bf[np*2+0][1] = r4[1];
        bf[np*2+1][0] = r4[2]; bf[np*2+1][1] = r4[3];
      }
      #pragma unroll
      for (int ma = 0; ma < 4; ma++)
        #pragma unroll
        for (int na = 0; na < NATOMS; na++)
          mma_f16(acc[ma][na], af[ma], bf[na]);
    }
  };

  const int nc = K / 32;
  load_chunk(0, 0);
  for (int c = 0; c < nc; c++){
    const int buf = c & 1;
    if (c + 1 < nc){
      load_chunk(buf ^ 1, c + 1);
      asm volatile("cp.async.wait_group 1;" ::: "memory");
    } else {
      asm volatile("cp.async.wait_group 0;" ::: "memory");
    }
    __syncthreads();
    compute(buf);
    __syncthreads();
  }

  #pragma unroll
  for (int ma = 0; ma < 4; ma++){
    const int r = row0 + wm + ma*16 + (lane >> 2);
    #pragma unroll
    for (int na = 0; na < NATOMS; na++){
      const int cc = n0 + wn + na*8 + (lane & 3)*2;
      if (cc < Ntot){
        *reinterpret_cast<float2*>(&C[(size_t)r*Ntot + cc])     = make_float2(acc[ma][na][0], acc[ma][na][1]);
        *reinterpret_cast<float2*>(&C[(size_t)(r+8)*Ntot + cc]) = make_float2(acc[ma][na][2], acc[ma][na][3]);
      }
    }
  }
}

// ---------------- depthwise causal conv + SiLU; also emits half z-gate -----
__global__ void conv_ker(const float* __restrict__ conv_w, const float* __restrict__ conv_b, int l){
  int z   = blockIdx.y;
  int gid = blockIdx.x*256 + threadIdx.x;
  int i  = gid / (DIF/4);
  int dq = gid % (DIF/4);
  int d  = dq * 4;
  int b = i / LL, t = i % LL;
  int widx = l*4 + z;
  const float* xz = g_xz[z];
  const float4 wA = *reinterpret_cast<const float4*>(&conv_w[(size_t)(widx*DIF + d+0)*4]);
  const float4 wB = *reinterpret_cast<const float4*>(&conv_w[(size_t)(widx*DIF + d+1)*4]);
  const float4 wC = *reinterpret_cast<const float4*>(&conv_w[(size_t)(widx*DIF + d+2)*4]);
  const float4 wD = *reinterpret_cast<const float4*>(&conv_w[(size_t)(widx*DIF + d+3)*4]);
  float wt[4][4] = {{wA.x,wA.y,wA.z,wA.w},{wB.x,wB.y,wB.z,wB.w},
                    {wC.x,wC.y,wC.z,wC.w},{wD.x,wD.y,wD.z,wD.w}};
  float4 s = *reinterpret_cast<const float4*>(&conv_b[(size_t)widx*DIF + d]);
  size_t base = (size_t)b*LL;
  if ((z & 1) == 0){
    #pragma unroll
    for (int k = 0; k < 4; k++){
      int tt = t + k - 3;
      if (tt >= 0){
        float4 v = *reinterpret_cast<const float4*>(&xz[(base + tt)*1024 + d]);
        s.x = fmaf(wt[0][k], v.x, s.x);
        s.y = fmaf(wt[1][k], v.y, s.y);
        s.z = fmaf(wt[2][k], v.z, s.z);
        s.w = fmaf(wt[3][k], v.w, s.w);
      }
    }
  } else {
    #pragma unroll
    for (int j = 0; j < 4; j++){
      int tt = t + j;
      if (tt < LL){
        float4 v = *reinterpret_cast<const float4*>(&xz[(base + tt)*1024 + d]);
        s.x = fmaf(wt[0][3-j], v.x, s.x);
        s.y = fmaf(wt[1][3-j], v.y, s.y);
        s.z = fmaf(wt[2][3-j], v.z, s.z);
        s.w = fmaf(wt[3][3-j], v.w, s.w);
      }
    }
  }
  float4 o;
  o.x = siluf(s.x); o.y = siluf(s.y); o.z = siluf(s.z); o.w = siluf(s.w);
  *reinterpret_cast<float4*>(&g_xc[z][(size_t)i*DIF + d]) = o;
  __half2* oh = reinterpret_cast<__half2*>(&g_xch[z][(size_t)i*DIF + d]);
  oh[0] = __floats2half2_rn(o.x, o.y);
  oh[1] = __floats2half2_rn(o.z, o.w);
  // half z-gate for the scan
  float4 zt = *reinterpret_cast<const float4*>(&xz[(size_t)i*1024 + DIF + d]);
  __half2* zh2 = reinterpret_cast<__half2*>(&g_zh[z][(size_t)i*DIF + d]);
  zh2[0] = __floats2half2_rn(zt.x, zt.y);
  zh2[1] = __floats2half2_rn(zt.z, zt.w);
}

// ---------------- selective scan: smem-staged, fused delta + gate ----------
// Per block: 128 d-lanes of one (b, z). Chunks of 64 timesteps double-buffered
// via cp.async: dbl rows (fp32), xc (half), z-gate (half).
#define SCH 64
#define oDBL 0
#define oXC  24576
#define oZ   (24576 + 32768)
#define SCAN_SMEM (24576 + 32768 + 32768)    // 90112 B
__global__ void __launch_bounds__(128) scan_ker(const float* __restrict__ A_log,
                                                const float* __restrict__ Dp,
                                                const float* __restrict__ dtw,
                                                const float* __restrict__ dtb, int l){
  extern __shared__ char ssm[];
  const uint32_t sb = (uint32_t)__cvta_generic_to_shared(ssm);
  int z = blockIdx.z, b = blockIdx.y;
  int tid = threadIdx.x;
  int d0 = blockIdx.x*128;
  int d  = d0 + tid;
  int widx = l*4 + z;
  bool bwd = (z & 1);
  const __half* xch = g_xch[z];
  const __half* zhh = g_zh[z];
  const float*  dbl = g_dbl[z];
  __half* u = g_uh[z];

  float W[16];
  #pragma unroll
  for (int k = 0; k < 16; k++) W[k] = dtw[((size_t)widx*16 + k)*DIF + d];
  float bia = dtb[(size_t)widx*DIF + d];

  float Av[16];
  #pragma unroll
  for (int s = 0; s < 16; s++)
    Av[s] = -expf(A_log[((size_t)widx*DIF + d)*DSF + s]);
  bool pc = true;
  #pragma unroll
  for (int s = 1; s < 16; s++)
    pc = pc && (fabsf(Av[s] - (float)(s+1)*Av[0]) <= 1e-4f * fabsf(Av[s]));
  float Dpar = Dp[(size_t)widx*DIF + d];

  float h[16];
  #pragma unroll
  for (int s = 0; s < 16; s++) h[s] = 0.f;

  auto load_chunk = [&](int c, int buf){
    // dbl: 64 rows x 48 floats = 768 x 16B
    #pragma unroll
    for (int it = 0; it < 6; it++){
      int idx = tid + it*128;
      int ls = idx / 12, q = idx - ls*12;
      int t = bwd ? (LL-1 - (c*SCH+ls)) : (c*SCH+ls);
      cpa16(sb + oDBL + (uint32_t)(((buf*SCH + ls)*12 + q)*16),
            &dbl[(size_t)(b*LL + t)*48 + q*4]);
    }
    // xc: 64 rows x 128 half = 64 x 16 segs of 16B
    #pragma unroll
    for (int it = 0; it < 8; it++){
      int idx = tid + it*128;
      int ls = idx >> 4, sg = idx & 15;
      int t = bwd ? (LL-1 - (c*SCH+ls)) : (c*SCH+ls);
      cpa16(sb + oXC + (uint32_t)(((buf*SCH + ls)*128 + sg*8)*2),
            &xch[(size_t)(b*LL + t)*DIF + d0 + sg*8]);
    }
    // z-gate: same shape
    #pragma unroll
    for (int it = 0; it < 8; it++){
      int idx = tid + it*128;
      int ls = idx >> 4, sg = idx & 15;
      int t = bwd ? (LL-1 - (c*SCH+ls)) : (c*SCH+ls);
      cpa16(sb + oZ + (uint32_t)(((buf*SCH + ls)*128 + sg*8)*2),
            &zhh[(size_t)(b*LL + t)*DIF + d0 + sg*8]);
    }
    asm volatile("cp.async.commit_group;" ::: "memory");
  };

  const int nc = LL / SCH;     // 12
  load_chunk(0, 0);
  for (int c = 0; c < nc; c++){
    const int buf = c & 1;
    if (c + 1 < nc){
      load_chunk(c + 1, buf ^ 1);
      asm volatile("cp.async.wait_group 1;" ::: "memory");
    } else {
      asm volatile("cp.async.wait_group 0;" ::: "memory");
    }
    __syncthreads();

    const float4* sD = reinterpret_cast<const float4*>(ssm + oDBL) + (size_t)buf*SCH*12;
    const __half* sX = reinterpret_cast<const __half*>(ssm + oXC) + (size_t)buf*SCH*128;
    const __half* sZ = reinterpret_cast<const __half*>(ssm + oZ)  + (size_t)buf*SCH*128;

    for (int ls = 0; ls < SCH; ls++){
      int gi = c*SCH + ls;
      int t  = bwd ? (LL-1 - gi) : gi;
      float xcv = __half2float(sX[ls*128 + tid]);
      float zv  = __half2float(sZ[ls*128 + tid]);
      const float4* row = sD + ls*12;
      float4 q0 = row[0], q1 = row[1], q2 = row[2], q3 = row[3];
      // delta GEMV: 4 parallel chains + tree combine
      float a0 = fmaf(q0.x, W[0],  fmaf(q0.y, W[1],  fmaf(q0.z, W[2],  q0.w*W[3])));
      float a1 = fmaf(q1.x, W[4],  fmaf(q1.y, W[5],  fmaf(q1.z, W[6],  q1.w*W[7])));
      float a2 = fmaf(q2.x, W[8],  fmaf(q2.y, W[9],  fmaf(q2.z, W[10], q2.w*W[11])));
      float a3 = fmaf(q3.x, W[12], fmaf(q3.y, W[13], fmaf(q3.z, W[14], q3.w*W[15])));
      float a = bia + ((a0 + a1) + (a2 + a3));
      float dv = fmaxf(a, 0.f) + log1pf(__expf(-fabsf(a)));
      float du = dv * xcv;

      float acc0 = 0.f, acc1 = 0.f, acc2 = 0.f, acc3 = 0.f;
      if (pc){
        // log-depth powers: P[s] = e^(s+1)
        float e1 = __expf(dv * Av[0]);
        float e2 = e1*e1, e3 = e2*e1, e4 = e2*e2;
        float e5 = e4*e1, e6 = e4*e2, e7 = e4*e3, e8 = e4*e4;
        float e9 = e8*e1, e10 = e8*e2, e11 = e8*e3, e12 = e8*e4;
        float e13 = e8*e5, e14 = e8*e6, e15 = e8*e7, e16 = e8*e8;
        float4 B0 = row[4], B1 = row[5], B2 = row[6], B3 = row[7];
        float4 C0 = row[8], C1 = row[9], C2 = row[10], C3 = row[11];
        h[0]  = fmaf(e1,  h[0],  du*B0.x); acc0 = fmaf(h[0],  C0.x, acc0);
        h[1]  = fmaf(e2,  h[1],  du*B0.y); acc1 = fmaf(h[1],  C0.y, acc1);
        h[2]  = fmaf(e3,  h[2],  du*B0.z); acc2 = fmaf(h[2],  C0.z, acc2);
        h[3]  = fmaf(e4,  h[3],  du*B0.w); acc3 = fmaf(h[3],  C0.w, acc3);
        h[4]  = fmaf(e5,  h[4],  du*B1.x); acc0 = fmaf(h[4],  C1.x, acc0);
        h[5]  = fmaf(e6,  h[5],  du*B1.y); acc1 = fmaf(h[5],  C1.y, acc1);
        h[6]  = fmaf(e7,  h[6],  du*B1.z); acc2 = fmaf(h[6],  C1.z, acc2);
        h[7]  = fmaf(e8,  h[7],  du*B1.w); acc3 = fmaf(h[7],  C1.w, acc3);
        h[8]  = fmaf(e9,  h[8],  du*B2.x); acc0 = fmaf(h[8],  C2.x, acc0);
        h[9]  = fmaf(e10, h[9],  du*B2.y); acc1 = fmaf(h[9],  C2.y, acc1);
        h[10] = fmaf(e11, h[10], du*B2.z); acc2 = fmaf(h[10], C2.z, acc2);
        h[11] = fmaf(e12, h[11], du*B2.w); acc3 = fmaf(h[11], C2.w, acc3);
        h[12] = fmaf(e13, h[12], du*B3.x); acc0 = fmaf(h[12], C3.x, acc0);
        h[13] = fmaf(e14, h[13], du*B3.y); acc1 = fmaf(h[13], C3.y, acc1);
        h[14] = fmaf(e15, h[14], du*B3.z); acc2 = fmaf(h[14], C3.z, acc2);
        h[15] = fmaf(e16, h[15], du*B3.w); acc3 = fmaf(h[15], C3.w, acc3);
      } else {
        #pragma unroll
        for (int q = 0; q < 4; q++){
          float4 B4 = row[4+q];
          float4 C4 = row[8+q];
          float b0 = __expf(dv*Av[q*4+0]); h[q*4+0] = fmaf(b0, h[q*4+0], du*B4.x); acc0 = fmaf(h[q*4+0], C4.x, acc0);
          float b1 = __expf(dv*Av[q*4+1]); h[q*4+1] = fmaf(b1, h[q*4+1], du*B4.y); acc1 = fmaf(h[q*4+1], C4.y, acc1);
          float b2 = __expf(dv*Av[q*4+2]); h[q*4+2] = fmaf(b2, h[q*4+2], du*B4.z); acc2 = fmaf(h[q*4+2], C4.z, acc2);
          float b3 = __expf(dv*Av[q*4+3]); h[q*4+3] = fmaf(b3, h[q*4+3], du*B4.w); acc3 = fmaf(h[q*4+3], C4.w, acc3);
        }
      }
      float acc = (acc0 + acc1) + (acc2 + acc3);
      float y = acc + xcv * Dpar;
      u[(size_t)(b*LL + t)*DIF + d] = __float2half(y * siluf(zv));
    }
    __syncthreads();
  }
}

// ---------------- combine: LN(o0+o1), LN(o2+o3), residual add --------------
__global__ void combine_ker(const float* __restrict__ lnw, const float* __restrict__ lnb){
  int i = blockIdx.x, c = threadIdx.x;
  float a  = g_o[0][(size_t)i*DMF + c] + g_o[1][(size_t)i*DMF + c];
  float bv = g_o[2][(size_t)i*DMF + c] + g_o[3][(size_t)i*DMF + c];
  __shared__ float r1[256], r2[256];
  r1[c] = a; r2[c] = bv; __syncthreads();
  for (int s = 128; s > 0; s >>= 1){
    if (c < s){ r1[c] += r1[c+s]; r2[c] += r2[c+s]; }
    __syncthreads();
  }
  float ma = r1[0] * (1.f/DMF), mb = r2[0] * (1.f/DMF);
  __syncthreads();
  float da = a - ma, db = bv - mb;
  r1[c] = da*da; r2[c] = db*db; __syncthreads();
  for (int s = 128; s > 0; s >>= 1){
    if (c < s){ r1[c] += r1[c+s]; r2[c] += r2[c+s]; }
    __syncthreads();
  }
  float va = r1[0] * (1.f/DMF), vb = r2[0] * (1.f/DMF);
  float s1 = da * rsqrtf(va + 1e-5f) * lnw[c] + lnb[c];
  float s2 = db * rsqrtf(vb + 1e-5f) * lnw[c] + lnb[c];
  float nv = g_x[(size_t)i*DMF + c] + 0.5f * (s1 + s2);
  g_x [(size_t)i*DMF + c] = nv;
  g_xh[(size_t)i*DMF + c] = __float2half(nv);
}

// ---------------- host orchestration ---------------------------------------
#define SMEM_H128 ((2*ABUF + 2*128*STRH)*2)   // 40960 B
#define SMEM_H64  ((2*ABUF + 2*64*STRH)*2)    // 30720 B

extern "C" void kernel_launch(void* const* d_in, const int* in_sizes, int n_in,
                              void* d_out, int out_size){
  const float* x       = (const float*)d_in[0];
  const float* pe      = (const float*)d_in[1];
  const float* ln_w    = (const float*)d_in[2];
  const float* ln_b    = (const float*)d_in[3];
  const float* in_proj = (const float*)d_in[4];
  const float* conv_w  = (const float*)d_in[5];
  const float* conv_b  = (const float*)d_in[6];
  const float* x_proj  = (const float*)d_in[7];
  const float* dt_w    = (const float*)d_in[8];
  const float* dt_b    = (const float*)d_in[9];
  const float* A_log   = (const float*)d_in[10];
  const float* Dp      = (const float*)d_in[11];
  const float* out_prj = (const float*)d_in[12];

  void *pxh, *pseq1h, *pxz, *pxch, *pdbl, *puh, *po, *pw1, *pw2, *pw4;
  cudaGetSymbolAddress(&pxh,    g_xh);
  cudaGetSymbolAddress(&pseq1h, g_seq1h);
  cudaGetSymbolAddress(&pxz,    g_xz);
  cudaGetSymbolAddress(&pxch,   g_xch);
  cudaGetSymbolAddress(&pdbl,   g_dbl);
  cudaGetSymbolAddress(&puh,    g_uh);
  cudaGetSymbolAddress(&po,     g_o);
  cudaGetSymbolAddress(&pw1,    g_wt1);
  cudaGetSymbolAddress(&pw2,    g_wt2);
  cudaGetSymbolAddress(&pw4,    g_wt4);

  cudaFuncSetAttribute(scan_ker, cudaFuncAttributeMaxDynamicSharedMemorySize, SCAN_SMEM);

  // launch 1: weight transpose + half convert
  wtrans_ker<<<dim3(16, 32, 24), dim3(32, 8)>>>(in_proj, x_proj, out_prj);
  // launch 2
  add_pe_ker<<<MM, 256>>>(x, pe);

  for (int l = 0; l < NLAY; l++){
    transpose_ker<<<dim3(LL, Bb), 256>>>();
    // GEMM1: xz[z] = seq @ in_proj[l,z]  (N=1024, K=256)
    hgemm_ker<128><<<dim3(MM/128, 8, 4), 256, SMEM_H128>>>(
        (const __half*)pxh, (const __half*)pseq1h, (size_t)0,
        (const __half*)pw1, (float*)pxz, 256, 1024, l);
    conv_ker<<<dim3((MM*(DIF/4))/256, 4), 256>>>(conv_w, conv_b, l);
    // GEMM2: dbl[z] = xc[z] @ x_proj (N=48 pad 64, K=512)
    hgemm_ker<64><<<dim3(MM/128, 1, 4), 256, SMEM_H64>>>(
        (const __half*)pxch, (const __half*)0, (size_t)MM*DIF,
        (const __half*)pw2, (float*)pdbl, 512, 48, l);
    // fused delta + selective scan + gate (smem-staged)
    scan_ker<<<dim3(4, Bb, 4), 128, SCAN_SMEM>>>(A_log, Dp, dt_w, dt_b, l);
    // GEMM4: o[z] = u[z] @ out_proj (N=256, K=512)
    hgemm_ker<128><<<dim3(MM/128, 2, 4), 256, SMEM_H128>>>(
        (const __half*)puh, (const __half*)0, (size_t)MM*DIF,
        (const __half*)pw4, (float*)po, 512, 256, l);
    combine_ker<<<MM, 256>>>(ln_w, ln_b);
  }

  copy_out_ker<<<MM, 256>>>((float*)d_out);
}

// round 8
// speedup vs baseline: 4.6428x; 1.2001x over previous
#include <cuda_runtime.h>
#include <cuda_fp16.h>
#include <math.h>
#include <stdint.h>

// Problem dims
#define Bb   8
#define Oo   12
#define Tt   64
#define DMF  256
#define DIF  512
#define DSF  16
#define LL   768          // Oo*Tt
#define MM   6144         // Bb*LL
#define NLAY 2
#define NSEG 4
#define LSEG 192          // LL/NSEG

// ---------------- scratch (static device globals; no runtime allocs) -------
__device__ float  g_x   [MM*DMF];                     // fp32 residual stream
__device__ __align__(16) __half g_xh  [MM*DMF];       // half residual copy
__device__ float  g_xz  [4][(size_t)MM*2*DIF];        // GEMM1 out (fp32)
__device__ __align__(16) __half g_xch [4][(size_t)MM*DIF];   // conv out (half)
__device__ __align__(16) __half g_zh  [4][(size_t)MM*DIF];   // z-gate (half)
__device__ float  g_dbl [4][(size_t)MM*48];           // GEMM2 out
__device__ __align__(16) __half g_uh  [4][(size_t)MM*DIF];   // scan out (half)
__device__ __align__(8)  __half2 g_dg [4][(size_t)MM*DIF];   // (dv, gate) per step
__device__ float  g_hf  [4*8*NSEG*DIF*16];            // per-segment final h
__device__ float  g_sdv [4*8*NSEG*DIF];               // per-segment sum(dv)
__device__ float  g_o   [4][(size_t)MM*DMF];          // GEMM4 out
// transposed + half weights: [w][n][k]
__device__ __align__(16) __half g_wt1[8*1024*256];
__device__ __align__(16) __half g_wt2[8*64*512];
__device__ __align__(16) __half g_wt4[8*256*512];

__device__ __forceinline__ float siluf(float x){ return x / (1.f + __expf(-x)); }

// ---------------- PTX helpers ----------------------------------------------
__device__ __forceinline__ void mma_f16(float* c, const uint32_t* a, const uint32_t* b){
  asm volatile(
    "mma.sync.aligned.m16n8k16.row.col.f32.f16.f16.f32 "
    "{%0,%1,%2,%3}, {%4,%5,%6,%7}, {%8,%9}, {%0,%1,%2,%3};\n"
    : "+f"(c[0]), "+f"(c[1]), "+f"(c[2]), "+f"(c[3])
    : "r"(a[0]), "r"(a[1]), "r"(a[2]), "r"(a[3]), "r"(b[0]), "r"(b[1]));
}
__device__ __forceinline__ void ldsm4(uint32_t* r, uint32_t addr){
  asm volatile("ldmatrix.sync.aligned.m8n8.x4.shared.b16 {%0,%1,%2,%3}, [%4];"
    : "=r"(r[0]), "=r"(r[1]), "=r"(r[2]), "=r"(r[3]) : "r"(addr));
}
__device__ __forceinline__ void cpa16(uint32_t dst, const void* src){
  asm volatile("cp.async.cg.shared.global [%0], [%1], 16;" :: "r"(dst), "l"(src));
}

// ---------------- weight transpose + fp16 convert ---------------------------
__global__ void wtrans_ker(const float* __restrict__ ip, const float* __restrict__ xp,
                           const float* __restrict__ op){
  int s = blockIdx.z >> 3;
  int w = blockIdx.z & 7;
  int K = (s==0)?256:512;
  int N = (s==0)?1024:((s==1)?48:256);
  int Nout = (s==1)?64:N;
  const float* src = (s==0)?ip:((s==1)?xp:op);
  __half* dst = (s==0)?g_wt1:((s==1)?g_wt2:g_wt4);
  src += (size_t)w*K*N; dst += (size_t)w*(size_t)Nout*K;
  int k0 = blockIdx.x*32, n0 = blockIdx.y*32;
  if (k0 >= K || n0 >= Nout) return;
  __shared__ float tile[32][33];
  int tx = threadIdx.x, ty = threadIdx.y;
  for (int i = ty; i < 32; i += 8){
    int k = k0+i, n = n0+tx;
    tile[i][tx] = (k < K && n < N) ? src[(size_t)k*N + n] : 0.f;
  }
  __syncthreads();
  for (int i = ty; i < 32; i += 8){
    int n = n0+i, k = k0+tx;
    if (n < Nout && k < K) dst[(size_t)n*K + k] = __float2half(tile[tx][i]);
  }
}

// ---------------- elementwise kernels --------------------------------------
__global__ void add_pe_ker(const float* __restrict__ x, const float* __restrict__ pe){
  int i = blockIdx.x, c = threadIdx.x;
  int t = i % Tt;
  float v = x[(size_t)i*DMF + c] + pe[t*DMF + c];
  g_x [(size_t)i*DMF + c] = v;
  g_xh[(size_t)i*DMF + c] = __float2half(v);
}
__global__ void copy_out_ker(float* __restrict__ out){
  int i = blockIdx.x, c = threadIdx.x;
  out[(size_t)i*DMF + c] = g_x[(size_t)i*DMF + c];
}

// ---------------- fp16 tensor-core GEMM (ldmatrix + cp.async) --------------
// perm!=0: for z>=2, A rows are the (o,t)->(t,o) permutation of A0 rows.
#define STRH 40
#define ABUF (128*STRH)
template<int NT>
__global__ void __launch_bounds__(256) hgemm_ker(
    const __half* __restrict__ A0, size_t zstr,
    const __half* __restrict__ WtB, float* __restrict__ Cb,
    int K, int Ntot, int l, int perm)
{
  constexpr int BBUF = NT*STRH;
  extern __shared__ __half smh[];
  const uint32_t sb = (uint32_t)__cvta_generic_to_shared(smh);
  const uint32_t aOff[2] = {0u, (uint32_t)ABUF*2u};
  const uint32_t bOff[2] = {(uint32_t)(2*ABUF)*2u, (uint32_t)(2*ABUF + BBUF)*2u};

  const int z = blockIdx.z;
  const __half* A = A0 + (size_t)z*zstr;
  const int n0 = blockIdx.y * NT;
  const int Nrows = (Ntot==48) ? 64 : Ntot;
  const __half* Wt = WtB + ((size_t)(l*4 + z)*Nrows + n0) * K;
  float* C = Cb + (size_t)z * (size_t)MM * Ntot;

  const int tid  = threadIdx.x;
  const int lane = tid & 31;
  const int w    = tid >> 5;
  constexpr int WN = NT/4;
  constexpr int NATOMS = WN/8;
  constexpr int NPAIRS = WN/16;
  const int wm = (w & 1) * 64;
  const int wn = (w >> 1) * WN;
  const int row0 = blockIdx.x * 128;

  float acc[4][NATOMS][4];
  #pragma unroll
  for (int ma = 0; ma < 4; ma++)
    #pragma unroll
    for (int na = 0; na < NATOMS; na++)
      #pragma unroll
      for (int q = 0; q < 4; q++) acc[ma][na][q] = 0.f;

  const int a_r = tid >> 1;
  const int a_u = (tid & 1) * 2;
  // per-thread A source row (permuted for z>=2 when perm)
  int grow = row0 + a_r;
  if (perm && z >= 2){
    int b2 = grow / LL;
    int p  = grow - b2*LL;
    int tq = p / Oo;
    int o  = p - tq*Oo;
    grow = b2*LL + o*Tt + tq;
  }
  const __half* Arow = A + (size_t)grow*K;

  const uint32_t aLd = (uint32_t)((wm + (lane & 15))*STRH + (lane >> 4)*8) * 2u;
  const int nloc = ((lane & 16) >> 1) | (lane & 7);
  const uint32_t bLd = (uint32_t)((wn + nloc)*STRH + ((lane >> 3) & 1)*8) * 2u;

  auto load_chunk = [&](int buf, int c){
    const int kb = c*32;
    const uint32_t ab = sb + aOff[buf];
    const uint32_t bb = sb + bOff[buf];
    #pragma unroll
    for (int u = 0; u < 2; u++)
      cpa16(ab + (uint32_t)(a_r*STRH + (a_u+u)*8)*2u, Arow + kb + (a_u+u)*8);
    #pragma unroll
    for (int it = 0; it < NT/64; it++){
      int idx = tid + it*256;
      int r = idx >> 2, u = idx & 3;
      cpa16(bb + (uint32_t)(r*STRH + u*8)*2u, &Wt[(size_t)r*K + kb + u*8]);
    }
    asm volatile("cp.async.commit_group;" ::: "memory");
  };

  auto compute = [&](int buf){
    const uint32_t ab = sb + aOff[buf];
    const uint32_t bb = sb + bOff[buf];
    #pragma unroll
    for (int ks = 0; ks < 2; ks++){
      uint32_t af[4][4];
      #pragma unroll
      for (int ma = 0; ma < 4; ma++)
        ldsm4(af[ma], ab + aLd + (uint32_t)(ma*16*STRH + ks*16)*2u);
      uint32_t bf[2*NPAIRS][2];
      #pragma unroll
      for (int np = 0; np < NPAIRS; np++){
        uint32_t r4[4];
        ldsm4(r4, bb + bLd + (uint32_t)(np*16*STRH + ks*16)*2u);
        bf[np*2+0][0] = r4[0]; bf[np*2+0][1] = r4[1];
        bf[np*2+1][0] = r4[2]; bf[np*2+1][1] = r4[3];
      }
      #pragma unroll
      for (int ma = 0; ma < 4; ma++)
        #pragma unroll
        for (int na = 0; na < NATOMS; na++)
          mma_f16(acc[ma][na], af[ma], bf[na]);
    }
  };

  const int nc = K / 32;
  load_chunk(0, 0);
  for (int c = 0; c < nc; c++){
    const int buf = c & 1;
    if (c + 1 < nc){
      load_chunk(buf ^ 1, c + 1);
      asm volatile("cp.async.wait_group 1;" ::: "memory");
    } else {
      asm volatile("cp.async.wait_group 0;" ::: "memory");
    }
    __syncthreads();
    compute(buf);
    __syncthreads();
  }

  #pragma unroll
  for (int ma = 0; ma < 4; ma++){
    const int r = row0 + wm + ma*16 + (lane >> 2);
    #pragma unroll
    for (int na = 0; na < NATOMS; na++){
      const int cc = n0 + wn + na*8 + (lane & 3)*2;
      if (cc < Ntot){
        *reinterpret_cast<float2*>(&C[(size_t)r*Ntot + cc])     = make_float2(acc[ma][na][0], acc[ma][na][1]);
        *reinterpret_cast<float2*>(&C[(size_t)(r+8)*Ntot + cc]) = make_float2(acc[ma][na][2], acc[ma][na][3]);
      }
    }
  }
}

// ---------------- depthwise causal conv + SiLU; emits half xc & z-gate -----
__global__ void conv_ker(const float* __restrict__ conv_w, const float* __restrict__ conv_b, int l){
  int z   = blockIdx.y;
  int gid = blockIdx.x*256 + threadIdx.x;
  int i  = gid / (DIF/4);
  int dq = gid % (DIF/4);
  int d  = dq * 4;
  int b = i / LL, t = i % LL;
  int widx = l*4 + z;
  const float* xz = g_xz[z];
  const float4 wA = *reinterpret_cast<const float4*>(&conv_w[(size_t)(widx*DIF + d+0)*4]);
  const float4 wB = *reinterpret_cast<const float4*>(&conv_w[(size_t)(widx*DIF + d+1)*4]);
  const float4 wC = *reinterpret_cast<const float4*>(&conv_w[(size_t)(widx*DIF + d+2)*4]);
  const float4 wD = *reinterpret_cast<const float4*>(&conv_w[(size_t)(widx*DIF + d+3)*4]);
  float wt[4][4] = {{wA.x,wA.y,wA.z,wA.w},{wB.x,wB.y,wB.z,wB.w},
                    {wC.x,wC.y,wC.z,wC.w},{wD.x,wD.y,wD.z,wD.w}};
  float4 s = *reinterpret_cast<const float4*>(&conv_b[(size_t)widx*DIF + d]);
  size_t base = (size_t)b*LL;
  if ((z & 1) == 0){
    #pragma unroll
    for (int k = 0; k < 4; k++){
      int tt = t + k - 3;
      if (tt >= 0){
        float4 v = *reinterpret_cast<const float4*>(&xz[(base + tt)*1024 + d]);
        s.x = fmaf(wt[0][k], v.x, s.x);
        s.y = fmaf(wt[1][k], v.y, s.y);
        s.z = fmaf(wt[2][k], v.z, s.z);
        s.w = fmaf(wt[3][k], v.w, s.w);
      }
    }
  } else {
    #pragma unroll
    for (int j = 0; j < 4; j++){
      int tt = t + j;
      if (tt < LL){
        float4 v = *reinterpret_cast<const float4*>(&xz[(base + tt)*1024 + d]);
        s.x = fmaf(wt[0][3-j], v.x, s.x);
        s.y = fmaf(wt[1][3-j], v.y, s.y);
        s.z = fmaf(wt[2][3-j], v.z, s.z);
        s.w = fmaf(wt[3][3-j], v.w, s.w);
      }
    }
  }
  __half2* oh = reinterpret_cast<__half2*>(&g_xch[z][(size_t)i*DIF + d]);
  oh[0] = __floats2half2_rn(siluf(s.x), siluf(s.y));
  oh[1] = __floats2half2_rn(siluf(s.z), siluf(s.w));
  float4 zt = *reinterpret_cast<const float4*>(&xz[(size_t)i*1024 + DIF + d]);
  __half2* zh2 = reinterpret_cast<__half2*>(&g_zh[z][(size_t)i*DIF + d]);
  zh2[0] = __floats2half2_rn(zt.x, zt.y);
  zh2[1] = __floats2half2_rn(zt.z, zt.w);
}

// ---------------- scan phase 1: per-segment local scan (h0 = 0) ------------
// grid: (4 dblk, 8 b, 16 = z*4+seg), 128 thr. Stores gated partial u,
// per-step (dv,gate) half2, segment-final h (16f) and sum(dv).
#define S1CH 32
#define oDBL 0
#define oXC  12288
#define oZ   28672
#define S1_SMEM 45056
__global__ void __launch_bounds__(128) scan1_ker(const float* __restrict__ A_log,
                                                 const float* __restrict__ Dp,
                                                 const float* __restrict__ dtw,
                                                 const float* __restrict__ dtb, int l){
  extern __shared__ char ssm[];
  const uint32_t sb = (uint32_t)__cvta_generic_to_shared(ssm);
  int tid = threadIdx.x;
  int d0 = blockIdx.x*128, d = d0 + tid;
  int b = blockIdx.y;
  int z = blockIdx.z >> 2, seg = blockIdx.z & 3;
  int widx = l*4 + z;
  bool bwd = (z & 1);
  const __half* xch = g_xch[z];
  const __half* zhh = g_zh[z];
  const float*  dbl = g_dbl[z];
  __half*  u  = g_uh[z];
  __half2* dg = g_dg[z];

  float W[16];
  #pragma unroll
  for (int k = 0; k < 16; k++) W[k] = dtw[((size_t)widx*16 + k)*DIF + d];
  float bia = dtb[(size_t)widx*DIF + d];
  float Av[16];
  #pragma unroll
  for (int s = 0; s < 16; s++)
    Av[s] = -expf(A_log[((size_t)widx*DIF + d)*DSF + s]);
  bool pc = true;
  #pragma unroll
  for (int s = 1; s < 16; s++)
    pc = pc && (fabsf(Av[s] - (float)(s+1)*Av[0]) <= 1e-4f * fabsf(Av[s]));
  float Dpar = Dp[(size_t)widx*DIF + d];

  float h[16];
  #pragma unroll
  for (int s = 0; s < 16; s++) h[s] = 0.f;
  float sumdv = 0.f;
  const int gi0 = seg*LSEG;

  auto load_chunk = [&](int c, int buf){
    #pragma unroll
    for (int it = 0; it < 3; it++){
      int idx = tid + it*128;
      int ls = idx / 12, q = idx - ls*12;
      int gi = gi0 + c*S1CH + ls;
      int t = bwd ? (LL-1 - gi) : gi;
      cpa16(sb + oDBL + (uint32_t)(((buf*S1CH + ls)*12 + q)*16),
            &dbl[(size_t)(b*LL + t)*48 + q*4]);
    }
    #pragma unroll
    for (int it = 0; it < 4; it++){
      int idx = tid + it*128;
      int ls = idx >> 4, sg = idx & 15;
      int gi = gi0 + c*S1CH + ls;
      int t = bwd ? (LL-1 - gi) : gi;
      cpa16(sb + oXC + (uint32_t)(((buf*S1CH + ls)*128 + sg*8)*2),
            &xch[(size_t)(b*LL + t)*DIF + d0 + sg*8]);
      cpa16(sb + oZ + (uint32_t)(((buf*S1CH + ls)*128 + sg*8)*2),
            &zhh[(size_t)(b*LL + t)*DIF + d0 + sg*8]);
    }
    asm volatile("cp.async.commit_group;" ::: "memory");
  };

  const int nc = LSEG / S1CH;   // 6
  load_chunk(0, 0);
  for (int c = 0; c < nc; c++){
    const int buf = c & 1;
    if (c + 1 < nc){
      load_chunk(c + 1, buf ^ 1);
      asm volatile("cp.async.wait_group 1;" ::: "memory");
    } else {
      asm volatile("cp.async.wait_group 0;" ::: "memory");
    }
    __syncthreads();
    const float4* sD = reinterpret_cast<const float4*>(ssm + oDBL) + (size_t)buf*S1CH*12;
    const __half* sX = reinterpret_cast<const __half*>(ssm + oXC) + (size_t)buf*S1CH*128;
    const __half* sZ = reinterpret_cast<const __half*>(ssm + oZ)  + (size_t)buf*S1CH*128;

    for (int ls = 0; ls < S1CH; ls++){
      int gi = gi0 + c*S1CH + ls;
      int t  = bwd ? (LL-1 - gi) : gi;
      float xcv = __half2float(sX[ls*128 + tid]);
      float zv  = __half2float(sZ[ls*128 + tid]);
      const float4* row = sD + ls*12;
      float4 q0 = row[0], q1 = row[1], q2 = row[2], q3 = row[3];
      float a0 = fmaf(q0.x, W[0],  fmaf(q0.y, W[1],  fmaf(q0.z, W[2],  q0.w*W[3])));
      float a1 = fmaf(q1.x, W[4],  fmaf(q1.y, W[5],  fmaf(q1.z, W[6],  q1.w*W[7])));
      float a2 = fmaf(q2.x, W[8],  fmaf(q2.y, W[9],  fmaf(q2.z, W[10], q2.w*W[11])));
      float a3 = fmaf(q3.x, W[12], fmaf(q3.y, W[13], fmaf(q3.z, W[14], q3.w*W[15])));
      float a = bia + ((a0 + a1) + (a2 + a3));
      float dv = fmaxf(a, 0.f) + log1pf(__expf(-fabsf(a)));
      sumdv += dv;
      float du = dv * xcv;

      float acc0 = 0.f, acc1 = 0.f, acc2 = 0.f, acc3 = 0.f;
      if (pc){
        float e1 = __expf(dv * Av[0]);
        float e2 = e1*e1, e3 = e2*e1, e4 = e2*e2;
        float e5 = e4*e1, e6 = e4*e2, e7 = e4*e3, e8 = e4*e4;
        float e9 = e8*e1, e10 = e8*e2, e11 = e8*e3, e12 = e8*e4;
        float e13 = e8*e5, e14 = e8*e6, e15 = e8*e7, e16 = e8*e8;
        float4 B0 = row[4], B1 = row[5], B2 = row[6], B3 = row[7];
        float4 C0 = row[8], C1 = row[9], C2 = row[10], C3 = row[11];
        h[0]  = fmaf(e1,  h[0],  du*B0.x); acc0 = fmaf(h[0],  C0.x, acc0);
        h[1]  = fmaf(e2,  h[1],  du*B0.y); acc1 = fmaf(h[1],  C0.y, acc1);
        h[2]  = fmaf(e3,  h[2],  du*B0.z); acc2 = fmaf(h[2],  C0.z, acc2);
        h[3]  = fmaf(e4,  h[3],  du*B0.w); acc3 = fmaf(h[3],  C0.w, acc3);
        h[4]  = fmaf(e5,  h[4],  du*B1.x); acc0 = fmaf(h[4],  C1.x, acc0);
        h[5]  = fmaf(e6,  h[5],  du*B1.y); acc1 = fmaf(h[5],  C1.y, acc1);
        h[6]  = fmaf(e7,  h[6],  du*B1.z); acc2 = fmaf(h[6],  C1.z, acc2);
        h[7]  = fmaf(e8,  h[7],  du*B1.w); acc3 = fmaf(h[7],  C1.w, acc3);
        h[8]  = fmaf(e9,  h[8],  du*B2.x); acc0 = fmaf(h[8],  C2.x, acc0);
        h[9]  = fmaf(e10, h[9],  du*B2.y); acc1 = fmaf(h[9],  C2.y, acc1);
        h[10] = fmaf(e11, h[10], du*B2.z); acc2 = fmaf(h[10], C2.z, acc2);
        h[11] = fmaf(e12, h[11], du*B2.w); acc3 = fmaf(h[11], C2.w, acc3);
        h[12] = fmaf(e13, h[12], du*B3.x); acc0 = fmaf(h[12], C3.x, acc0);
        h[13] = fmaf(e14, h[13], du*B3.y); acc1 = fmaf(h[13], C3.y, acc1);
        h[14] = fmaf(e15, h[14], du*B3.z); acc2 = fmaf(h[14], C3.z, acc2);
        h[15] = fmaf(e16, h[15], du*B3.w); acc3 = fmaf(h[15], C3.w, acc3);
      } else {
        #pragma unroll
        for (int q = 0; q < 4; q++){
          float4 B4 = row[4+q];
          float4 C4 = row[8+q];
          float b0 = __expf(dv*Av[q*4+0]); h[q*4+0] = fmaf(b0, h[q*4+0], du*B4.x); acc0 = fmaf(h[q*4+0], C4.x, acc0);
          float b1 = __expf(dv*Av[q*4+1]); h[q*4+1] = fmaf(b1, h[q*4+1], du*B4.y); acc1 = fmaf(h[q*4+1], C4.y, acc1);
          float b2 = __expf(dv*Av[q*4+2]); h[q*4+2] = fmaf(b2, h[q*4+2], du*B4.z); acc2 = fmaf(h[q*4+2], C4.z, acc2);
          float b3 = __expf(dv*Av[q*4+3]); h[q*4+3] = fmaf(b3, h[q*4+3], du*B4.w); acc3 = fmaf(h[q*4+3], C4.w, acc3);
        }
      }
      float gate = siluf(zv);
      float y = (acc0 + acc1) + (acc2 + acc3) + xcv * Dpar;
      size_t rowd = (size_t)(b*LL + t)*DIF + d;
      u[rowd]  = __float2half(y * gate);
      dg[rowd] = __floats2half2_rn(dv, gate);
    }
    __syncthreads();
  }
  // store segment-final state + sum(dv)
  int segbase = ((z*8 + b)*NSEG + seg)*DIF + d;
  float4* hf4 = reinterpret_cast<float4*>(&g_hf[(size_t)segbase*16]);
  hf4[0] = make_float4(h[0],  h[1],  h[2],  h[3]);
  hf4[1] = make_float4(h[4],  h[5],  h[6],  h[7]);
  hf4[2] = make_float4(h[8],  h[9],  h[10], h[11]);
  hf4[3] = make_float4(h[12], h[13], h[14], h[15]);
  g_sdv[segbase] = sumdv;
}

// ---------------- scan phase 2: cross-segment correction (segs 1..3) -------
// grid: (4 dblk, 8 b, 12 = z*3 + seg-1), 128 thr.
#define oC2  0
#define oDG2 4096
#define oU2  36864
#define S2_SMEM 53248
__global__ void __launch_bounds__(128) scan2_ker(const float* __restrict__ A_log, int l){
  extern __shared__ char ssm[];
  const uint32_t sb = (uint32_t)__cvta_generic_to_shared(ssm);
  int tid = threadIdx.x;
  int d0 = blockIdx.x*128, d = d0 + tid;
  int b = blockIdx.y;
  int z = blockIdx.z / 3, seg = blockIdx.z - z*3 + 1;
  int widx = l*4 + z;
  bool bwd = (z & 1);
  const float*  dbl = g_dbl[z];
  const __half2* dg = g_dg[z];
  __half* u = g_uh[z];

  float Av[16];
  #pragma unroll
  for (int s = 0; s < 16; s++)
    Av[s] = -expf(A_log[((size_t)widx*DIF + d)*DSF + s]);
  bool pc = true;
  #pragma unroll
  for (int s = 1; s < 16; s++)
    pc = pc && (fabsf(Av[s] - (float)(s+1)*Av[0]) <= 1e-4f * fabsf(Av[s]));

  // combine incoming state: h_in = fold over segments k < seg
  float hin[16];
  #pragma unroll
  for (int s = 0; s < 16; s++) hin[s] = 0.f;
  for (int k = 0; k < seg; k++){
    int kb = ((z*8 + b)*NSEG + k)*DIF + d;
    float sd = g_sdv[kb];
    const float4* hf4 = reinterpret_cast<const float4*>(&g_hf[(size_t)kb*16]);
    float4 f0 = hf4[0], f1 = hf4[1], f2 = hf4[2], f3 = hf4[3];
    float hf[16] = {f0.x,f0.y,f0.z,f0.w, f1.x,f1.y,f1.z,f1.w,
                    f2.x,f2.y,f2.z,f2.w, f3.x,f3.y,f3.z,f3.w};
    if (pc){
      float E = __expf(Av[0]*sd);
      float p = 1.f;
      #pragma unroll
      for (int s = 0; s < 16; s++){ p *= E; hin[s] = fmaf(p, hin[s], hf[s]); }
    } else {
      #pragma unroll
      for (int s = 0; s < 16; s++) hin[s] = fmaf(__expf(Av[s]*sd), hin[s], hf[s]);
    }
  }

  const int gi0 = seg*LSEG;
  auto load_chunk = [&](int c, int buf){
    {
      int ls = tid >> 2, q = tid & 3;
      int gi = gi0 + c*S1CH + ls;
      int t = bwd ? (LL-1 - gi) : gi;
      cpa16(sb + oC2 + (uint32_t)(((buf*S1CH + ls)*4 + q)*16),
            &dbl[(size_t)(b*LL + t)*48 + 32 + q*4]);
    }
    #pragma unroll
    for (int it = 0; it < 8; it++){
      int idx = tid + it*128;
      int ls = idx >> 5, sg = idx & 31;
      int gi = gi0 + c*S1CH + ls;
      int t = bwd ? (LL-1 - gi) : gi;
      cpa16(sb + oDG2 + (uint32_t)(((buf*S1CH + ls)*128 + sg*4)*4),
            &dg[(size_t)(b*LL + t)*DIF + d0 + sg*4]);
    }
    #pragma unroll
    for (int it = 0; it < 4; it++){
      int idx = tid + it*128;
      int ls = idx >> 4, sg = idx & 15;
      int gi = gi0 + c*S1CH + ls;
      int t = bwd ? (LL-1 - gi) : gi;
      cpa16(sb + oU2 + (uint32_t)(((buf*S1CH + ls)*128 + sg*8)*2),
            &u[(size_t)(b*LL + t)*DIF + d0 + sg*8]);
    }
    asm volatile("cp.async.commit_group;" ::: "memory");
  };

  float cacc = 0.f;
  const int nc = LSEG / S1CH;
  load_chunk(0, 0);
  for (int c = 0; c < nc; c++){
    const int buf = c & 1;
    if (c + 1 < nc){
      load_chunk(c + 1, buf ^ 1);
      asm volatile("cp.async.wait_group 1;" ::: "memory");
    } else {
      asm volatile("cp.async.wait_group 0;" ::: "memory");
    }
    __syncthreads();
    const float4*  sC = reinterpret_cast<const float4*>(ssm + oC2) + (size_t)buf*S1CH*4;
    const __half2* sG = reinterpret_cast<const __half2*>(ssm + oDG2) + (size_t)buf*S1CH*128;
    const __half*  sU = reinterpret_cast<const __half*>(ssm + oU2) + (size_t)buf*S1CH*128;

    for (int ls = 0; ls < S1CH; ls++){
      int gi = gi0 + c*S1CH + ls;
      int t  = bwd ? (LL-1 - gi) : gi;
      float2 dgv = __half22float2(sG[ls*128 + tid]);
      cacc += dgv.x;                       // cumulative sum(dv), inclusive
      float4 C0 = sC[ls*4+0], C1 = sC[ls*4+1], C2 = sC[ls*4+2], C3 = sC[ls*4+3];
      float corr;
      if (pc){
        float e1 = __expf(Av[0]*cacc);
        float e2 = e1*e1, e3 = e2*e1, e4 = e2*e2;
        float e5 = e4*e1, e6 = e4*e2, e7 = e4*e3, e8 = e4*e4;
        float e9 = e8*e1, e10 = e8*e2, e11 = e8*e3, e12 = e8*e4;
        float e13 = e8*e5, e14 = e8*e6, e15 = e8*e7, e16 = e8*e8;
        float c0 = fmaf(e1*hin[0],  C0.x, 0.f);
        c0 = fmaf(e5*hin[4],  C1.x, c0);
        c0 = fmaf(e9*hin[8],  C2.x, c0);
        c0 = fmaf(e13*hin[12], C3.x, c0);
        float c1 = fmaf(e2*hin[1],  C0.y, 0.f);
        c1 = fmaf(e6*hin[5],  C1.y, c1);
        c1 = fmaf(e10*hin[9], C2.y, c1);
        c1 = fmaf(e14*hin[13], C3.y, c1);
        float c2 = fmaf(e3*hin[2],  C0.z, 0.f);
        c2 = fmaf(e7*hin[6],  C1.z, c2);
        c2 = fmaf(e11*hin[10], C2.z, c2);
        c2 = fmaf(e15*hin[14], C3.z, c2);
        float c3 = fmaf(e4*hin[3],  C0.w, 0.f);
        c3 = fmaf(e8*hin[7],  C1.w, c3);
        c3 = fmaf(e12*hin[11], C2.w, c3);
        c3 = fmaf(e16*hin[15], C3.w, c3);
        corr = (c0 + c1) + (c2 + c3);
      } else {
        float Cw[16] = {C0.x,C0.y,C0.z,C0.w, C1.x,C1.y,C1.z,C1.w,
                        C2.x,C2.y,C2.z,C2.w, C3.x,C3.y,C3.z,C3.w};
        corr = 0.f;
        #pragma unroll
        for (int s = 0; s < 16; s++)
          corr = fmaf(__expf(Av[s]*cacc)*hin[s], Cw[s], corr);
      }
      float up = __half2float(sU[ls*128 + tid]);
      u[(size_t)(b*LL + t)*DIF + d] = __float2half(fmaf(corr, dgv.y, up));
    }
    __syncthreads();
  }
}

// ---------------- combine: LN(o0+o1), LN(o2+o3), residual add --------------
__global__ void combine_ker(const float* __restrict__ lnw, const float* __restrict__ lnb){
  int i = blockIdx.x, c = threadIdx.x;
  float a  = g_o[0][(size_t)i*DMF + c] + g_o[1][(size_t)i*DMF + c];
  float bv = g_o[2][(size_t)i*DMF + c] + g_o[3][(size_t)i*DMF + c];
  __shared__ float r1[256], r2[256];
  r1[c] = a; r2[c] = bv; __syncthreads();
  for (int s = 128; s > 0; s >>= 1){
    if (c < s){ r1[c] += r1[c+s]; r2[c] += r2[c+s]; }
    __syncthreads();
  }
  float ma = r1[0] * (1.f/DMF), mb = r2[0] * (1.f/DMF);
  __syncthreads();
  float da = a - ma, db = bv - mb;
  r1[c] = da*da; r2[c] = db*db; __syncthreads();
  for (int s = 128; s > 0; s >>= 1){
    if (c < s){ r1[c] += r1[c+s]; r2[c] += r2[c+s]; }
    __syncthreads();
  }
  float va = r1[0] * (1.f/DMF), vb = r2[0] * (1.f/DMF);
  float s1 = da * rsqrtf(va + 1e-5f) * lnw[c] + lnb[c];
  float s2 = db * rsqrtf(vb + 1e-5f) * lnw[c] + lnb[c];
  float nv = g_x[(size_t)i*DMF + c] + 0.5f * (s1 + s2);
  g_x [(size_t)i*DMF + c] = nv;
  g_xh[(size_t)i*DMF + c] = __float2half(nv);
}

// ---------------- host orchestration ---------------------------------------
#define SMEM_H128 ((2*ABUF + 2*128*STRH)*2)   // 40960 B
#define SMEM_H64  ((2*ABUF + 2*64*STRH)*2)    // 30720 B

extern "C" void kernel_launch(void* const* d_in, const int* in_sizes, int n_in,
                              void* d_out, int out_size){
  const float* x       = (const float*)d_in[0];
  const float* pe      = (const float*)d_in[1];
  const float* ln_w    = (const float*)d_in[2];
  const float* ln_b    = (const float*)d_in[3];
  const float* in_proj = (const float*)d_in[4];
  const float* conv_w  = (const float*)d_in[5];
  const float* conv_b  = (const float*)d_in[6];
  const float* x_proj  = (const float*)d_in[7];
  const float* dt_w    = (const float*)d_in[8];
  const float* dt_b    = (const float*)d_in[9];
  const float* A_log   = (const float*)d_in[10];
  const float* Dp      = (const float*)d_in[11];
  const float* out_prj = (const float*)d_in[12];

  void *pxh, *pxz, *pxch, *pdbl, *puh, *po, *pw1, *pw2, *pw4;
  cudaGetSymbolAddress(&pxh,  g_xh);
  cudaGetSymbolAddress(&pxz,  g_xz);
  cudaGetSymbolAddress(&pxch, g_xch);
  cudaGetSymbolAddress(&pdbl, g_dbl);
  cudaGetSymbolAddress(&puh,  g_uh);
  cudaGetSymbolAddress(&po,   g_o);
  cudaGetSymbolAddress(&pw1,  g_wt1);
  cudaGetSymbolAddress(&pw2,  g_wt2);
  cudaGetSymbolAddress(&pw4,  g_wt4);

  cudaFuncSetAttribute(scan1_ker, cudaFuncAttributeMaxDynamicSharedMemorySize, S1_SMEM);
  cudaFuncSetAttribute(scan2_ker, cudaFuncAttributeMaxDynamicSharedMemorySize, S2_SMEM);

  wtrans_ker<<<dim3(16, 32, 24), dim3(32, 8)>>>(in_proj, x_proj, out_prj);
  add_pe_ker<<<MM, 256>>>(x, pe);

  for (int l = 0; l < NLAY; l++){
    // GEMM1: xz[z] = seq(z) @ in_proj[l,z]  (N=1024, K=256); perm folds blk-1 transpose
    hgemm_ker<128><<<dim3(MM/128, 8, 4), 256, SMEM_H128>>>(
        (const __half*)pxh, (size_t)0,
        (const __half*)pw1, (float*)pxz, 256, 1024, l, 1);
    conv_ker<<<dim3((MM*(DIF/4))/256, 4), 256>>>(conv_w, conv_b, l);
    // GEMM2: dbl[z] = xc[z] @ x_proj (N=48 pad 64, K=512)
    hgemm_ker<64><<<dim3(MM/128, 1, 4), 256, SMEM_H64>>>(
        (const __half*)pxch, (size_t)MM*DIF,
        (const __half*)pw2, (float*)pdbl, 512, 48, l, 0);
    // selective scan: segmented phase 1 + cross-segment fixup
    scan1_ker<<<dim3(4, Bb, 16), 128, S1_SMEM>>>(A_log, Dp, dt_w, dt_b, l);
    scan2_ker<<<dim3(4, Bb, 12), 128, S2_SMEM>>>(A_log, l);
    // GEMM4: o[z] = u[z] @ out_proj (N=256, K=512)
    hgemm_ker<128><<<dim3(MM/128, 2, 4), 256, SMEM_H128>>>(
        (const __half*)puh, (size_t)MM*DIF,
        (const __half*)pw4, (float*)po, 512, 256, l, 0);
    combine_ker<<<MM, 256>>>(ln_w, ln_b);
  }

  copy_out_ker<<<MM, 256>>>((float*)d_out);
}

// round 10
// speedup vs baseline: 5.3372x; 1.1496x over previous
#include <cuda_runtime.h>
#include <cuda_fp16.h>
#include <math.h>
#include <stdint.h>

// Problem dims
#define Bb   8
#define Oo   12
#define Tt   64
#define DMF  256
#define DIF  512
#define DSF  16
#define LL   768          // Oo*Tt
#define MM   6144         // Bb*LL
#define NLAY 2
#define NSEG 4
#define LSEG 192          // LL/NSEG

// ---------------- scratch (static device globals; no runtime allocs) -------
__device__ float  g_x   [MM*DMF];                     // fp32 residual stream
__device__ __align__(16) __half g_xh  [MM*DMF];       // half residual copy
__device__ __align__(16) __half g_xzh [4][(size_t)MM*2*DIF]; // GEMM1 out (half)
__device__ __align__(16) __half g_xch [4][(size_t)MM*DIF];   // conv out (half)
__device__ float  g_dbl [4][(size_t)MM*48];           // GEMM2 out
__device__ __align__(16) __half g_uh  [4][(size_t)MM*DIF];   // scan out (half)
__device__ __align__(8)  __half2 g_dg [4][(size_t)MM*DIF];   // (dv, gate) per step
__device__ float  g_hf  [4*8*NSEG*DIF*16];            // per-segment final h
__device__ float  g_sdv [4*8*NSEG*DIF];               // per-segment sum(dv)
__device__ float  g_o   [4][(size_t)MM*DMF];          // GEMM4 out
// transposed + half weights: [w][n][k]
__device__ __align__(16) __half g_wt1[8*1024*256];
__device__ __align__(16) __half g_wt2[8*64*512];
__device__ __align__(16) __half g_wt4[8*256*512];

__device__ __forceinline__ float siluf(float x){ return x / (1.f + __expf(-x)); }

// ---------------- PTX helpers ----------------------------------------------
__device__ __forceinline__ void mma_f16(float* c, const uint32_t* a, const uint32_t* b){
  asm volatile(
    "mma.sync.aligned.m16n8k16.row.col.f32.f16.f16.f32 "
    "{%0,%1,%2,%3}, {%4,%5,%6,%7}, {%8,%9}, {%0,%1,%2,%3};\n"
    : "+f"(c[0]), "+f"(c[1]), "+f"(c[2]), "+f"(c[3])
    : "r"(a[0]), "r"(a[1]), "r"(a[2]), "r"(a[3]), "r"(b[0]), "r"(b[1]));
}
__device__ __forceinline__ void ldsm4(uint32_t* r, uint32_t addr){
  asm volatile("ldmatrix.sync.aligned.m8n8.x4.shared.b16 {%0,%1,%2,%3}, [%4];"
    : "=r"(r[0]), "=r"(r[1]), "=r"(r[2]), "=r"(r[3]) : "r"(addr));
}
__device__ __forceinline__ void cpa16(uint32_t dst, const void* src){
  asm volatile("cp.async.cg.shared.global [%0], [%1], 16;" :: "r"(dst), "l"(src));
}

// ---------------- weight transpose + fp16 convert ---------------------------
__global__ void wtrans_ker(const float* __restrict__ ip, const float* __restrict__ xp,
                           const float* __restrict__ op){
  int s = blockIdx.z >> 3;
  int w = blockIdx.z & 7;
  int K = (s==0)?256:512;
  int N = (s==0)?1024:((s==1)?48:256);
  int Nout = (s==1)?64:N;
  const float* src = (s==0)?ip:((s==1)?xp:op);
  __half* dst = (s==0)?g_wt1:((s==1)?g_wt2:g_wt4);
  src += (size_t)w*K*N; dst += (size_t)w*(size_t)Nout*K;
  int k0 = blockIdx.x*32, n0 = blockIdx.y*32;
  if (k0 >= K || n0 >= Nout) return;
  __shared__ float tile[32][33];
  int tx = threadIdx.x, ty = threadIdx.y;
  for (int i = ty; i < 32; i += 8){
    int k = k0+i, n = n0+tx;
    tile[i][tx] = (k < K && n < N) ? src[(size_t)k*N + n] : 0.f;
  }
  __syncthreads();
  for (int i = ty; i < 32; i += 8){
    int n = n0+i, k = k0+tx;
    if (n < Nout && k < K) dst[(size_t)n*K + k] = __float2half(tile[tx][i]);
  }
}

// ---------------- elementwise kernels --------------------------------------
__global__ void add_pe_ker(const float* __restrict__ x, const float* __restrict__ pe){
  int i = blockIdx.x, c = threadIdx.x;
  int t = i % Tt;
  float v = x[(size_t)i*DMF + c] + pe[t*DMF + c];
  g_x [(size_t)i*DMF + c] = v;
  g_xh[(size_t)i*DMF + c] = __float2half(v);
}
__global__ void copy_out_ker(float* __restrict__ out){
  int i = blockIdx.x, c = threadIdx.x;
  out[(size_t)i*DMF + c] = g_x[(size_t)i*DMF + c];
}

// ---------------- fp16 tensor-core GEMM (ldmatrix + cp.async) --------------
// perm!=0: for z>=2, A rows are the (o,t)->(t,o) permutation of A0 rows.
// hout!=0: store __half output, else fp32.
#define STRH 40
#define ABUF (128*STRH)
template<int NT>
__global__ void __launch_bounds__(256) hgemm_ker(
    const __half* __restrict__ A0, size_t zstr,
    const __half* __restrict__ WtB, void* __restrict__ Cb,
    int K, int Ntot, int l, int perm, int hout)
{
  constexpr int BBUF = NT*STRH;
  extern __shared__ __half smh[];
  const uint32_t sb = (uint32_t)__cvta_generic_to_shared(smh);
  const uint32_t aOff[2] = {0u, (uint32_t)ABUF*2u};
  const uint32_t bOff[2] = {(uint32_t)(2*ABUF)*2u, (uint32_t)(2*ABUF + BBUF)*2u};

  const int z = blockIdx.z;
  const __half* A = A0 + (size_t)z*zstr;
  const int n0 = blockIdx.y * NT;
  const int Nrows = (Ntot==48) ? 64 : Ntot;
  const __half* Wt = WtB + ((size_t)(l*4 + z)*Nrows + n0) * K;

  const int tid  = threadIdx.x;
  const int lane = tid & 31;
  const int w    = tid >> 5;
  constexpr int WN = NT/4;
  constexpr int NATOMS = WN/8;
  constexpr int NPAIRS = WN/16;
  const int wm = (w & 1) * 64;
  const int wn = (w >> 1) * WN;
  const int row0 = blockIdx.x * 128;

  float acc[4][NATOMS][4];
  #pragma unroll
  for (int ma = 0; ma < 4; ma++)
    #pragma unroll
    for (int na = 0; na < NATOMS; na++)
      #pragma unroll
      for (int q = 0; q < 4; q++) acc[ma][na][q] = 0.f;

  const int a_r = tid >> 1;
  const int a_u = (tid & 1) * 2;
  int grow = row0 + a_r;
  if (perm && z >= 2){
    int b2 = grow / LL;
    int p  = grow - b2*LL;
    int tq = p / Oo;
    int o  = p - tq*Oo;
    grow = b2*LL + o*Tt + tq;
  }
  const __half* Arow = A + (size_t)grow*K;

  const uint32_t aLd = (uint32_t)((wm + (lane & 15))*STRH + (lane >> 4)*8) * 2u;
  const int nloc = ((lane & 16) >> 1) | (lane & 7);
  const uint32_t bLd = (uint32_t)((wn + nloc)*STRH + ((lane >> 3) & 1)*8) * 2u;

  auto load_chunk = [&](int buf, int c){
    const int kb = c*32;
    const uint32_t ab = sb + aOff[buf];
    const uint32_t bb = sb + bOff[buf];
    #pragma unroll
    for (int u = 0; u < 2; u++)
      cpa16(ab + (uint32_t)(a_r*STRH + (a_u+u)*8)*2u, Arow + kb + (a_u+u)*8);
    #pragma unroll
    for (int it = 0; it < NT/64; it++){
      int idx = tid + it*256;
      int r = idx >> 2, u = idx & 3;
      cpa16(bb + (uint32_t)(r*STRH + u*8)*2u, &Wt[(size_t)r*K + kb + u*8]);
    }
    asm volatile("cp.async.commit_group;" ::: "memory");
  };

  auto compute = [&](int buf){
    const uint32_t ab = sb + aOff[buf];
    const uint32_t bb = sb + bOff[buf];
    #pragma unroll
    for (int ks = 0; ks < 2; ks++){
      uint32_t af[4][4];
      #pragma unroll
      for (int ma = 0; ma < 4; ma++)
        ldsm4(af[ma], ab + aLd + (uint32_t)(ma*16*STRH + ks*16)*2u);
      uint32_t bf[2*NPAIRS][2];
      #pragma unroll
      for (int np = 0; np < NPAIRS; np++){
        uint32_t r4[4];
        ldsm4(r4, bb + bLd + (uint32_t)(np*16*STRH + ks*16)*2u);
        bf[np*2+0][0] = r4[0]; bf[np*2+0][1] = r4[1];
        bf[np*2+1][0] = r4[2]; bf[np*2+1][1] = r4[3];
      }
      #pragma unroll
      for (int ma = 0; ma < 4; ma++)
        #pragma unroll
        for (int na = 0; na < NATOMS; na++)
          mma_f16(acc[ma][na], af[ma], bf[na]);
    }
  };

  const int nc = K / 32;
  load_chunk(0, 0);
  for (int c = 0; c < nc; c++){
    const int buf = c & 1;
    if (c + 1 < nc){
      load_chunk(buf ^ 1, c + 1);
      asm volatile("cp.async.wait_group 1;" ::: "memory");
    } else {
      asm volatile("cp.async.wait_group 0;" ::: "memory");
    }
    __syncthreads();
    compute(buf);
    __syncthreads();
  }

  if (hout){
    __half* Ch = (__half*)Cb + (size_t)z * (size_t)MM * Ntot;
    #pragma unroll
    for (int ma = 0; ma < 4; ma++){
      const int r = row0 + wm + ma*16 + (lane >> 2);
      #pragma unroll
      for (int na = 0; na < NATOMS; na++){
        const int cc = n0 + wn + na*8 + (lane & 3)*2;
        if (cc < Ntot){
          *reinterpret_cast<__half2*>(&Ch[(size_t)r*Ntot + cc])     = __floats2half2_rn(acc[ma][na][0], acc[ma][na][1]);
          *reinterpret_cast<__half2*>(&Ch[(size_t)(r+8)*Ntot + cc]) = __floats2half2_rn(acc[ma][na][2], acc[ma][na][3]);
        }
      }
    }
  } else {
    float* C = (float*)Cb + (size_t)z * (size_t)MM * Ntot;
    #pragma unroll
    for (int ma = 0; ma < 4; ma++){
      const int r = row0 + wm + ma*16 + (lane >> 2);
      #pragma unroll
      for (int na = 0; na < NATOMS; na++){
        const int cc = n0 + wn + na*8 + (lane & 3)*2;
        if (cc < Ntot){
          *reinterpret_cast<float2*>(&C[(size_t)r*Ntot + cc])     = make_float2(acc[ma][na][0], acc[ma][na][1]);
          *reinterpret_cast<float2*>(&C[(size_t)(r+8)*Ntot + cc]) = make_float2(acc[ma][na][2], acc[ma][na][3]);
        }
      }
    }
  }
}

// ---------------- depthwise causal conv + SiLU (half in/out) ---------------
__global__ void conv_ker(const float* __restrict__ conv_w, const float* __restrict__ conv_b, int l){
  int z   = blockIdx.y;
  int gid = blockIdx.x*256 + threadIdx.x;
  int i  = gid / (DIF/4);
  int dq = gid % (DIF/4);
  int d  = dq * 4;
  int b = i / LL, t = i % LL;
  int widx = l*4 + z;
  const __half* xz = g_xzh[z];
  const float4 wA = *reinterpret_cast<const float4*>(&conv_w[(size_t)(widx*DIF + d+0)*4]);
  const float4 wB = *reinterpret_cast<const float4*>(&conv_w[(size_t)(widx*DIF + d+1)*4]);
  const float4 wC = *reinterpret_cast<const float4*>(&conv_w[(size_t)(widx*DIF + d+2)*4]);
  const float4 wD = *reinterpret_cast<const float4*>(&conv_w[(size_t)(widx*DIF + d+3)*4]);
  float wt[4][4] = {{wA.x,wA.y,wA.z,wA.w},{wB.x,wB.y,wB.z,wB.w},
                    {wC.x,wC.y,wC.z,wC.w},{wD.x,wD.y,wD.z,wD.w}};
  float4 s = *reinterpret_cast<const float4*>(&conv_b[(size_t)widx*DIF + d]);
  size_t base = (size_t)b*LL;
  if ((z & 1) == 0){
    #pragma unroll
    for (int k = 0; k < 4; k++){
      int tt = t + k - 3;
      if (tt >= 0){
        const __half2* v2 = reinterpret_cast<const __half2*>(&xz[(base + tt)*1024 + d]);
        float2 va = __half22float2(v2[0]), vb = __half22float2(v2[1]);
        s.x = fmaf(wt[0][k], va.x, s.x);
        s.y = fmaf(wt[1][k], va.y, s.y);
        s.z = fmaf(wt[2][k], vb.x, s.z);
        s.w = fmaf(wt[3][k], vb.y, s.w);
      }
    }
  } else {
    #pragma unroll
    for (int j = 0; j < 4; j++){
      int tt = t + j;
      if (tt < LL){
        const __half2* v2 = reinterpret_cast<const __half2*>(&xz[(base + tt)*1024 + d]);
        float2 va = __half22float2(v2[0]), vb = __half22float2(v2[1]);
        s.x = fmaf(wt[0][3-j], va.x, s.x);
        s.y = fmaf(wt[1][3-j], va.y, s.y);
        s.z = fmaf(wt[2][3-j], vb.x, s.z);
        s.w = fmaf(wt[3][3-j], vb.y, s.w);
      }
    }
  }
  __half2* oh = reinterpret_cast<__half2*>(&g_xch[z][(size_t)i*DIF + d]);
  oh[0] = __floats2half2_rn(siluf(s.x), siluf(s.y));
  oh[1] = __floats2half2_rn(siluf(s.z), siluf(s.w));
}

// ---------------- scan phase 1: per-segment local scan (h0 = 0) ------------
#define S1CH 32
#define oDBL 0
#define oXC  12288
#define oZ   28672
#define S1_SMEM 45056
__global__ void __launch_bounds__(128) scan1_ker(const float* __restrict__ A_log,
                                                 const float* __restrict__ Dp,
                                                 const float* __restrict__ dtw,
                                                 const float* __restrict__ dtb, int l){
  extern __shared__ char ssm[];
  const uint32_t sb = (uint32_t)__cvta_generic_to_shared(ssm);
  int tid = threadIdx.x;
  int d0 = blockIdx.x*128, d = d0 + tid;
  int b = blockIdx.y;
  int z = blockIdx.z >> 2, seg = blockIdx.z & 3;
  int widx = l*4 + z;
  bool bwd = (z & 1);
  const __half* xch = g_xch[z];
  const __half* xzz = g_xzh[z];          // z-gate lives at column DIF..2*DIF
  const float*  dbl = g_dbl[z];
  __half*  u  = g_uh[z];
  __half2* dg = g_dg[z];

  float W[16];
  #pragma unroll
  for (int k = 0; k < 16; k++) W[k] = dtw[((size_t)widx*16 + k)*DIF + d];
  float bia = dtb[(size_t)widx*DIF + d];
  float Av[16];
  #pragma unroll
  for (int s = 0; s < 16; s++)
    Av[s] = -expf(A_log[((size_t)widx*DIF + d)*DSF + s]);
  bool pc = true;
  #pragma unroll
  for (int s = 1; s < 16; s++)
    pc = pc && (fabsf(Av[s] - (float)(s+1)*Av[0]) <= 1e-4f * fabsf(Av[s]));
  float Dpar = Dp[(size_t)widx*DIF + d];

  float h[16];
  #pragma unroll
  for (int s = 0; s < 16; s++) h[s] = 0.f;
  float sumdv = 0.f;
  const int gi0 = seg*LSEG;

  auto load_chunk = [&](int c, int buf){
    #pragma unroll
    for (int it = 0; it < 3; it++){
      int idx = tid + it*128;
      int ls = idx / 12, q = idx - ls*12;
      int gi = gi0 + c*S1CH + ls;
      int t = bwd ? (LL-1 - gi) : gi;
      cpa16(sb + oDBL + (uint32_t)(((buf*S1CH + ls)*12 + q)*16),
            &dbl[(size_t)(b*LL + t)*48 + q*4]);
    }
    #pragma unroll
    for (int it = 0; it < 4; it++){
      int idx = tid + it*128;
      int ls = idx >> 4, sg = idx & 15;
      int gi = gi0 + c*S1CH + ls;
      int t = bwd ? (LL-1 - gi) : gi;
      cpa16(sb + oXC + (uint32_t)(((buf*S1CH + ls)*128 + sg*8)*2),
            &xch[(size_t)(b*LL + t)*DIF + d0 + sg*8]);
      cpa16(sb + oZ + (uint32_t)(((buf*S1CH + ls)*128 + sg*8)*2),
            &xzz[(size_t)(b*LL + t)*1024 + DIF + d0 + sg*8]);
    }
    asm volatile("cp.async.commit_group;" ::: "memory");
  };

  const int nc = LSEG / S1CH;   // 6
  load_chunk(0, 0);
  for (int c = 0; c < nc; c++){
    const int buf = c & 1;
    if (c + 1 < nc){
      load_chunk(c + 1, buf ^ 1);
      asm volatile("cp.async.wait_group 1;" ::: "memory");
    } else {
      asm volatile("cp.async.wait_group 0;" ::: "memory");
    }
    __syncthreads();
    const float4* sD = reinterpret_cast<const float4*>(ssm + oDBL) + (size_t)buf*S1CH*12;
    const __half* sX = reinterpret_cast<const __half*>(ssm + oXC) + (size_t)buf*S1CH*128;
    const __half* sZ = reinterpret_cast<const __half*>(ssm + oZ)  + (size_t)buf*S1CH*128;

    for (int ls = 0; ls < S1CH; ls++){
      int gi = gi0 + c*S1CH + ls;
      int t  = bwd ? (LL-1 - gi) : gi;
      float xcv = __half2float(sX[ls*128 + tid]);
      float zv  = __half2float(sZ[ls*128 + tid]);
      const float4* row = sD + ls*12;
      float4 q0 = row[0], q1 = row[1], q2 = row[2], q3 = row[3];
      float a0 = fmaf(q0.x, W[0],  fmaf(q0.y, W[1],  fmaf(q0.z, W[2],  q0.w*W[3])));
      float a1 = fmaf(q1.x, W[4],  fmaf(q1.y, W[5],  fmaf(q1.z, W[6],  q1.w*W[7])));
      float a2 = fmaf(q2.x, W[8],  fmaf(q2.y, W[9],  fmaf(q2.z, W[10], q2.w*W[11])));
      float a3 = fmaf(q3.x, W[12], fmaf(q3.y, W[13], fmaf(q3.z, W[14], q3.w*W[15])));
      float a = bia + ((a0 + a1) + (a2 + a3));
      float dv = fmaxf(a, 0.f) + log1pf(__expf(-fabsf(a)));
      sumdv += dv;
      float du = dv * xcv;

      float acc0 = 0.f, acc1 = 0.f, acc2 = 0.f, acc3 = 0.f;
      if (pc){
        float e1 = __expf(dv * Av[0]);
        float e2 = e1*e1, e3 = e2*e1, e4 = e2*e2;
        float e5 = e4*e1, e6 = e4*e2, e7 = e4*e3, e8 = e4*e4;
        float e9 = e8*e1, e10 = e8*e2, e11 = e8*e3, e12 = e8*e4;
        float e13 = e8*e5, e14 = e8*e6, e15 = e8*e7, e16 = e8*e8;
        float4 B0 = row[4], B1 = row[5], B2 = row[6], B3 = row[7];
        float4 C0 = row[8], C1 = row[9], C2 = row[10], C3 = row[11];
        h[0]  = fmaf(e1,  h[0],  du*B0.x); acc0 = fmaf(h[0],  C0.x, acc0);
        h[1]  = fmaf(e2,  h[1],  du*B0.y); acc1 = fmaf(h[1],  C0.y, acc1);
        h[2]  = fmaf(e3,  h[2],  du*B0.z); acc2 = fmaf(h[2],  C0.z, acc2);
        h[3]  = fmaf(e4,  h[3],  du*B0.w); acc3 = fmaf(h[3],  C0.w, acc3);
        h[4]  = fmaf(e5,  h[4],  du*B1.x); acc0 = fmaf(h[4],  C1.x, acc0);
        h[5]  = fmaf(e6,  h[5],  du*B1.y); acc1 = fmaf(h[5],  C1.y, acc1);
        h[6]  = fmaf(e7,  h[6],  du*B1.z); acc2 = fmaf(h[6],  C1.z, acc2);
        h[7]  = fmaf(e8,  h[7],  du*B1.w); acc3 = fmaf(h[7],  C1.w, acc3);
        h[8]  = fmaf(e9,  h[8],  du*B2.x); acc0 = fmaf(h[8],  C2.x, acc0);
        h[9]  = fmaf(e10, h[9],  du*B2.y); acc1 = fmaf(h[9],  C2.y, acc1);
        h[10] = fmaf(e11, h[10], du*B2.z); acc2 = fmaf(h[10], C2.z, acc2);
        h[11] = fmaf(e12, h[11], du*B2.w); acc3 = fmaf(h[11], C2.w, acc3);
        h[12] = fmaf(e13, h[12], du*B3.x); acc0 = fmaf(h[12], C3.x, acc0);
        h[13] = fmaf(e14, h[13], du*B3.y); acc1 = fmaf(h[13], C3.y, acc1);
        h[14] = fmaf(e15, h[14], du*B3.z); acc2 = fmaf(h[14], C3.z, acc2);
        h[15] = fmaf(e16, h[15], du*B3.w); acc3 = fmaf(h[15], C3.w, acc3);
      } else {
        #pragma unroll
        for (int q = 0; q < 4; q++){
          float4 B4 = row[4+q];
          float4 C4 = row[8+q];
          float b0 = __expf(dv*Av[q*4+0]); h[q*4+0] = fmaf(b0, h[q*4+0], du*B4.x); acc0 = fmaf(h[q*4+0], C4.x, acc0);
          float b1 = __expf(dv*Av[q*4+1]); h[q*4+1] = fmaf(b1, h[q*4+1], du*B4.y); acc1 = fmaf(h[q*4+1], C4.y, acc1);
          float b2 = __expf(dv*Av[q*4+2]); h[q*4+2] = fmaf(b2, h[q*4+2], du*B4.z); acc2 = fmaf(h[q*4+2], C4.z, acc2);
          float b3 = __expf(dv*Av[q*4+3]); h[q*4+3] = fmaf(b3, h[q*4+3], du*B4.w); acc3 = fmaf(h[q*4+3], C4.w, acc3);
        }
      }
      float gate = siluf(zv);
      float y = (acc0 + acc1) + (acc2 + acc3) + xcv * Dpar;
      size_t rowd = (size_t)(b*LL + t)*DIF + d;
      u[rowd]  = __float2half(y * gate);
      dg[rowd] = __floats2half2_rn(dv, gate);
    }
    __syncthreads();
  }
  int segbase = ((z*8 + b)*NSEG + seg)*DIF + d;
  float4* hf4 = reinterpret_cast<float4*>(&g_hf[(size_t)segbase*16]);
  hf4[0] = make_float4(h[0],  h[1],  h[2],  h[3]);
  hf4[1] = make_float4(h[4],  h[5],  h[6],  h[7]);
  hf4[2] = make_float4(h[8],  h[9],  h[10], h[11]);
  hf4[3] = make_float4(h[12], h[13], h[14], h[15]);
  g_sdv[segbase] = sumdv;
}

// ---------------- scan phase 2: cross-segment correction (early exit) ------
#define oC2  0
#define oDG2 4096
#define oU2  36864
#define S2_SMEM 53248
__global__ void __launch_bounds__(128) scan2_ker(const float* __restrict__ A_log, int l){
  extern __shared__ char ssm[];
  const uint32_t sb = (uint32_t)__cvta_generic_to_shared(ssm);
  int tid = threadIdx.x;
  int d0 = blockIdx.x*128, d = d0 + tid;
  int b = blockIdx.y;
  int z = blockIdx.z / 3, seg = blockIdx.z - z*3 + 1;
  int widx = l*4 + z;
  bool bwd = (z & 1);
  const float*  dbl = g_dbl[z];
  const __half2* dg = g_dg[z];
  __half* u = g_uh[z];

  float Av[16];
  #pragma unroll
  for (int s = 0; s < 16; s++)
    Av[s] = -expf(A_log[((size_t)widx*DIF + d)*DSF + s]);
  bool pc = true;
  #pragma unroll
  for (int s = 1; s < 16; s++)
    pc = pc && (fabsf(Av[s] - (float)(s+1)*Av[0]) <= 1e-4f * fabsf(Av[s]));
  float amax = Av[0];
  #pragma unroll
  for (int s = 1; s < 16; s++) amax = fmaxf(amax, Av[s]);   // slowest decay

  float hin[16];
  #pragma unroll
  for (int s = 0; s < 16; s++) hin[s] = 0.f;
  for (int k = 0; k < seg; k++){
    int kb = ((z*8 + b)*NSEG + k)*DIF + d;
    float sd = g_sdv[kb];
    const float4* hf4 = reinterpret_cast<const float4*>(&g_hf[(size_t)kb*16]);
    float4 f0 = hf4[0], f1 = hf4[1], f2 = hf4[2], f3 = hf4[3];
    float hf[16] = {f0.x,f0.y,f0.z,f0.w, f1.x,f1.y,f1.z,f1.w,
                    f2.x,f2.y,f2.z,f2.w, f3.x,f3.y,f3.z,f3.w};
    if (pc){
      float E = __expf(Av[0]*sd);
      float p = 1.f;
      #pragma unroll
      for (int s = 0; s < 16; s++){ p *= E; hin[s] = fmaf(p, hin[s], hf[s]); }
    } else {
      #pragma unroll
      for (int s = 0; s < 16; s++) hin[s] = fmaf(__expf(Av[s]*sd), hin[s], hf[s]);
    }
  }

  const int gi0 = seg*LSEG;
  auto load_chunk = [&](int c, int buf){
    {
      int ls = tid >> 2, q = tid & 3;
      int gi = gi0 + c*S1CH + ls;
      int t = bwd ? (LL-1 - gi) : gi;
      cpa16(sb + oC2 + (uint32_t)(((buf*S1CH + ls)*4 + q)*16),
            &dbl[(size_t)(b*LL + t)*48 + 32 + q*4]);
    }
    #pragma unroll
    for (int it = 0; it < 8; it++){
      int idx = tid + it*128;
      int ls = idx >> 5, sg = idx & 31;
      int gi = gi0 + c*S1CH + ls;
      int t = bwd ? (LL-1 - gi) : gi;
      cpa16(sb + oDG2 + (uint32_t)(((buf*S1CH + ls)*128 + sg*4)*4),
            &dg[(size_t)(b*LL + t)*DIF + d0 + sg*4]);
    }
    #pragma unroll
    for (int it = 0; it < 4; it++){
      int idx = tid + it*128;
      int ls = idx >> 4, sg = idx & 15;
      int gi = gi0 + c*S1CH + ls;
      int t = bwd ? (LL-1 - gi) : gi;
      cpa16(sb + oU2 + (uint32_t)(((buf*S1CH + ls)*128 + sg*8)*2),
            &u[(size_t)(b*LL + t)*DIF + d0 + sg*8]);
    }
    asm volatile("cp.async.commit_group;" ::: "memory");
  };

  float cacc = 0.f;
  const int nc = LSEG / S1CH;
  load_chunk(0, 0);
  for (int c = 0; c < nc; c++){
    const int buf = c & 1;
    if (c + 1 < nc){
      load_chunk(c + 1, buf ^ 1);
      asm volatile("cp.async.wait_group 1;" ::: "memory");
    } else {
      asm volatile("cp.async.wait_group 0;" ::: "memory");
    }
    __syncthreads();
    const float4*  sC = reinterpret_cast<const float4*>(ssm + oC2) + (size_t)buf*S1CH*4;
    const __half2* sG = reinterpret_cast<const __half2*>(ssm + oDG2) + (size_t)buf*S1CH*128;
    const __half*  sU = reinterpret_cast<const __half*>(ssm + oU2) + (size_t)buf*S1CH*128;

    for (int ls = 0; ls < S1CH; ls++){
      int gi = gi0 + c*S1CH + ls;
      int t  = bwd ? (LL-1 - gi) : gi;
      float2 dgv = __half22float2(sG[ls*128 + tid]);
      cacc += dgv.x;
      float4 C0 = sC[ls*4+0], C1 = sC[ls*4+1], C2 = sC[ls*4+2], C3 = sC[ls*4+3];
      float corr;
      if (pc){
        float e1 = __expf(Av[0]*cacc);
        float e2 = e1*e1, e3 = e2*e1, e4 = e2*e2;
        float e5 = e4*e1, e6 = e4*e2, e7 = e4*e3, e8 = e4*e4;
        float e9 = e8*e1, e10 = e8*e2, e11 = e8*e3, e12 = e8*e4;
        float e13 = e8*e5, e14 = e8*e6, e15 = e8*e7, e16 = e8*e8;
        float c0 = fmaf(e1*hin[0],  C0.x, 0.f);
        c0 = fmaf(e5*hin[4],  C1.x, c0);
        c0 = fmaf(e9*hin[8],  C2.x, c0);
        c0 = fmaf(e13*hin[12], C3.x, c0);
        float c1 = fmaf(e2*hin[1],  C0.y, 0.f);
        c1 = fmaf(e6*hin[5],  C1.y, c1);
        c1 = fmaf(e10*hin[9], C2.y, c1);
        c1 = fmaf(e14*hin[13], C3.y, c1);
        float c2 = fmaf(e3*hin[2],  C0.z, 0.f);
        c2 = fmaf(e7*hin[6],  C1.z, c2);
        c2 = fmaf(e11*hin[10], C2.z, c2);
        c2 = fmaf(e15*hin[14], C3.z, c2);
        float c3 = fmaf(e4*hin[3],  C0.w, 0.f);
        c3 = fmaf(e8*hin[7],  C1.w, c3);
        c3 = fmaf(e12*hin[11], C2.w, c3);
        c3 = fmaf(e16*hin[15], C3.w, c3);
        corr = (c0 + c1) + (c2 + c3);
      } else {
        float Cw[16] = {C0.x,C0.y,C0.z,C0.w, C1.x,C1.y,C1.z,C1.w,
                        C2.x,C2.y,C2.z,C2.w, C3.x,C3.y,C3.z,C3.w};
        corr = 0.f;
        #pragma unroll
        for (int s = 0; s < 16; s++)
          corr = fmaf(__expf(Av[s]*cacc)*hin[s], Cw[s], corr);
      }
      float up = __half2float(sU[ls*128 + tid]);
      u[(size_t)(b*LL + t)*DIF + d] = __float2half(fmaf(corr, dgv.y, up));
    }
    // early exit: correction factor exp(amax*cacc) < e^-25 for all lanes
    int done = (cacc * (-amax) > 25.f) ? 1 : 0;
    if (__syncthreads_and(done)){
      asm volatile("cp.async.wait_group 0;" ::: "memory");
      break;
    }
  }
}

// ---------------- combine: LN(o0+o1), LN(o2+o3), residual add --------------
__global__ void combine_ker(const float* __restrict__ lnw, const float* __restrict__ lnb){
  int i = blockIdx.x, c = threadIdx.x;
  float a  = g_o[0][(size_t)i*DMF + c] + g_o[1][(size_t)i*DMF + c];
  float bv = g_o[2][(size_t)i*DMF + c] + g_o[3][(size_t)i*DMF + c];
  __shared__ float r1[256], r2[256];
  r1[c] = a; r2[c] = bv; __syncthreads();
  for (int s = 128; s > 0; s >>= 1){
    if (c < s){ r1[c] += r1[c+s]; r2[c] += r2[c+s]; }
    __syncthreads();
  }
  float ma = r1[0] * (1.f/DMF), mb = r2[0] * (1.f/DMF);
  __syncthreads();
  float da = a - ma, db = bv - mb;
  r1[c] = da*da; r2[c] = db*db; __syncthreads();
  for (int s = 128; s > 0; s >>= 1){
    if (c < s){ r1[c] += r1[c+s]; r2[c] += r2[c+s]; }
    __syncthreads();
  }
  float va = r1[0] * (1.f/DMF), vb = r2[0] * (1.f/DMF);
  float s1 = da * rsqrtf(va + 1e-5f) * lnw[c] + lnb[c];
  float s2 = db * rsqrtf(vb + 1e-5f) * lnw[c] + lnb[c];
  float nv = g_x[(size_t)i*DMF + c] + 0.5f * (s1 + s2);
  g_x [(size_t)i*DMF + c] = nv;
  g_xh[(size_t)i*DMF + c] = __float2half(nv);
}

// ---------------- host orchestration ---------------------------------------
#define SMEM_H128 ((2*ABUF + 2*128*STRH)*2)   // 40960 B
#define SMEM_H64  ((2*ABUF + 2*64*STRH)*2)    // 30720 B

extern "C" void kernel_launch(void* const* d_in, const int* in_sizes, int n_in,
                              void* d_out, int out_size){
  const float* x       = (const float*)d_in[0];
  const float* pe      = (const float*)d_in[1];
  const float* ln_w    = (const float*)d_in[2];
  const float* ln_b    = (const float*)d_in[3];
  const float* in_proj = (const float*)d_in[4];
  const float* conv_w  = (const float*)d_in[5];
  const float* conv_b  = (const float*)d_in[6];
  const float* x_proj  = (const float*)d_in[7];
  const float* dt_w    = (const float*)d_in[8];
  const float* dt_b    = (const float*)d_in[9];
  const float* A_log   = (const float*)d_in[10];
  const float* Dp      = (const float*)d_in[11];
  const float* out_prj = (const float*)d_in[12];

  void *pxh, *pxzh, *pxch, *pdbl, *puh, *po, *pw1, *pw2, *pw4;
  cudaGetSymbolAddress(&pxh,  g_xh);
  cudaGetSymbolAddress(&pxzh, g_xzh);
  cudaGetSymbolAddress(&pxch, g_xch);
  cudaGetSymbolAddress(&pdbl, g_dbl);
  cudaGetSymbolAddress(&puh,  g_uh);
  cudaGetSymbolAddress(&po,   g_o);
  cudaGetSymbolAddress(&pw1,  g_wt1);
  cudaGetSymbolAddress(&pw2,  g_wt2);
  cudaGetSymbolAddress(&pw4,  g_wt4);

  cudaFuncSetAttribute(scan1_ker, cudaFuncAttributeMaxDynamicSharedMemorySize, S1_SMEM);
  cudaFuncSetAttribute(scan2_ker, cudaFuncAttributeMaxDynamicSharedMemorySize, S2_SMEM);

  wtrans_ker<<<dim3(16, 32, 24), dim3(32, 8)>>>(in_proj, x_proj, out_prj);
  add_pe_ker<<<MM, 256>>>(x, pe);

  for (int l = 0; l < NLAY; l++){
    // GEMM1: xz[z] = seq(z) @ in_proj[l,z]  (N=1024, K=256, half out)
    hgemm_ker<128><<<dim3(MM/128, 8, 4), 256, SMEM_H128>>>(
        (const __half*)pxh, (size_t)0,
        (const __half*)pw1, pxzh, 256, 1024, l, 1, 1);
    conv_ker<<<dim3((MM*(DIF/4))/256, 4), 256>>>(conv_w, conv_b, l);
    // GEMM2: dbl[z] = xc[z] @ x_proj (N=48 pad 64, K=512, fp32 out)
    hgemm_ker<64><<<dim3(MM/128, 1, 4), 256, SMEM_H64>>>(
        (const __half*)pxch, (size_t)MM*DIF,
        (const __half*)pw2, pdbl, 512, 48, l, 0, 0);
    // selective scan: segmented phase 1 + early-exit fixup
    scan1_ker<<<dim3(4, Bb, 16), 128, S1_SMEM>>>(A_log, Dp, dt_w, dt_b, l);
    scan2_ker<<<dim3(4, Bb, 12), 128, S2_SMEM>>>(A_log, l);
    // GEMM4: o[z] = u[z] @ out_proj (N=256, K=512, fp32 out)
    hgemm_ker<128><<<dim3(MM/128, 2, 4), 256, SMEM_H128>>>(
        (const __half*)puh, (size_t)MM*DIF,
        (const __half*)pw4, po, 512, 256, l, 0, 0);
    combine_ker<<<MM, 256>>>(ln_w, ln_b);
  }

  copy_out_ker<<<MM, 256>>>((float*)d_out);
}

// round 11
// speedup vs baseline: 5.6299x; 1.0548x over previous
#include <cuda_runtime.h>
#include <cuda_fp16.h>
#include <math.h>
#include <stdint.h>

// Problem dims
#define Bb   8
#define Oo   12
#define Tt   64
#define DMF  256
#define DIF  512
#define DSF  16
#define LL   768          // Oo*Tt
#define MM   6144         // Bb*LL
#define NLAY 2
#define NSEG 8
#define LSEG 96           // LL/NSEG

// ---------------- scratch (static device globals; no runtime allocs) -------
__device__ float  g_x   [MM*DMF];                     // fp32 residual stream
__device__ __align__(16) __half g_xh  [MM*DMF];       // half residual copy
__device__ __align__(16) __half g_xzh [4][(size_t)MM*2*DIF]; // GEMM1 out (half)
__device__ __align__(16) __half g_xch [4][(size_t)MM*DIF];   // conv out (half)
__device__ float  g_dbl [4][(size_t)MM*48];           // GEMM2 out
__device__ __align__(16) __half g_uh  [4][(size_t)MM*DIF];   // scan out (half)
__device__ __align__(8)  __half2 g_dg [4][(size_t)MM*DIF];   // (dv, gate) per step
__device__ float  g_hf  [4*8*NSEG*DIF*16];            // per-segment final h
__device__ float  g_sdv [4*8*NSEG*DIF];               // per-segment sum(dv)
__device__ float  g_o   [4][(size_t)MM*DMF];          // GEMM4 out
// transposed + half weights: [w][n][k]
__device__ __align__(16) __half g_wt1[8*1024*256];
__device__ __align__(16) __half g_wt2[8*64*512];
__device__ __align__(16) __half g_wt4[8*256*512];

__device__ __forceinline__ float siluf(float x){ return x / (1.f + __expf(-x)); }

// ---------------- PTX helpers ----------------------------------------------
__device__ __forceinline__ void mma_f16(float* c, const uint32_t* a, const uint32_t* b){
  asm volatile(
    "mma.sync.aligned.m16n8k16.row.col.f32.f16.f16.f32 "
    "{%0,%1,%2,%3}, {%4,%5,%6,%7}, {%8,%9}, {%0,%1,%2,%3};\n"
    : "+f"(c[0]), "+f"(c[1]), "+f"(c[2]), "+f"(c[3])
    : "r"(a[0]), "r"(a[1]), "r"(a[2]), "r"(a[3]), "r"(b[0]), "r"(b[1]));
}
__device__ __forceinline__ void ldsm4(uint32_t* r, uint32_t addr){
  asm volatile("ldmatrix.sync.aligned.m8n8.x4.shared.b16 {%0,%1,%2,%3}, [%4];"
    : "=r"(r[0]), "=r"(r[1]), "=r"(r[2]), "=r"(r[3]) : "r"(addr));
}
__device__ __forceinline__ void cpa16(uint32_t dst, const void* src){
  asm volatile("cp.async.cg.shared.global [%0], [%1], 16;" :: "r"(dst), "l"(src));
}

// ---------------- weight transpose + fp16 convert ---------------------------
__global__ void wtrans_ker(const float* __restrict__ ip, const float* __restrict__ xp,
                           const float* __restrict__ op){
  int s = blockIdx.z >> 3;
  int w = blockIdx.z & 7;
  int K = (s==0)?256:512;
  int N = (s==0)?1024:((s==1)?48:256);
  int Nout = (s==1)?64:N;
  const float* src = (s==0)?ip:((s==1)?xp:op);
  __half* dst = (s==0)?g_wt1:((s==1)?g_wt2:g_wt4);
  src += (size_t)w*K*N; dst += (size_t)w*(size_t)Nout*K;
  int k0 = blockIdx.x*32, n0 = blockIdx.y*32;
  if (k0 >= K || n0 >= Nout) return;
  __shared__ float tile[32][33];
  int tx = threadIdx.x, ty = threadIdx.y;
  for (int i = ty; i < 32; i += 8){
    int k = k0+i, n = n0+tx;
    tile[i][tx] = (k < K && n < N) ? src[(size_t)k*N + n] : 0.f;
  }
  __syncthreads();
  for (int i = ty; i < 32; i += 8){
    int n = n0+i, k = k0+tx;
    if (n < Nout && k < K) dst[(size_t)n*K + k] = __float2half(tile[tx][i]);
  }
}

// ---------------- elementwise kernels --------------------------------------
__global__ void add_pe_ker(const float* __restrict__ x, const float* __restrict__ pe){
  int i = blockIdx.x, c = threadIdx.x;
  int t = i % Tt;
  float v = x[(size_t)i*DMF + c] + pe[t*DMF + c];
  g_x [(size_t)i*DMF + c] = v;
  g_xh[(size_t)i*DMF + c] = __float2half(v);
}
__global__ void copy_out_ker(float* __restrict__ out){
  int i = blockIdx.x, c = threadIdx.x;
  out[(size_t)i*DMF + c] = g_x[(size_t)i*DMF + c];
}

// ---------------- fp16 tensor-core GEMM (ldmatrix + cp.async) --------------
#define STRH 40
#define ABUF (128*STRH)
template<int NT>
__global__ void __launch_bounds__(256) hgemm_ker(
    const __half* __restrict__ A0, size_t zstr,
    const __half* __restrict__ WtB, void* __restrict__ Cb,
    int K, int Ntot, int l, int perm, int hout)
{
  constexpr int BBUF = NT*STRH;
  extern __shared__ __half smh[];
  const uint32_t sb = (uint32_t)__cvta_generic_to_shared(smh);
  const uint32_t aOff[2] = {0u, (uint32_t)ABUF*2u};
  const uint32_t bOff[2] = {(uint32_t)(2*ABUF)*2u, (uint32_t)(2*ABUF + BBUF)*2u};

  const int z = blockIdx.z;
  const __half* A = A0 + (size_t)z*zstr;
  const int n0 = blockIdx.y * NT;
  const int Nrows = (Ntot==48) ? 64 : Ntot;
  const __half* Wt = WtB + ((size_t)(l*4 + z)*Nrows + n0) * K;

  const int tid  = threadIdx.x;
  const int lane = tid & 31;
  const int w    = tid >> 5;
  constexpr int WN = NT/4;
  constexpr int NATOMS = WN/8;
  constexpr int NPAIRS = WN/16;
  const int wm = (w & 1) * 64;
  const int wn = (w >> 1) * WN;
  const int row0 = blockIdx.x * 128;

  float acc[4][NATOMS][4];
  #pragma unroll
  for (int ma = 0; ma < 4; ma++)
    #pragma unroll
    for (int na = 0; na < NATOMS; na++)
      #pragma unroll
      for (int q = 0; q < 4; q++) acc[ma][na][q] = 0.f;

  const int a_r = tid >> 1;
  const int a_u = (tid & 1) * 2;
  int grow = row0 + a_r;
  if (perm && z >= 2){
    int b2 = grow / LL;
    int p  = grow - b2*LL;
    int tq = p / Oo;
    int o  = p - tq*Oo;
    grow = b2*LL + o*Tt + tq;
  }
  const __half* Arow = A + (size_t)grow*K;

  const uint32_t aLd = (uint32_t)((wm + (lane & 15))*STRH + (lane >> 4)*8) * 2u;
  const int nloc = ((lane & 16) >> 1) | (lane & 7);
  const uint32_t bLd = (uint32_t)((wn + nloc)*STRH + ((lane >> 3) & 1)*8) * 2u;

  auto load_chunk = [&](int buf, int c){
    const int kb = c*32;
    const uint32_t ab = sb + aOff[buf];
    const uint32_t bb = sb + bOff[buf];
    #pragma unroll
    for (int u = 0; u < 2; u++)
      cpa16(ab + (uint32_t)(a_r*STRH + (a_u+u)*8)*2u, Arow + kb + (a_u+u)*8);
    #pragma unroll
    for (int it = 0; it < NT/64; it++){
      int idx = tid + it*256;
      int r = idx >> 2, u = idx & 3;
      cpa16(bb + (uint32_t)(r*STRH + u*8)*2u, &Wt[(size_t)r*K + kb + u*8]);
    }
    asm volatile("cp.async.commit_group;" ::: "memory");
  };

  auto compute = [&](int buf){
    const uint32_t ab = sb + aOff[buf];
    const uint32_t bb = sb + bOff[buf];
    #pragma unroll
    for (int ks = 0; ks < 2; ks++){
      uint32_t af[4][4];
      #pragma unroll
      for (int ma = 0; ma < 4; ma++)
        ldsm4(af[ma], ab + aLd + (uint32_t)(ma*16*STRH + ks*16)*2u);
      uint32_t bf[2*NPAIRS][2];
      #pragma unroll
      for (int np = 0; np < NPAIRS; np++){
        uint32_t r4[4];
        ldsm4(r4, bb + bLd + (uint32_t)(np*16*STRH + ks*16)*2u);
        bf[np*2+0][0] = r4[0]; bf[np*2+0][1] = r4[1];
        bf[np*2+1][0] = r4[2]; bf[np*2+1][1] = r4[3];
      }
      #pragma unroll
      for (int ma = 0; ma < 4; ma++)
        #pragma unroll
        for (int na = 0; na < NATOMS; na++)
          mma_f16(acc[ma][na], af[ma], bf[na]);
    }
  };

  const int nc = K / 32;
  load_chunk(0, 0);
  for (int c = 0; c < nc; c++){
    const int buf = c & 1;
    if (c + 1 < nc){
      load_chunk(buf ^ 1, c + 1);
      asm volatile("cp.async.wait_group 1;" ::: "memory");
    } else {
      asm volatile("cp.async.wait_group 0;" ::: "memory");
    }
    __syncthreads();
    compute(buf);
    __syncthreads();
  }

  if (hout){
    __half* Ch = (__half*)Cb + (size_t)z * (size_t)MM * Ntot;
    #pragma unroll
    for (int ma = 0; ma < 4; ma++){
      const int r = row0 + wm + ma*16 + (lane >> 2);
      #pragma unroll
      for (int na = 0; na < NATOMS; na++){
        const int cc = n0 + wn + na*8 + (lane & 3)*2;
        if (cc < Ntot){
          *reinterpret_cast<__half2*>(&Ch[(size_t)r*Ntot + cc])     = __floats2half2_rn(acc[ma][na][0], acc[ma][na][1]);
          *reinterpret_cast<__half2*>(&Ch[(size_t)(r+8)*Ntot + cc]) = __floats2half2_rn(acc[ma][na][2], acc[ma][na][3]);
        }
      }
    }
  } else {
    float* C = (float*)Cb + (size_t)z * (size_t)MM * Ntot;
    #pragma unroll
    for (int ma = 0; ma < 4; ma++){
      const int r = row0 + wm + ma*16 + (lane >> 2);
      #pragma unroll
      for (int na = 0; na < NATOMS; na++){
        const int cc = n0 + wn + na*8 + (lane & 3)*2;
        if (cc < Ntot){
          *reinterpret_cast<float2*>(&C[(size_t)r*Ntot + cc])     = make_float2(acc[ma][na][0], acc[ma][na][1]);
          *reinterpret_cast<float2*>(&C[(size_t)(r+8)*Ntot + cc]) = make_float2(acc[ma][na][2], acc[ma][na][3]);
        }
      }
    }
  }
}

// ---------------- depthwise causal conv + SiLU (half in/out, 4 t/thread) ---
__global__ void conv_ker(const float* __restrict__ conv_w, const float* __restrict__ conv_b, int l){
  int z   = blockIdx.y;
  int gid = blockIdx.x*256 + threadIdx.x;     // over (MM/4) * (DIF/4)
  const int NT4 = LL/4;                       // 192 t-quads per batch
  int i4 = gid / (DIF/4);
  int dq = gid % (DIF/4);
  int d  = dq*4;
  int b  = i4 / NT4;
  int t0 = (i4 - b*NT4)*4;
  int widx = l*4 + z;
  const __half* xz = g_xzh[z];

  float wv[4][4], bi[4];
  #pragma unroll
  for (int di = 0; di < 4; di++){
    float4 w4 = *reinterpret_cast<const float4*>(&conv_w[(size_t)(widx*DIF + d+di)*4]);
    wv[di][0]=w4.x; wv[di][1]=w4.y; wv[di][2]=w4.z; wv[di][3]=w4.w;
  }
  {
    float4 b4 = *reinterpret_cast<const float4*>(&conv_b[(size_t)widx*DIF + d]);
    bi[0]=b4.x; bi[1]=b4.y; bi[2]=b4.z; bi[3]=b4.w;
  }
  size_t base = (size_t)b*LL;
  float v[7][4];
  bool fwd = ((z & 1) == 0);
  #pragma unroll
  for (int j = 0; j < 7; j++){
    int tt = fwd ? (t0 + j - 3) : (t0 + j);
    if (tt >= 0 && tt < LL){
      const __half2* p = reinterpret_cast<const __half2*>(&xz[(base+tt)*1024 + d]);
      float2 a = __half22float2(p[0]), c2 = __half22float2(p[1]);
      v[j][0]=a.x; v[j][1]=a.y; v[j][2]=c2.x; v[j][3]=c2.y;
    } else {
      v[j][0]=v[j][1]=v[j][2]=v[j][3]=0.f;
    }
  }
  #pragma unroll
  for (int k = 0; k < 4; k++){
    float o[4];
    #pragma unroll
    for (int di = 0; di < 4; di++){
      float s = bi[di];
      if (fwd){
        #pragma unroll
        for (int i2 = 0; i2 < 4; i2++) s = fmaf(wv[di][i2], v[k+i2][di], s);
      } else {
        #pragma unroll
        for (int j = 0; j < 4; j++)    s = fmaf(wv[di][3-j], v[k+j][di], s);
      }
      o[di] = siluf(s);
    }
    __half2* oh = reinterpret_cast<__half2*>(&g_xch[z][(base + t0 + k)*DIF + d]);
    oh[0] = __floats2half2_rn(o[0], o[1]);
    oh[1] = __floats2half2_rn(o[2], o[3]);
  }
}

// ---------------- scan phase 1: per-segment local scan (h0 = 0) ------------
#define S1CH 32
#define oDBL 0
#define oXC  12288
#define oZ   28672
#define S1_SMEM 45056
__global__ void __launch_bounds__(128) scan1_ker(const float* __restrict__ A_log,
                                                 const float* __restrict__ Dp,
                                                 const float* __restrict__ dtw,
                                                 const float* __restrict__ dtb, int l){
  extern __shared__ char ssm[];
  const uint32_t sb = (uint32_t)__cvta_generic_to_shared(ssm);
  int tid = threadIdx.x;
  int d0 = blockIdx.x*128, d = d0 + tid;
  int b = blockIdx.y;
  int z = blockIdx.z >> 3, seg = blockIdx.z & 7;
  int widx = l*4 + z;
  bool bwd = (z & 1);
  const __half* xch = g_xch[z];
  const __half* xzz = g_xzh[z];
  const float*  dbl = g_dbl[z];
  __half*  u  = g_uh[z];
  __half2* dg = g_dg[z];

  float W[16];
  #pragma unroll
  for (int k = 0; k < 16; k++) W[k] = dtw[((size_t)widx*16 + k)*DIF + d];
  float bia = dtb[(size_t)widx*DIF + d];
  float Av[16];
  #pragma unroll
  for (int s = 0; s < 16; s++)
    Av[s] = -expf(A_log[((size_t)widx*DIF + d)*DSF + s]);
  bool pc = true;
  #pragma unroll
  for (int s = 1; s < 16; s++)
    pc = pc && (fabsf(Av[s] - (float)(s+1)*Av[0]) <= 1e-4f * fabsf(Av[s]));
  float Dpar = Dp[(size_t)widx*DIF + d];

  float h[16];
  #pragma unroll
  for (int s = 0; s < 16; s++) h[s] = 0.f;
  float sumdv = 0.f;
  const int gi0 = seg*LSEG;

  auto load_chunk = [&](int c, int buf){
    #pragma unroll
    for (int it = 0; it < 3; it++){
      int idx = tid + it*128;
      int ls = idx / 12, q = idx - ls*12;
      int gi = gi0 + c*S1CH + ls;
      int t = bwd ? (LL-1 - gi) : gi;
      cpa16(sb + oDBL + (uint32_t)(((buf*S1CH + ls)*12 + q)*16),
            &dbl[(size_t)(b*LL + t)*48 + q*4]);
    }
    #pragma unroll
    for (int it = 0; it < 4; it++){
      int idx = tid + it*128;
      int ls = idx >> 4, sg = idx & 15;
      int gi = gi0 + c*S1CH + ls;
      int t = bwd ? (LL-1 - gi) : gi;
      cpa16(sb + oXC + (uint32_t)(((buf*S1CH + ls)*128 + sg*8)*2),
            &xch[(size_t)(b*LL + t)*DIF + d0 + sg*8]);
      cpa16(sb + oZ + (uint32_t)(((buf*S1CH + ls)*128 + sg*8)*2),
            &xzz[(size_t)(b*LL + t)*1024 + DIF + d0 + sg*8]);
    }
    asm volatile("cp.async.commit_group;" ::: "memory");
  };

  const int nc = LSEG / S1CH;   // 3
  load_chunk(0, 0);
  for (int c = 0; c < nc; c++){
    const int buf = c & 1;
    if (c + 1 < nc){
      load_chunk(c + 1, buf ^ 1);
      asm volatile("cp.async.wait_group 1;" ::: "memory");
    } else {
      asm volatile("cp.async.wait_group 0;" ::: "memory");
    }
    __syncthreads();
    const float4* sD = reinterpret_cast<const float4*>(ssm + oDBL) + (size_t)buf*S1CH*12;
    const __half* sX = reinterpret_cast<const __half*>(ssm + oXC) + (size_t)buf*S1CH*128;
    const __half* sZ = reinterpret_cast<const __half*>(ssm + oZ)  + (size_t)buf*S1CH*128;

    for (int ls = 0; ls < S1CH; ls++){
      int gi = gi0 + c*S1CH + ls;
      int t  = bwd ? (LL-1 - gi) : gi;
      float xcv = __half2float(sX[ls*128 + tid]);
      float zv  = __half2float(sZ[ls*128 + tid]);
      const float4* row = sD + ls*12;
      float4 q0 = row[0], q1 = row[1], q2 = row[2], q3 = row[3];
      float a0 = fmaf(q0.x, W[0],  fmaf(q0.y, W[1],  fmaf(q0.z, W[2],  q0.w*W[3])));
      float a1 = fmaf(q1.x, W[4],  fmaf(q1.y, W[5],  fmaf(q1.z, W[6],  q1.w*W[7])));
      float a2 = fmaf(q2.x, W[8],  fmaf(q2.y, W[9],  fmaf(q2.z, W[10], q2.w*W[11])));
      float a3 = fmaf(q3.x, W[12], fmaf(q3.y, W[13], fmaf(q3.z, W[14], q3.w*W[15])));
      float a = bia + ((a0 + a1) + (a2 + a3));
      float dv = fmaxf(a, 0.f) + log1pf(__expf(-fabsf(a)));
      sumdv += dv;
      float du = dv * xcv;

      float acc0 = 0.f, acc1 = 0.f, acc2 = 0.f, acc3 = 0.f;
      if (pc){
        float e1 = __expf(dv * Av[0]);
        float e2 = e1*e1, e3 = e2*e1, e4 = e2*e2;
        float e5 = e4*e1, e6 = e4*e2, e7 = e4*e3, e8 = e4*e4;
        float e9 = e8*e1, e10 = e8*e2, e11 = e8*e3, e12 = e8*e4;
        float e13 = e8*e5, e14 = e8*e6, e15 = e8*e7, e16 = e8*e8;
        float4 B0 = row[4], B1 = row[5], B2 = row[6], B3 = row[7];
        float4 C0 = row[8], C1 = row[9], C2 = row[10], C3 = row[11];
        h[0]  = fmaf(e1,  h[0],  du*B0.x); acc0 = fmaf(h[0],  C0.x, acc0);
        h[1]  = fmaf(e2,  h[1],  du*B0.y); acc1 = fmaf(h[1],  C0.y, acc1);
        h[2]  = fmaf(e3,  h[2],  du*B0.z); acc2 = fmaf(h[2],  C0.z, acc2);
        h[3]  = fmaf(e4,  h[3],  du*B0.w); acc3 = fmaf(h[3],  C0.w, acc3);
        h[4]  = fmaf(e5,  h[4],  du*B1.x); acc0 = fmaf(h[4],  C1.x, acc0);
        h[5]  = fmaf(e6,  h[5],  du*B1.y); acc1 = fmaf(h[5],  C1.y, acc1);
        h[6]  = fmaf(e7,  h[6],  du*B1.z); acc2 = fmaf(h[6],  C1.z, acc2);
        h[7]  = fmaf(e8,  h[7],  du*B1.w); acc3 = fmaf(h[7],  C1.w, acc3);
        h[8]  = fmaf(e9,  h[8],  du*B2.x); acc0 = fmaf(h[8],  C2.x, acc0);
        h[9]  = fmaf(e10, h[9],  du*B2.y); acc1 = fmaf(h[9],  C2.y, acc1);
        h[10] = fmaf(e11, h[10], du*B2.z); acc2 = fmaf(h[10], C2.z, acc2);
        h[11] = fmaf(e12, h[11], du*B2.w); acc3 = fmaf(h[11], C2.w, acc3);
        h[12] = fmaf(e13, h[12], du*B3.x); acc0 = fmaf(h[12], C3.x, acc0);
        h[13] = fmaf(e14, h[13], du*B3.y); acc1 = fmaf(h[13], C3.y, acc1);
        h[14] = fmaf(e15, h[14], du*B3.z); acc2 = fmaf(h[14], C3.z, acc2);
        h[15] = fmaf(e16, h[15], du*B3.w); acc3 = fmaf(h[15], C3.w, acc3);
      } else {
        #pragma unroll
        for (int q = 0; q < 4; q++){
          float4 B4 = row[4+q];
          float4 C4 = row[8+q];
          float b0 = __expf(dv*Av[q*4+0]); h[q*4+0] = fmaf(b0, h[q*4+0], du*B4.x); acc0 = fmaf(h[q*4+0], C4.x, acc0);
          float b1 = __expf(dv*Av[q*4+1]); h[q*4+1] = fmaf(b1, h[q*4+1], du*B4.y); acc1 = fmaf(h[q*4+1], C4.y, acc1);
          float b2 = __expf(dv*Av[q*4+2]); h[q*4+2] = fmaf(b2, h[q*4+2], du*B4.z); acc2 = fmaf(h[q*4+2], C4.z, acc2);
          float b3 = __expf(dv*Av[q*4+3]); h[q*4+3] = fmaf(b3, h[q*4+3], du*B4.w); acc3 = fmaf(h[q*4+3], C4.w, acc3);
        }
      }
      float gate = siluf(zv);
      float y = (acc0 + acc1) + (acc2 + acc3) + xcv * Dpar;
      size_t rowd = (size_t)(b*LL + t)*DIF + d;
      u[rowd]  = __float2half(y * gate);
      dg[rowd] = __floats2half2_rn(dv, gate);
    }
    __syncthreads();
  }
  int segbase = ((z*8 + b)*NSEG + seg)*DIF + d;
  float4* hf4 = reinterpret_cast<float4*>(&g_hf[(size_t)segbase*16]);
  hf4[0] = make_float4(h[0],  h[1],  h[2],  h[3]);
  hf4[1] = make_float4(h[4],  h[5],  h[6],  h[7]);
  hf4[2] = make_float4(h[8],  h[9],  h[10], h[11]);
  hf4[3] = make_float4(h[12], h[13], h[14], h[15]);
  g_sdv[segbase] = sumdv;
}

// ---------------- scan phase 2: cross-segment correction (early exit) ------
#define oC2  0
#define oDG2 4096
#define oU2  36864
#define S2_SMEM 53248
__global__ void __launch_bounds__(128) scan2_ker(const float* __restrict__ A_log, int l){
  extern __shared__ char ssm[];
  const uint32_t sb = (uint32_t)__cvta_generic_to_shared(ssm);
  int tid = threadIdx.x;
  int d0 = blockIdx.x*128, d = d0 + tid;
  int b = blockIdx.y;
  int z = blockIdx.z / (NSEG-1), seg = blockIdx.z - z*(NSEG-1) + 1;
  int widx = l*4 + z;
  bool bwd = (z & 1);
  const float*  dbl = g_dbl[z];
  const __half2* dg = g_dg[z];
  __half* u = g_uh[z];

  float Av[16];
  #pragma unroll
  for (int s = 0; s < 16; s++)
    Av[s] = -expf(A_log[((size_t)widx*DIF + d)*DSF + s]);
  bool pc = true;
  #pragma unroll
  for (int s = 1; s < 16; s++)
    pc = pc && (fabsf(Av[s] - (float)(s+1)*Av[0]) <= 1e-4f * fabsf(Av[s]));
  float amax = Av[0];
  #pragma unroll
  for (int s = 1; s < 16; s++) amax = fmaxf(amax, Av[s]);

  float hin[16];
  #pragma unroll
  for (int s = 0; s < 16; s++) hin[s] = 0.f;
  for (int k = 0; k < seg; k++){
    int kb = ((z*8 + b)*NSEG + k)*DIF + d;
    float sd = g_sdv[kb];
    const float4* hf4 = reinterpret_cast<const float4*>(&g_hf[(size_t)kb*16]);
    float4 f0 = hf4[0], f1 = hf4[1], f2 = hf4[2], f3 = hf4[3];
    float hf[16] = {f0.x,f0.y,f0.z,f0.w, f1.x,f1.y,f1.z,f1.w,
                    f2.x,f2.y,f2.z,f2.w, f3.x,f3.y,f3.z,f3.w};
    if (pc){
      float E = __expf(Av[0]*sd);
      float p = 1.f;
      #pragma unroll
      for (int s = 0; s < 16; s++){ p *= E; hin[s] = fmaf(p, hin[s], hf[s]); }
    } else {
      #pragma unroll
      for (int s = 0; s < 16; s++) hin[s] = fmaf(__expf(Av[s]*sd), hin[s], hf[s]);
    }
  }

  const int gi0 = seg*LSEG;
  auto load_chunk = [&](int c, int buf){
    {
      int ls = tid >> 2, q = tid & 3;
      int gi = gi0 + c*S1CH + ls;
      int t = bwd ? (LL-1 - gi) : gi;
      cpa16(sb + oC2 + (uint32_t)(((buf*S1CH + ls)*4 + q)*16),
            &dbl[(size_t)(b*LL + t)*48 + 32 + q*4]);
    }
    #pragma unroll
    for (int it = 0; it < 8; it++){
      int idx = tid + it*128;
      int ls = idx >> 5, sg = idx & 31;
      int gi = gi0 + c*S1CH + ls;
      int t = bwd ? (LL-1 - gi) : gi;
      cpa16(sb + oDG2 + (uint32_t)(((buf*S1CH + ls)*128 + sg*4)*4),
            &dg[(size_t)(b*LL + t)*DIF + d0 + sg*4]);
    }
    #pragma unroll
    for (int it = 0; it < 4; it++){
      int idx = tid + it*128;
      int ls = idx >> 4, sg = idx & 15;
      int gi = gi0 + c*S1CH + ls;
      int t = bwd ? (LL-1 - gi) : gi;
      cpa16(sb + oU2 + (uint32_t)(((buf*S1CH + ls)*128 + sg*8)*2),
            &u[(size_t)(b*LL + t)*DIF + d0 + sg*8]);
    }
    asm volatile("cp.async.commit_group;" ::: "memory");
  };

  float cacc = 0.f;
  const int nc = LSEG / S1CH;   // 3
  load_chunk(0, 0);
  for (int c = 0; c < nc; c++){
    const int buf = c & 1;
    if (c + 1 < nc){
      load_chunk(c + 1, buf ^ 1);
      asm volatile("cp.async.wait_group 1;" ::: "memory");
    } else {
      asm volatile("cp.async.wait_group 0;" ::: "memory");
    }
    __syncthreads();
    const float4*  sC = reinterpret_cast<const float4*>(ssm + oC2) + (size_t)buf*S1CH*4;
    const __half2* sG = reinterpret_cast<const __half2*>(ssm + oDG2) + (size_t)buf*S1CH*128;
    const __half*  sU = reinterpret_cast<const __half*>(ssm + oU2) + (size_t)buf*S1CH*128;

    for (int ls = 0; ls < S1CH; ls++){
      int gi = gi0 + c*S1CH + ls;
      int t  = bwd ? (LL-1 - gi) : gi;
      float2 dgv = __half22float2(sG[ls*128 + tid]);
      cacc += dgv.x;
      float4 C0 = sC[ls*4+0], C1 = sC[ls*4+1], C2 = sC[ls*4+2], C3 = sC[ls*4+3];
      float corr;
      if (pc){
        float e1 = __expf(Av[0]*cacc);
        float e2 = e1*e1, e3 = e2*e1, e4 = e2*e2;
        float e5 = e4*e1, e6 = e4*e2, e7 = e4*e3, e8 = e4*e4;
        float e9 = e8*e1, e10 = e8*e2, e11 = e8*e3, e12 = e8*e4;
        float e13 = e8*e5, e14 = e8*e6, e15 = e8*e7, e16 = e8*e8;
        float c0 = fmaf(e1*hin[0],  C0.x, 0.f);
        c0 = fmaf(e5*hin[4],  C1.x, c0);
        c0 = fmaf(e9*hin[8],  C2.x, c0);
        c0 = fmaf(e13*hin[12], C3.x, c0);
        float c1 = fmaf(e2*hin[1],  C0.y, 0.f);
        c1 = fmaf(e6*hin[5],  C1.y, c1);
        c1 = fmaf(e10*hin[9], C2.y, c1);
        c1 = fmaf(e14*hin[13], C3.y, c1);
        float c2 = fmaf(e3*hin[2],  C0.z, 0.f);
        c2 = fmaf(e7*hin[6],  C1.z, c2);
        c2 = fmaf(e11*hin[10], C2.z, c2);
        c2 = fmaf(e15*hin[14], C3.z, c2);
        float c3 = fmaf(e4*hin[3],  C0.w, 0.f);
        c3 = fmaf(e8*hin[7],  C1.w, c3);
        c3 = fmaf(e12*hin[11], C2.w, c3);
        c3 = fmaf(e16*hin[15], C3.w, c3);
        corr = (c0 + c1) + (c2 + c3);
      } else {
        float Cw[16] = {C0.x,C0.y,C0.z,C0.w, C1.x,C1.y,C1.z,C1.w,
                        C2.x,C2.y,C2.z,C2.w, C3.x,C3.y,C3.z,C3.w};
        corr = 0.f;
        #pragma unroll
        for (int s = 0; s < 16; s++)
          corr = fmaf(__expf(Av[s]*cacc)*hin[s], Cw[s], corr);
      }
      float up = __half2float(sU[ls*128 + tid]);
      u[(size_t)(b*LL + t)*DIF + d] = __float2half(fmaf(corr, dgv.y, up));
    }
    int done = (cacc * (-amax) > 25.f) ? 1 : 0;
    if (__syncthreads_and(done)){
      asm volatile("cp.async.wait_group 0;" ::: "memory");
      break;
    }
  }
}

// ---------------- combine: LN(o0+o1), LN(o2+o3), residual add --------------
__global__ void combine_ker(const float* __restrict__ lnw, const float* __restrict__ lnb){
  int i = blockIdx.x, c = threadIdx.x;
  float a  = g_o[0][(size_t)i*DMF + c] + g_o[1][(size_t)i*DMF + c];
  float bv = g_o[2][(size_t)i*DMF + c] + g_o[3][(size_t)i*DMF + c];
  __shared__ float r1[256], r2[256];
  r1[c] = a; r2[c] = bv; __syncthreads();
  for (int s = 128; s > 0; s >>= 1){
    if (c < s){ r1[c] += r1[c+s]; r2[c] += r2[c+s]; }
    __syncthreads();
  }
  float ma = r1[0] * (1.f/DMF), mb = r2[0] * (1.f/DMF);
  __syncthreads();
  float da = a - ma, db = bv - mb;
  r1[c] = da*da; r2[c] = db*db; __syncthreads();
  for (int s = 128; s > 0; s >>= 1){
    if (c < s){ r1[c] += r1[c+s]; r2[c] += r2[c+s]; }
    __syncthreads();
  }
  float va = r1[0] * (1.f/DMF), vb = r2[0] * (1.f/DMF);
  float s1 = da * rsqrtf(va + 1e-5f) * lnw[c] + lnb[c];
  float s2 = db * rsqrtf(vb + 1e-5f) * lnw[c] + lnb[c];
  float nv = g_x[(size_t)i*DMF + c] + 0.5f * (s1 + s2);
  g_x [(size_t)i*DMF + c] = nv;
  g_xh[(size_t)i*DMF + c] = __float2half(nv);
}

// ---------------- host orchestration ---------------------------------------
#define SMEM_H128 ((2*ABUF + 2*128*STRH)*2)   // 40960 B
#define SMEM_H64  ((2*ABUF + 2*64*STRH)*2)    // 30720 B

extern "C" void kernel_launch(void* const* d_in, const int* in_sizes, int n_in,
                              void* d_out, int out_size){
  const float* x       = (const float*)d_in[0];
  const float* pe      = (const float*)d_in[1];
  const float* ln_w    = (const float*)d_in[2];
  const float* ln_b    = (const float*)d_in[3];
  const float* in_proj = (const float*)d_in[4];
  const float* conv_w  = (const float*)d_in[5];
  const float* conv_b  = (const float*)d_in[6];
  const float* x_proj  = (const float*)d_in[7];
  const float* dt_w    = (const float*)d_in[8];
  const float* dt_b    = (const float*)d_in[9];
  const float* A_log   = (const float*)d_in[10];
  const float* Dp      = (const float*)d_in[11];
  const float* out_prj = (const float*)d_in[12];

  void *pxh, *pxzh, *pxch, *pdbl, *puh, *po, *pw1, *pw2, *pw4;
  cudaGetSymbolAddress(&pxh,  g_xh);
  cudaGetSymbolAddress(&pxzh, g_xzh);
  cudaGetSymbolAddress(&pxch, g_xch);
  cudaGetSymbolAddress(&pdbl, g_dbl);
  cudaGetSymbolAddress(&puh,  g_uh);
  cudaGetSymbolAddress(&po,   g_o);
  cudaGetSymbolAddress(&pw1,  g_wt1);
  cudaGetSymbolAddress(&pw2,  g_wt2);
  cudaGetSymbolAddress(&pw4,  g_wt4);

  cudaFuncSetAttribute(scan1_ker, cudaFuncAttributeMaxDynamicSharedMemorySize, S1_SMEM);
  cudaFuncSetAttribute(scan2_ker, cudaFuncAttributeMaxDynamicSharedMemorySize, S2_SMEM);

  wtrans_ker<<<dim3(16, 32, 24), dim3(32, 8)>>>(in_proj, x_proj, out_prj);
  add_pe_ker<<<MM, 256>>>(x, pe);

  for (int l = 0; l < NLAY; l++){
    // GEMM1: xz[z] = seq(z) @ in_proj[l,z]  (N=1024, K=256, half out)
    hgemm_ker<128><<<dim3(MM/128, 8, 4), 256, SMEM_H128>>>(
        (const __half*)pxh, (size_t)0,
        (const __half*)pw1, pxzh, 256, 1024, l, 1, 1);
    conv_ker<<<dim3((MM/4)*(DIF/4)/256, 4), 256>>>(conv_w, conv_b, l);
    // GEMM2: dbl[z] = xc[z] @ x_proj (N=48 pad 64, K=512, fp32 out)
    hgemm_ker<64><<<dim3(MM/128, 1, 4), 256, SMEM_H64>>>(
        (const __half*)pxch, (size_t)MM*DIF,
        (const __half*)pw2, pdbl, 512, 48, l, 0, 0);
    // selective scan: 8-segment phase 1 + early-exit fixup
    scan1_ker<<<dim3(4, Bb, 4*NSEG), 128, S1_SMEM>>>(A_log, Dp, dt_w, dt_b, l);
    scan2_ker<<<dim3(4, Bb, 4*(NSEG-1)), 128, S2_SMEM>>>(A_log, l);
    // GEMM4: o[z] = u[z] @ out_proj (N=256, K=512, fp32 out)
    hgemm_ker<128><<<dim3(MM/128, 2, 4), 256, SMEM_H128>>>(
        (const __half*)puh, (size_t)MM*DIF,
        (const __half*)pw4, po, 512, 256, l, 0, 0);
    combine_ker<<<MM, 256>>>(ln_w, ln_b);
  }

  copy_out_ker<<<MM, 256>>>((float*)d_out);
}